// round 2
// baseline (speedup 1.0000x reference)
#include <cuda_runtime.h>
#include <math.h>

// Problem dims (fixed by the reference)
#define TB_B 2
#define TB_S 2048
#define TB_D 1024
#define TB_F 4096
#define TB_H 16
#define TB_HD 64
#define TB_T (TB_B * TB_S)   // 4096 tokens

// ---------------- scratch (no allocation allowed -> device globals) ----------
__device__ float g_xn [(size_t)TB_T * TB_D];   // srmsnorm(x), later srmsnorm(h)
__device__ float g_q  [(size_t)TB_T * TB_D];
__device__ float g_k  [(size_t)TB_T * TB_D];
__device__ float g_v  [(size_t)TB_T * TB_D];
__device__ float g_att[(size_t)TB_T * TB_D];
__device__ float g_h  [(size_t)TB_T * TB_D];
__device__ float g_ff [(size_t)TB_T * TB_F];

// ---------------- srmsnorm: x / max(||x||,eps) * sqrt(D) ---------------------
__global__ void srmsnorm_kernel(const float* __restrict__ x, float* __restrict__ y) {
    int row = blockIdx.x;
    int tid = threadIdx.x;
    const float* xr = x + (size_t)row * TB_D;
    float4 v = *(const float4*)(xr + tid * 4);
    float ss = v.x*v.x + v.y*v.y + v.z*v.z + v.w*v.w;
    #pragma unroll
    for (int o = 16; o; o >>= 1) ss += __shfl_xor_sync(0xffffffffu, ss, o);
    __shared__ float wred[8];
    __shared__ float s_scale;
    if ((tid & 31) == 0) wred[tid >> 5] = ss;
    __syncthreads();
    if (tid == 0) {
        float tot = 0.f;
        #pragma unroll
        for (int i = 0; i < 8; i++) tot += wred[i];
        float nrm = sqrtf(tot);
        s_scale = 32.0f / fmaxf(nrm, 1e-12f);   // sqrt(1024) = 32
    }
    __syncthreads();
    float sc = s_scale;
    float4 o4 = make_float4(v.x*sc, v.y*sc, v.z*sc, v.w*sc);
    *(float4*)(y + (size_t)row * TB_D + tid * 4) = o4;
}

// ---------------- GELU (tanh approximation, matches jax approximate=True) ----
__device__ __forceinline__ float gelu_tanh(float v) {
    const float c = 0.79788456080286535588f; // sqrt(2/pi)
    float t = c * (v + 0.044715f * v * v * v);
    return 0.5f * v * (1.0f + tanhf(t));
}

// ---------------- 128x128x16 tiled fp32 GEMM, 8x8 per thread -----------------
// EPI: 0 = none, 1 = +residual, 2 = gelu
template<int EPI>
__device__ __forceinline__ void gemm_body(
    const float* __restrict__ A, const float* __restrict__ W,
    const float* __restrict__ res, float* __restrict__ C,
    int M, int N, int K, int bm, int bn)
{
    __shared__ float Ast[16][132];   // transposed A tile: Ast[k][m]
    __shared__ float Bs [16][128];   // Bs[k][n]
    int tid = threadIdx.x;
    int tx = tid & 15, ty = tid >> 4;

    float acc[8][8];
    #pragma unroll
    for (int i = 0; i < 8; i++)
        #pragma unroll
        for (int j = 0; j < 8; j++) acc[i][j] = 0.f;

    const float* Ab = A + (size_t)bm * K;
    const float* Wb = W + bn;

    for (int kt = 0; kt < K; kt += 16) {
        // A tile: 128 rows x 16 cols = 512 float4
        #pragma unroll
        for (int i = tid; i < 512; i += 256) {
            int r = i >> 2, c4 = (i & 3) << 2;
            float4 va = *(const float4*)(Ab + (size_t)r * K + kt + c4);
            Ast[c4 + 0][r] = va.x; Ast[c4 + 1][r] = va.y;
            Ast[c4 + 2][r] = va.z; Ast[c4 + 3][r] = va.w;
        }
        // B tile: 16 rows x 128 cols = 512 float4
        #pragma unroll
        for (int i = tid; i < 512; i += 256) {
            int r = i >> 5, c4 = (i & 31) << 2;
            *(float4*)(&Bs[r][c4]) = *(const float4*)(Wb + (size_t)(kt + r) * N + c4);
        }
        __syncthreads();
        #pragma unroll
        for (int k = 0; k < 16; k++) {
            float4 a0 = *(const float4*)(&Ast[k][ty * 4]);
            float4 a1 = *(const float4*)(&Ast[k][64 + ty * 4]);
            float4 b0 = *(const float4*)(&Bs[k][tx * 4]);
            float4 b1 = *(const float4*)(&Bs[k][64 + tx * 4]);
            float a[8] = {a0.x, a0.y, a0.z, a0.w, a1.x, a1.y, a1.z, a1.w};
            float b[8] = {b0.x, b0.y, b0.z, b0.w, b1.x, b1.y, b1.z, b1.w};
            #pragma unroll
            for (int i = 0; i < 8; i++)
                #pragma unroll
                for (int j = 0; j < 8; j++)
                    acc[i][j] = fmaf(a[i], b[j], acc[i][j]);
        }
        __syncthreads();
    }

    // epilogue (rows i: ty*4+i and 64+ty*4+i; cols: tx*4 and 64+tx*4)
    #pragma unroll
    for (int i = 0; i < 8; i++) {
        int row = bm + ((i < 4) ? (ty * 4 + i) : (64 + ty * 4 + i - 4));
        #pragma unroll
        for (int jh = 0; jh < 2; jh++) {
            int col = bn + jh * 64 + tx * 4;
            float v0 = acc[i][jh * 4 + 0], v1 = acc[i][jh * 4 + 1];
            float v2 = acc[i][jh * 4 + 2], v3 = acc[i][jh * 4 + 3];
            size_t idx = (size_t)row * N + col;
            if (EPI == 1) {
                float4 r4 = *(const float4*)(res + idx);
                v0 += r4.x; v1 += r4.y; v2 += r4.z; v3 += r4.w;
            } else if (EPI == 2) {
                v0 = gelu_tanh(v0); v1 = gelu_tanh(v1);
                v2 = gelu_tanh(v2); v3 = gelu_tanh(v3);
            }
            *(float4*)(C + idx) = make_float4(v0, v1, v2, v3);
        }
    }
}

template<int EPI>
__global__ __launch_bounds__(256, 2) void gemm_kernel(
    const float* __restrict__ A, const float* __restrict__ W,
    const float* __restrict__ res, float* __restrict__ C,
    int M, int N, int K)
{
    gemm_body<EPI>(A, W, res, C, M, N, K, blockIdx.y * 128, blockIdx.x * 128);
}

__global__ __launch_bounds__(256, 2) void gemm_qkv_kernel(
    const float* __restrict__ A,
    const float* __restrict__ w0, const float* __restrict__ w1, const float* __restrict__ w2,
    float* __restrict__ o0, float* __restrict__ o1, float* __restrict__ o2)
{
    const float* W = (blockIdx.z == 0) ? w0 : ((blockIdx.z == 1) ? w1 : w2);
    float* C = (blockIdx.z == 0) ? o0 : ((blockIdx.z == 1) ? o1 : o2);
    gemm_body<0>(A, W, nullptr, C, TB_T, TB_D, TB_D, blockIdx.y * 128, blockIdx.x * 128);
}

// ---------------- causal flash attention, fp32, 64x64 tiles ------------------
// grid (S/64, H, B), 256 threads (16x16), each thread 4x4 of the 64x64 tile.
__global__ __launch_bounds__(256) void attn_kernel(
    const float* __restrict__ Q, const float* __restrict__ Km,
    const float* __restrict__ Vm, float* __restrict__ O)
{
    extern __shared__ float sm[];
    float* Qt  = sm;              // [64][68] Qt[d][q]
    float* KP  = Qt + 64 * 68;    // [64][68] Kt[d][k], later Pt[k][q]
    float* Vs  = KP + 64 * 68;    // [64][64] Vs[k][hd]
    float* red = Vs + 64 * 64;    // [64][17]
    float* m_s = red + 64 * 17;   // [64]
    float* l_s = m_s + 64;        // [64]

    int tid = threadIdx.x;
    int tx = tid & 15, ty = tid >> 4;
    int qt0 = blockIdx.x * 64;
    int hh = blockIdx.y, bb = blockIdx.z;
    size_t base = ((size_t)bb * TB_S) * TB_D + (size_t)hh * TB_HD;
    const float* Qb = Q + base;
    const float* Kb = Km + base;
    const float* Vb = Vm + base;

    // load Q tile transposed
    for (int i = tid; i < 1024; i += 256) {
        int r = i >> 4, c4 = (i & 15) << 2;
        float4 q4 = *(const float4*)(Qb + (size_t)(qt0 + r) * TB_D + c4);
        Qt[(c4 + 0) * 68 + r] = q4.x; Qt[(c4 + 1) * 68 + r] = q4.y;
        Qt[(c4 + 2) * 68 + r] = q4.z; Qt[(c4 + 3) * 68 + r] = q4.w;
    }
    if (tid < 64) { m_s[tid] = -1e30f; l_s[tid] = 0.f; }

    float o[4][4];
    #pragma unroll
    for (int i = 0; i < 4; i++)
        #pragma unroll
        for (int j = 0; j < 4; j++) o[i][j] = 0.f;

    int ntiles = blockIdx.x + 1;
    for (int kt = 0; kt < ntiles; kt++) {
        int k0 = kt * 64;
        __syncthreads();   // prior-iter Pt/Vs readers done (and Q store fence @iter0)
        for (int i = tid; i < 1024; i += 256) {
            int r = i >> 4, c4 = (i & 15) << 2;
            float4 k4 = *(const float4*)(Kb + (size_t)(k0 + r) * TB_D + c4);
            KP[(c4 + 0) * 68 + r] = k4.x; KP[(c4 + 1) * 68 + r] = k4.y;
            KP[(c4 + 2) * 68 + r] = k4.z; KP[(c4 + 3) * 68 + r] = k4.w;
            float4 v4 = *(const float4*)(Vb + (size_t)(k0 + r) * TB_D + c4);
            *(float4*)(&Vs[r * 64 + c4]) = v4;
        }
        __syncthreads();

        // S = (Q K^T) * scale, causal mask
        float sfr[4][4];
        #pragma unroll
        for (int i = 0; i < 4; i++)
            #pragma unroll
            for (int j = 0; j < 4; j++) sfr[i][j] = 0.f;
        #pragma unroll 8
        for (int d = 0; d < 64; d++) {
            float4 a = *(const float4*)(&Qt[d * 68 + ty * 4]);
            float4 b = *(const float4*)(&KP[d * 68 + tx * 4]);
            float av[4] = {a.x, a.y, a.z, a.w};
            float bv[4] = {b.x, b.y, b.z, b.w};
            #pragma unroll
            for (int i = 0; i < 4; i++)
                #pragma unroll
                for (int j = 0; j < 4; j++)
                    sfr[i][j] = fmaf(av[i], bv[j], sfr[i][j]);
        }
        #pragma unroll
        for (int i = 0; i < 4; i++) {
            int qg = qt0 + ty * 4 + i;
            #pragma unroll
            for (int j = 0; j < 4; j++) {
                sfr[i][j] *= 0.125f;                 // hd^-0.5, hd=64
                int kg = k0 + tx * 4 + j;
                if (kg > qg) sfr[i][j] = -1e30f;
            }
        }
        // row-max partials
        #pragma unroll
        for (int i = 0; i < 4; i++) {
            float mx = fmaxf(fmaxf(sfr[i][0], sfr[i][1]), fmaxf(sfr[i][2], sfr[i][3]));
            red[(ty * 4 + i) * 17 + tx] = mx;
        }
        __syncthreads();
        float mnew[4], alpha[4], psum[4];
        #pragma unroll
        for (int i = 0; i < 4; i++) {
            int qr = ty * 4 + i;
            float mt = red[qr * 17];
            #pragma unroll
            for (int t = 1; t < 16; t++) mt = fmaxf(mt, red[qr * 17 + t]);
            float mo = m_s[qr];
            float mn = fmaxf(mo, mt);
            mnew[i] = mn;
            alpha[i] = __expf(mo - mn);
            float ps = 0.f;
            #pragma unroll
            for (int j = 0; j < 4; j++) {
                float p = __expf(sfr[i][j] - mn);
                ps += p;
                KP[(tx * 4 + j) * 68 + qr] = p;      // Pt[k][q], aliases K tile (done)
            }
            psum[i] = ps;
        }
        __syncthreads();   // red & m_s reads done; Pt visible
        #pragma unroll
        for (int i = 0; i < 4; i++) red[(ty * 4 + i) * 17 + tx] = psum[i];
        if (tx == 0) {
            #pragma unroll
            for (int i = 0; i < 4; i++) m_s[ty * 4 + i] = mnew[i];
        }
        __syncthreads();
        if (tx == 0) {
            #pragma unroll
            for (int i = 0; i < 4; i++) {
                int qr = ty * 4 + i;
                float s = 0.f;
                #pragma unroll
                for (int t = 0; t < 16; t++) s += red[qr * 17 + t];
                l_s[qr] = l_s[qr] * alpha[i] + s;
            }
        }
        // rescale O and accumulate P@V
        #pragma unroll
        for (int i = 0; i < 4; i++)
            #pragma unroll
            for (int j = 0; j < 4; j++) o[i][j] *= alpha[i];
        #pragma unroll 8
        for (int kk = 0; kk < 64; kk++) {
            float4 a = *(const float4*)(&KP[kk * 68 + ty * 4]);
            float4 b = *(const float4*)(&Vs[kk * 64 + tx * 4]);
            float av[4] = {a.x, a.y, a.z, a.w};
            float bv[4] = {b.x, b.y, b.z, b.w};
            #pragma unroll
            for (int i = 0; i < 4; i++)
                #pragma unroll
                for (int j = 0; j < 4; j++)
                    o[i][j] = fmaf(av[i], bv[j], o[i][j]);
        }
    }
    __syncthreads();
    float inv[4];
    #pragma unroll
    for (int i = 0; i < 4; i++) inv[i] = 1.0f / l_s[ty * 4 + i];
    #pragma unroll
    for (int i = 0; i < 4; i++) {
        int s_idx = qt0 + ty * 4 + i;
        float* op = O + ((size_t)bb * TB_S + s_idx) * TB_D + hh * TB_HD + tx * 4;
        *(float4*)op = make_float4(o[i][0] * inv[i], o[i][1] * inv[i],
                                   o[i][2] * inv[i], o[i][3] * inv[i]);
    }
}

// ---------------- launch ------------------------------------------------------
static const int ATTN_SMEM = (64 * 68 * 2 + 64 * 64 + 64 * 17 + 128) * (int)sizeof(float);

extern "C" void kernel_launch(void* const* d_in, const int* in_sizes, int n_in,
                              void* d_out, int out_size) {
    const float* x    = (const float*)d_in[0];
    const float* wq   = (const float*)d_in[1];
    const float* wk   = (const float*)d_in[2];
    const float* wv   = (const float*)d_in[3];
    const float* wo   = (const float*)d_in[4];
    const float* w_in = (const float*)d_in[5];
    const float* w_out= (const float*)d_in[6];
    float* out = (float*)d_out;
    (void)in_sizes; (void)n_in; (void)out_size;

    float *xn, *q, *k, *v, *att, *h, *ff;
    cudaGetSymbolAddress((void**)&xn,  g_xn);
    cudaGetSymbolAddress((void**)&q,   g_q);
    cudaGetSymbolAddress((void**)&k,   g_k);
    cudaGetSymbolAddress((void**)&v,   g_v);
    cudaGetSymbolAddress((void**)&att, g_att);
    cudaGetSymbolAddress((void**)&h,   g_h);
    cudaGetSymbolAddress((void**)&ff,  g_ff);

    cudaFuncSetAttribute(attn_kernel, cudaFuncAttributeMaxDynamicSharedMemorySize, ATTN_SMEM);

    // 1. xn = srmsnorm(x)
    srmsnorm_kernel<<<TB_T, 256>>>(x, xn);
    // 2. q,k,v = xn @ {wq,wk,wv}
    gemm_qkv_kernel<<<dim3(TB_D / 128, TB_T / 128, 3), 256>>>(xn, wq, wk, wv, q, k, v);
    // 3. causal attention
    attn_kernel<<<dim3(TB_S / 64, TB_H, TB_B), 256, ATTN_SMEM>>>(q, k, v, att);
    // 4. h = x + att @ wo
    gemm_kernel<1><<<dim3(TB_D / 128, TB_T / 128), 256>>>(att, wo, x, h, TB_T, TB_D, TB_D);
    // 5. hn = srmsnorm(h)  (reuse xn buffer)
    srmsnorm_kernel<<<TB_T, 256>>>(h, xn);
    // 6. ff = gelu(hn @ w_in)
    gemm_kernel<2><<<dim3(TB_F / 128, TB_T / 128), 256>>>(xn, w_in, nullptr, ff, TB_T, TB_F, TB_D);
    // 7. out = h + ff @ w_out
    gemm_kernel<1><<<dim3(TB_D / 128, TB_T / 128), 256>>>(ff, w_out, h, out, TB_T, TB_D, TB_F);
}

// round 4
// speedup vs baseline: 1.3939x; 1.3939x over previous
#include <cuda_runtime.h>
#include <cuda_bf16.h>
#include <math.h>
#include <stdint.h>

// Problem dims (fixed by the reference)
#define TB_B 2
#define TB_S 2048
#define TB_D 1024
#define TB_F 4096
#define TB_H 16
#define TB_HD 64
#define TB_T (TB_B * TB_S)   // 4096 tokens
#define TB_D3 (3 * TB_D)     // 3072 (split-bf16 expanded K)
#define TB_F3 (3 * TB_F)     // 12288

// tcgen05 is arch-specific: only available when compiling the sm_103a (or
// sm_100a) pass. The plain compute_103 fallback pass gets a SIMT body so
// every gencode target compiles.
#if defined(__CUDA_ARCH_FEAT_SM103_ALL) || defined(__CUDA_ARCH_FEAT_SM100_ALL)
#define HAS_TCGEN05 1
#else
#define HAS_TCGEN05 0
#endif

// ---------------- scratch (no allocation allowed -> device globals) ----------
__device__ __nv_bfloat16 g_xn3 [(size_t)TB_T * TB_D3];  // srmsnorm(x)/(h), split-bf16
__device__ __nv_bfloat16 g_att3[(size_t)TB_T * TB_D3];  // attention out, split-bf16
__device__ __nv_bfloat16 g_ff3 [(size_t)TB_T * TB_F3];  // gelu out, split-bf16
__device__ float g_q [(size_t)TB_T * TB_D];
__device__ float g_k [(size_t)TB_T * TB_D];
__device__ float g_v [(size_t)TB_T * TB_D];
__device__ float g_h [(size_t)TB_T * TB_D];
__device__ __nv_bfloat16 g_wq3 [(size_t)TB_D * TB_D3];  // [n=1024][3K=3072]
__device__ __nv_bfloat16 g_wk3 [(size_t)TB_D * TB_D3];
__device__ __nv_bfloat16 g_wv3 [(size_t)TB_D * TB_D3];
__device__ __nv_bfloat16 g_wo3 [(size_t)TB_D * TB_D3];
__device__ __nv_bfloat16 g_win3[(size_t)TB_F * TB_D3];  // [4096][3072]
__device__ __nv_bfloat16 g_wout3[(size_t)TB_D * TB_F3]; // [1024][12288]

// ---------------- PTX helpers (arch-neutral) ---------------------------------
__device__ __forceinline__ uint32_t smem_u32(const void* p) {
    uint32_t a;
    asm("{ .reg .u64 t; cvta.to.shared.u64 t, %1; cvt.u32.u64 %0, t; }" : "=r"(a) : "l"(p));
    return a;
}
__device__ __forceinline__ void split_bf16(float x, __nv_bfloat16& hi, __nv_bfloat16& lo) {
    hi = __float2bfloat16(x);
    lo = __float2bfloat16(x - __bfloat162float(hi));
}
__device__ __forceinline__ float gelu_tanh(float v) {
    const float c = 0.79788456080286535588f;
    float t = c * (v + 0.044715f * v * v * v);
    return 0.5f * v * (1.0f + tanhf(t));
}

#if HAS_TCGEN05
__device__ __forceinline__ uint32_t elect_one() {
    uint32_t p;
    asm volatile("{ .reg .pred p; elect.sync _|p, 0xFFFFFFFF; selp.b32 %0, 1, 0, p; }" : "=r"(p));
    return p;
}
__device__ __forceinline__ void mbar_init(uint32_t a, uint32_t cnt) {
    asm volatile("mbarrier.init.shared.b64 [%0], %1;" :: "r"(a), "r"(cnt) : "memory");
}
__device__ __forceinline__ void mbar_wait(uint32_t a, uint32_t parity) {
    asm volatile(
        "{\n\t.reg .pred P;\n\t"
        "LW%=:\n\t"
        "mbarrier.try_wait.parity.acquire.cta.shared::cta.b64 P, [%0], %1, 0x989680;\n\t"
        "@P bra LD%=;\n\t"
        "bra LW%=;\n\t"
        "LD%=:\n\t}"
        :: "r"(a), "r"(parity) : "memory");
}
__device__ __forceinline__ void cp_async16(uint32_t dst, const void* src) {
    asm volatile("cp.async.cg.shared.global [%0], [%1], 16;" :: "r"(dst), "l"(src) : "memory");
}
__device__ __forceinline__ void cp_async_arrive(uint32_t mbar) {
    asm volatile("cp.async.mbarrier.arrive.noinc.shared::cta.b64 [%0];" :: "r"(mbar) : "memory");
}
// SS bf16 MMA, cta_group::1, fp32 accum
__device__ __forceinline__ void mma_f16_ss(uint32_t d, uint64_t ad, uint64_t bd,
                                           uint32_t idesc, uint32_t en) {
    asm volatile(
        "{\n\t.reg .pred p;\n\tsetp.ne.u32 p, %4, 0;\n\t"
        "tcgen05.mma.cta_group::1.kind::f16 [%0], %1, %2, %3, {%5, %5, %5, %5}, p;\n\t}"
        :: "r"(d), "l"(ad), "l"(bd), "r"(idesc), "r"(en), "r"(0u) : "memory");
}
#define TCGEN05_LD_32X32B_X32(r, tmem_addr) \
    asm volatile( \
        "tcgen05.ld.sync.aligned.32x32b.x32.b32 " \
        "{%0, %1, %2, %3, %4, %5, %6, %7, " \
        " %8, %9, %10, %11, %12, %13, %14, %15, " \
        " %16, %17, %18, %19, %20, %21, %22, %23, " \
        " %24, %25, %26, %27, %28, %29, %30, %31}, [%32];" \
        : "=r"((r)[0]),  "=r"((r)[1]),  "=r"((r)[2]),  "=r"((r)[3]), \
          "=r"((r)[4]),  "=r"((r)[5]),  "=r"((r)[6]),  "=r"((r)[7]), \
          "=r"((r)[8]),  "=r"((r)[9]),  "=r"((r)[10]), "=r"((r)[11]), \
          "=r"((r)[12]), "=r"((r)[13]), "=r"((r)[14]), "=r"((r)[15]), \
          "=r"((r)[16]), "=r"((r)[17]), "=r"((r)[18]), "=r"((r)[19]), \
          "=r"((r)[20]), "=r"((r)[21]), "=r"((r)[22]), "=r"((r)[23]), \
          "=r"((r)[24]), "=r"((r)[25]), "=r"((r)[26]), "=r"((r)[27]), \
          "=r"((r)[28]), "=r"((r)[29]), "=r"((r)[30]), "=r"((r)[31]) \
        : "r"(tmem_addr))
#endif // HAS_TCGEN05

#define SWZ(o) ((o) ^ (((o) >> 3) & 0x70))
// SW128 smem descriptor base: layout=2, version=1, SBO=64, LBO=1
#define SMEM_DESC_BASE ((uint64_t(2) << 61) | (uint64_t(1) << 46) | (uint64_t(64) << 32) | (uint64_t(1) << 16))
#define MK_DESC(addr) (SMEM_DESC_BASE | ((uint64_t)((addr) >> 4) & 0x3FFF))
// idesc: F32 accum (1<<4), A=BF16 (1<<7), B=BF16 (1<<10), N=128 (16<<17), M=128 (8<<24)
#define MMA_IDESC 0x8200490u

// ---------------- weight convert + transpose: W[K][N] -> o[N][3K] (hi,hi,lo) --
__global__ void conv_w_kernel(const float* __restrict__ W, __nv_bfloat16* __restrict__ o,
                              int K, int N) {
    __shared__ float t[32][33];
    int n0 = blockIdx.x * 32, k0 = blockIdx.y * 32;
    int tx = threadIdx.x, ty = threadIdx.y; // 32 x 8
    #pragma unroll
    for (int i = 0; i < 4; i++)
        t[ty + 8 * i][tx] = W[(size_t)(k0 + ty + 8 * i) * N + n0 + tx];
    __syncthreads();
    size_t K3 = 3 * (size_t)K;
    #pragma unroll
    for (int i = 0; i < 4; i++) {
        int nn = ty + 8 * i, kk = tx;
        float x = t[kk][nn];
        __nv_bfloat16 hi, lo; split_bf16(x, hi, lo);
        size_t base = (size_t)(n0 + nn) * K3 + 3 * (size_t)(k0 + kk);
        o[base] = hi; o[base + 1] = hi; o[base + 2] = lo;   // B-side triple
    }
}

// ---------------- srmsnorm -> split-bf16 (A-side triple: hi,lo,hi) -----------
__global__ void srmsnorm3_kernel(const float* __restrict__ x, __nv_bfloat16* __restrict__ y) {
    int row = blockIdx.x;
    int tid = threadIdx.x;
    const float* xr = x + (size_t)row * TB_D;
    float4 v = *(const float4*)(xr + tid * 4);
    float ss = v.x*v.x + v.y*v.y + v.z*v.z + v.w*v.w;
    #pragma unroll
    for (int o = 16; o; o >>= 1) ss += __shfl_xor_sync(0xffffffffu, ss, o);
    __shared__ float wred[8];
    __shared__ float s_scale;
    if ((tid & 31) == 0) wred[tid >> 5] = ss;
    __syncthreads();
    if (tid == 0) {
        float tot = 0.f;
        #pragma unroll
        for (int i = 0; i < 8; i++) tot += wred[i];
        s_scale = 32.0f / fmaxf(sqrtf(tot), 1e-12f);
    }
    __syncthreads();
    float sc = s_scale;
    float vals[4] = {v.x * sc, v.y * sc, v.z * sc, v.w * sc};
    size_t base = (size_t)row * TB_D3 + (size_t)tid * 12;
    #pragma unroll
    for (int j = 0; j < 4; j++) {
        __nv_bfloat16 hi, lo; split_bf16(vals[j], hi, lo);
        y[base + 3*j] = hi; y[base + 3*j + 1] = lo; y[base + 3*j + 2] = hi;
    }
}

// ---------------- tcgen05 split-bf16 GEMM ------------------------------------
// C[M,N] = A3[M,K3] x B3[N,K3]^T ; CTA tile 128x256, 4-stage cp.async pipeline.
// EPI: 0 = fp32 out, 1 = fp32 + residual, 2 = gelu -> split-bf16 triple out
#define GNST 4
#define STAGE_A 16384
#define STAGE_BYTES 49152
#define GEMM_SMEM (GNST * STAGE_BYTES + 1024)

template<int EPI>
__device__ __forceinline__ void tc_gemm_body(
    const __nv_bfloat16* __restrict__ A3, const __nv_bfloat16* __restrict__ B3,
    const float* __restrict__ res, void* __restrict__ Cout,
    int N, int K3, int m0, int n0)
{
#if HAS_TCGEN05
    extern __shared__ char dsm_raw[];
    __shared__ uint32_t s_tmem;
    __shared__ __align__(8) uint64_t s_bars[2 * GNST]; // full[4], empty[4]
    uint32_t dsm = (smem_u32(dsm_raw) + 1023) & ~1023u;
    int tid = threadIdx.x, wid = tid >> 5, lane = tid & 31;

    if (wid == 0) {
        asm volatile("tcgen05.alloc.cta_group::1.sync.aligned.shared::cta.b32 [%0], %1;"
                     :: "r"(smem_u32((void*)&s_tmem)), "r"(256u) : "memory");
    }
    if (tid == 0) {
        #pragma unroll
        for (int s = 0; s < GNST; s++) {
            mbar_init(smem_u32(&s_bars[s]), 128);        // full: 128 cp.async arrivals
            mbar_init(smem_u32(&s_bars[GNST + s]), 1);   // empty: 1 tcgen05.commit
        }
    }
    __syncthreads();
    uint32_t tmem = s_tmem;

    const __nv_bfloat16* Ab = A3 + (size_t)m0 * K3;
    const __nv_bfloat16* Bb = B3 + (size_t)n0 * K3;
    int nch = K3 >> 6;   // 64 bf16 elements per chunk (128B SW128 row); multiple of 4

    for (int c = 0; c < nch; c++) {
        int s = c & 3;
        uint32_t sA = dsm + s * STAGE_BYTES;
        uint32_t sB = sA + STAGE_A;
        if (c >= GNST)
            mbar_wait(smem_u32(&s_bars[GNST + s]), ((c >> 2) - 1) & 1);
        const __nv_bfloat16* ga = Ab + ((size_t)c << 6);
        const __nv_bfloat16* gb = Bb + ((size_t)c << 6);
        #pragma unroll
        for (int i = 0; i < 8; i++) {          // A: 128 rows x 128B
            int u = tid + (i << 7);
            int r = u >> 3, q = u & 7;
            cp_async16(sA + SWZ(r * 128 + q * 16), ga + (size_t)r * K3 + q * 8);
        }
        #pragma unroll
        for (int i = 0; i < 16; i++) {         // B: 256 rows x 128B
            int u = tid + (i << 7);
            int r = u >> 3, q = u & 7;
            cp_async16(sB + SWZ(r * 128 + q * 16), gb + (size_t)r * K3 + q * 8);
        }
        cp_async_arrive(smem_u32(&s_bars[s]));
        if (wid == 0) {
            mbar_wait(smem_u32(&s_bars[s]), (c >> 2) & 1);
            if (elect_one()) {
                uint64_t ad  = MK_DESC(sA);
                uint64_t bd0 = MK_DESC(sB);
                uint64_t bd1 = MK_DESC(sB + 16384);   // B rows 128..255
                #pragma unroll
                for (int k = 0; k < 4; k++) {
                    uint32_t en = (c | k) ? 1u : 0u;
                    mma_f16_ss(tmem,       ad + 2*k, bd0 + 2*k, MMA_IDESC, en);
                    mma_f16_ss(tmem + 128, ad + 2*k, bd1 + 2*k, MMA_IDESC, en);
                }
                asm volatile(
                    "tcgen05.commit.cta_group::1.mbarrier::arrive::one.shared::cluster.b64 [%0];"
                    :: "r"(smem_u32(&s_bars[GNST + s])) : "memory");
            }
        }
    }
    // drain: the last 4 chunks' commits (one per stage) carry parity
    // ((nch>>2)-1)&1 and were never consumed in-loop; waiting them guarantees
    // ALL MMAs (including the final chunk's) have completed.
    {
        uint32_t pe = ((uint32_t)(nch >> 2) - 1u) & 1u;
        #pragma unroll
        for (int s = 0; s < GNST; s++)
            mbar_wait(smem_u32(&s_bars[GNST + s]), pe);
    }
    asm volatile("tcgen05.fence::after_thread_sync;" ::: "memory");

    // epilogue: each warp reads its 32-lane TMEM subpartition, 32 cols at a time
    int mrow = m0 + wid * 32 + lane;
    for (int cb = 0; cb < 256; cb += 32) {
        uint32_t dr[32];
        TCGEN05_LD_32X32B_X32(dr, tmem + cb);
        asm volatile("tcgen05.wait::ld.sync.aligned;" ::: "memory");
        int n = n0 + cb;
        if (EPI == 2) {
            __nv_bfloat16* C = (__nv_bfloat16*)Cout;
            size_t base = (size_t)mrow * (3 * (size_t)N) + 3 * (size_t)n;
            #pragma unroll
            for (int j = 0; j < 32; j++) {
                float f = gelu_tanh(__uint_as_float(dr[j]));
                __nv_bfloat16 hi, lo; split_bf16(f, hi, lo);
                C[base + 3*j] = hi; C[base + 3*j + 1] = lo; C[base + 3*j + 2] = hi;
            }
        } else {
            float* C = (float*)Cout;
            size_t base = (size_t)mrow * N + n;
            #pragma unroll
            for (int j = 0; j < 32; j += 4) {
                float4 v = make_float4(__uint_as_float(dr[j]),   __uint_as_float(dr[j+1]),
                                       __uint_as_float(dr[j+2]), __uint_as_float(dr[j+3]));
                if (EPI == 1) {
                    float4 r4 = *(const float4*)(res + base + j);
                    v.x += r4.x; v.y += r4.y; v.z += r4.z; v.w += r4.w;
                }
                *(float4*)(C + base + j) = v;
            }
        }
    }
    __syncthreads();
    if (wid == 0) {
        asm volatile("tcgen05.relinquish_alloc_permit.cta_group::1.sync.aligned;");
        asm volatile("tcgen05.dealloc.cta_group::1.sync.aligned.b32 %0, %1;"
                     :: "r"(tmem), "r"(256u));
    }
#else
    // ---------------- SIMT fallback (non-sm_103a cubin only) -----------------
    // Correct but slow; exists so the compute_103 gencode pass compiles and,
    // if ever selected at runtime, still produces the right answer.
    extern __shared__ char dsm_raw[];
    __nv_bfloat16* As = (__nv_bfloat16*)dsm_raw;   // one A-row chunk
    const int CH = 2048;
    int tid = threadIdx.x;
    int n_a = n0 + 2 * tid, n_b = n_a + 1;
    for (int m = 0; m < 128; m++) {
        const __nv_bfloat16* arow = A3 + (size_t)(m0 + m) * K3;
        float acc0 = 0.f, acc1 = 0.f;
        for (int c0 = 0; c0 < K3; c0 += CH) {
            int len = min(CH, K3 - c0);
            for (int i = tid; i < len / 8; i += 128)
                ((float4*)As)[i] = ((const float4*)(arow + c0))[i];
            __syncthreads();
            const __nv_bfloat16* b0 = B3 + (size_t)n_a * K3 + c0;
            const __nv_bfloat16* b1 = B3 + (size_t)n_b * K3 + c0;
            for (int k = 0; k < len; k++) {
                float a = __bfloat162float(As[k]);
                acc0 = fmaf(a, __bfloat162float(b0[k]), acc0);
                acc1 = fmaf(a, __bfloat162float(b1[k]), acc1);
            }
            __syncthreads();
        }
        int mrow = m0 + m;
        if (EPI == 2) {
            __nv_bfloat16* C = (__nv_bfloat16*)Cout;
            size_t base = (size_t)mrow * (3 * (size_t)N);
            float f0 = gelu_tanh(acc0), f1 = gelu_tanh(acc1);
            __nv_bfloat16 hi, lo;
            split_bf16(f0, hi, lo);
            C[base + 3*n_a] = hi; C[base + 3*n_a + 1] = lo; C[base + 3*n_a + 2] = hi;
            split_bf16(f1, hi, lo);
            C[base + 3*n_b] = hi; C[base + 3*n_b + 1] = lo; C[base + 3*n_b + 2] = hi;
        } else {
            float* C = (float*)Cout;
            size_t base = (size_t)mrow * N;
            if (EPI == 1) { acc0 += res[base + n_a]; acc1 += res[base + n_b]; }
            C[base + n_a] = acc0; C[base + n_b] = acc1;
        }
    }
#endif
}

template<int EPI>
__global__ __launch_bounds__(128, 1) void tc_gemm(
    const __nv_bfloat16* __restrict__ A3, const __nv_bfloat16* __restrict__ B3,
    const float* __restrict__ res, void* __restrict__ C, int N, int K3)
{
    tc_gemm_body<EPI>(A3, B3, res, C, N, K3, blockIdx.y * 128, blockIdx.x * 256);
}

__global__ __launch_bounds__(128, 1) void tc_gemm_qkv(
    const __nv_bfloat16* __restrict__ A3,
    const __nv_bfloat16* __restrict__ b0, const __nv_bfloat16* __restrict__ b1,
    const __nv_bfloat16* __restrict__ b2,
    float* __restrict__ c0, float* __restrict__ c1, float* __restrict__ c2)
{
    const __nv_bfloat16* B3 = (blockIdx.z == 0) ? b0 : ((blockIdx.z == 1) ? b1 : b2);
    float* C = (blockIdx.z == 0) ? c0 : ((blockIdx.z == 1) ? c1 : c2);
    tc_gemm_body<0>(A3, B3, nullptr, C, TB_D, TB_D3, blockIdx.y * 128, blockIdx.x * 256);
}

// ---------------- causal flash attention, fp32, 64x64 tiles ------------------
__global__ __launch_bounds__(256) void attn_kernel(
    const float* __restrict__ Q, const float* __restrict__ Km,
    const float* __restrict__ Vm, __nv_bfloat16* __restrict__ O3)
{
    extern __shared__ float sm[];
    float* Qt  = sm;              // [64][68] Qt[d][q]
    float* KP  = Qt + 64 * 68;    // [64][68] Kt[d][k], later Pt[k][q]
    float* Vs  = KP + 64 * 68;    // [64][64]
    float* red = Vs + 64 * 64;    // [64][17]
    float* m_s = red + 64 * 17;
    float* l_s = m_s + 64;

    int tid = threadIdx.x;
    int tx = tid & 15, ty = tid >> 4;
    int qt0 = blockIdx.x * 64;
    int hh = blockIdx.y, bb = blockIdx.z;
    size_t base = ((size_t)bb * TB_S) * TB_D + (size_t)hh * TB_HD;
    const float* Qb = Q + base;
    const float* Kb = Km + base;
    const float* Vb = Vm + base;

    for (int i = tid; i < 1024; i += 256) {
        int r = i >> 4, c4 = (i & 15) << 2;
        float4 q4 = *(const float4*)(Qb + (size_t)(qt0 + r) * TB_D + c4);
        Qt[(c4 + 0) * 68 + r] = q4.x; Qt[(c4 + 1) * 68 + r] = q4.y;
        Qt[(c4 + 2) * 68 + r] = q4.z; Qt[(c4 + 3) * 68 + r] = q4.w;
    }
    if (tid < 64) { m_s[tid] = -1e30f; l_s[tid] = 0.f; }

    float o[4][4];
    #pragma unroll
    for (int i = 0; i < 4; i++)
        #pragma unroll
        for (int j = 0; j < 4; j++) o[i][j] = 0.f;

    int ntiles = blockIdx.x + 1;
    for (int kt = 0; kt < ntiles; kt++) {
        int k0 = kt * 64;
        __syncthreads();
        for (int i = tid; i < 1024; i += 256) {
            int r = i >> 4, c4 = (i & 15) << 2;
            float4 k4 = *(const float4*)(Kb + (size_t)(k0 + r) * TB_D + c4);
            KP[(c4 + 0) * 68 + r] = k4.x; KP[(c4 + 1) * 68 + r] = k4.y;
            KP[(c4 + 2) * 68 + r] = k4.z; KP[(c4 + 3) * 68 + r] = k4.w;
            float4 v4 = *(const float4*)(Vb + (size_t)(k0 + r) * TB_D + c4);
            *(float4*)(&Vs[r * 64 + c4]) = v4;
        }
        __syncthreads();

        float sfr[4][4];
        #pragma unroll
        for (int i = 0; i < 4; i++)
            #pragma unroll
            for (int j = 0; j < 4; j++) sfr[i][j] = 0.f;
        #pragma unroll 8
        for (int d = 0; d < 64; d++) {
            float4 a = *(const float4*)(&Qt[d * 68 + ty * 4]);
            float4 b = *(const float4*)(&KP[d * 68 + tx * 4]);
            float av[4] = {a.x, a.y, a.z, a.w};
            float bv[4] = {b.x, b.y, b.z, b.w};
            #pragma unroll
            for (int i = 0; i < 4; i++)
                #pragma unroll
                for (int j = 0; j < 4; j++)
                    sfr[i][j] = fmaf(av[i], bv[j], sfr[i][j]);
        }
        #pragma unroll
        for (int i = 0; i < 4; i++) {
            int qg = qt0 + ty * 4 + i;
            #pragma unroll
            for (int j = 0; j < 4; j++) {
                sfr[i][j] *= 0.125f;
                int kg = k0 + tx * 4 + j;
                if (kg > qg) sfr[i][j] = -1e30f;
            }
        }
        #pragma unroll
        for (int i = 0; i < 4; i++) {
            float mx = fmaxf(fmaxf(sfr[i][0], sfr[i][1]), fmaxf(sfr[i][2], sfr[i][3]));
            red[(ty * 4 + i) * 17 + tx] = mx;
        }
        __syncthreads();
        float mnew[4], alpha[4], psum[4];
        #pragma unroll
        for (int i = 0; i < 4; i++) {
            int qr = ty * 4 + i;
            float mt = red[qr * 17];
            #pragma unroll
            for (int t = 1; t < 16; t++) mt = fmaxf(mt, red[qr * 17 + t]);
            float mo = m_s[qr];
            float mn = fmaxf(mo, mt);
            mnew[i] = mn;
            alpha[i] = __expf(mo - mn);
            float ps = 0.f;
            #pragma unroll
            for (int j = 0; j < 4; j++) {
                float p = __expf(sfr[i][j] - mn);
                ps += p;
                KP[(tx * 4 + j) * 68 + qr] = p;
            }
            psum[i] = ps;
        }
        __syncthreads();
        #pragma unroll
        for (int i = 0; i < 4; i++) red[(ty * 4 + i) * 17 + tx] = psum[i];
        if (tx == 0) {
            #pragma unroll
            for (int i = 0; i < 4; i++) m_s[ty * 4 + i] = mnew[i];
        }
        __syncthreads();
        if (tx == 0) {
            #pragma unroll
            for (int i = 0; i < 4; i++) {
                int qr = ty * 4 + i;
                float s = 0.f;
                #pragma unroll
                for (int t = 0; t < 16; t++) s += red[qr * 17 + t];
                l_s[qr] = l_s[qr] * alpha[i] + s;
            }
        }
        #pragma unroll
        for (int i = 0; i < 4; i++)
            #pragma unroll
            for (int j = 0; j < 4; j++) o[i][j] *= alpha[i];
        #pragma unroll 8
        for (int kk = 0; kk < 64; kk++) {
            float4 a = *(const float4*)(&KP[kk * 68 + ty * 4]);
            float4 b = *(const float4*)(&Vs[kk * 64 + tx * 4]);
            float av[4] = {a.x, a.y, a.z, a.w};
            float bv[4] = {b.x, b.y, b.z, b.w};
            #pragma unroll
            for (int i = 0; i < 4; i++)
                #pragma unroll
                for (int j = 0; j < 4; j++)
                    o[i][j] = fmaf(av[i], bv[j], o[i][j]);
        }
    }
    __syncthreads();
    float inv[4];
    #pragma unroll
    for (int i = 0; i < 4; i++) inv[i] = 1.0f / l_s[ty * 4 + i];
    #pragma unroll
    for (int i = 0; i < 4; i++) {
        int s_idx = qt0 + ty * 4 + i;
        size_t obase = (size_t)((size_t)bb * TB_S + s_idx) * TB_D3 + 3 * (size_t)(hh * TB_HD + tx * 4);
        #pragma unroll
        for (int j = 0; j < 4; j++) {
            float f = o[i][j] * inv[i];
            __nv_bfloat16 hi, lo; split_bf16(f, hi, lo);
            O3[obase + 3*j] = hi; O3[obase + 3*j + 1] = lo; O3[obase + 3*j + 2] = hi;
        }
    }
}

// ---------------- launch ------------------------------------------------------
static const int ATTN_SMEM = (64 * 68 * 2 + 64 * 64 + 64 * 17 + 128) * (int)sizeof(float);

extern "C" void kernel_launch(void* const* d_in, const int* in_sizes, int n_in,
                              void* d_out, int out_size) {
    const float* x     = (const float*)d_in[0];
    const float* wq    = (const float*)d_in[1];
    const float* wk    = (const float*)d_in[2];
    const float* wv    = (const float*)d_in[3];
    const float* wo    = (const float*)d_in[4];
    const float* w_in  = (const float*)d_in[5];
    const float* w_out = (const float*)d_in[6];
    float* out = (float*)d_out;
    (void)in_sizes; (void)n_in; (void)out_size;

    __nv_bfloat16 *xn3, *att3, *ff3, *wq3, *wk3, *wv3, *wo3, *win3, *wout3;
    float *q, *k, *v, *h;
    cudaGetSymbolAddress((void**)&xn3,  g_xn3);
    cudaGetSymbolAddress((void**)&att3, g_att3);
    cudaGetSymbolAddress((void**)&ff3,  g_ff3);
    cudaGetSymbolAddress((void**)&q,    g_q);
    cudaGetSymbolAddress((void**)&k,    g_k);
    cudaGetSymbolAddress((void**)&v,    g_v);
    cudaGetSymbolAddress((void**)&h,    g_h);
    cudaGetSymbolAddress((void**)&wq3,  g_wq3);
    cudaGetSymbolAddress((void**)&wk3,  g_wk3);
    cudaGetSymbolAddress((void**)&wv3,  g_wv3);
    cudaGetSymbolAddress((void**)&wo3,  g_wo3);
    cudaGetSymbolAddress((void**)&win3, g_win3);
    cudaGetSymbolAddress((void**)&wout3, g_wout3);

    cudaFuncSetAttribute(attn_kernel, cudaFuncAttributeMaxDynamicSharedMemorySize, ATTN_SMEM);
    cudaFuncSetAttribute(tc_gemm_qkv, cudaFuncAttributeMaxDynamicSharedMemorySize, GEMM_SMEM);
    cudaFuncSetAttribute(tc_gemm<1>,  cudaFuncAttributeMaxDynamicSharedMemorySize, GEMM_SMEM);
    cudaFuncSetAttribute(tc_gemm<2>,  cudaFuncAttributeMaxDynamicSharedMemorySize, GEMM_SMEM);

    dim3 cwb(32, 8);
    // weight convert+transpose: W[K][N] -> [N][3K]
    conv_w_kernel<<<dim3(TB_D / 32, TB_D / 32), cwb>>>(wq,    wq3,  TB_D, TB_D);
    conv_w_kernel<<<dim3(TB_D / 32, TB_D / 32), cwb>>>(wk,    wk3,  TB_D, TB_D);
    conv_w_kernel<<<dim3(TB_D / 32, TB_D / 32), cwb>>>(wv,    wv3,  TB_D, TB_D);
    conv_w_kernel<<<dim3(TB_D / 32, TB_D / 32), cwb>>>(wo,    wo3,  TB_D, TB_D);
    conv_w_kernel<<<dim3(TB_F / 32, TB_D / 32), cwb>>>(w_in,  win3, TB_D, TB_F);
    conv_w_kernel<<<dim3(TB_D / 32, TB_F / 32), cwb>>>(w_out, wout3, TB_F, TB_D);

    // 1. xn3 = split(srmsnorm(x))
    srmsnorm3_kernel<<<TB_T, 256>>>(x, xn3);
    // 2. q,k,v = xn @ {wq,wk,wv}  (fp32 out)
    tc_gemm_qkv<<<dim3(TB_D / 256, TB_T / 128, 3), 128, GEMM_SMEM>>>(xn3, wq3, wk3, wv3, q, k, v);
    // 3. causal attention -> att3 (split-bf16)
    attn_kernel<<<dim3(TB_S / 64, TB_H, TB_B), 256, ATTN_SMEM>>>(q, k, v, att3);
    // 4. h = x + att @ wo
    tc_gemm<1><<<dim3(TB_D / 256, TB_T / 128), 128, GEMM_SMEM>>>(att3, wo3, x, h, TB_D, TB_D3);
    // 5. xn3 = split(srmsnorm(h))
    srmsnorm3_kernel<<<TB_T, 256>>>(h, xn3);
    // 6. ff3 = split(gelu(hn @ w_in))
    tc_gemm<2><<<dim3(TB_F / 256, TB_T / 128), 128, GEMM_SMEM>>>(xn3, win3, nullptr, ff3, TB_F, TB_D3);
    // 7. out = h + ff @ w_out
    tc_gemm<1><<<dim3(TB_D / 256, TB_T / 128), 128, GEMM_SMEM>>>(ff3, wout3, h, out, TB_D, TB_F3);
}

// round 5
// speedup vs baseline: 2.0178x; 1.4476x over previous
#include <cuda_runtime.h>
#include <cuda_bf16.h>
#include <math.h>
#include <stdint.h>

// Problem dims (fixed by the reference)
#define TB_B 2
#define TB_S 2048
#define TB_D 1024
#define TB_F 4096
#define TB_H 16
#define TB_HD 64
#define TB_T (TB_B * TB_S)   // 4096 tokens
#define TB_D3 (3 * TB_D)     // 3072 (split-bf16 expanded K)
#define TB_F3 (3 * TB_F)     // 12288

// tcgen05 / f32x2 are arch-feature-specific: only in the sm_103a/sm_100a pass.
#if defined(__CUDA_ARCH_FEAT_SM103_ALL) || defined(__CUDA_ARCH_FEAT_SM100_ALL)
#define HAS_TCGEN05 1
#else
#define HAS_TCGEN05 0
#endif

// ---------------- scratch (no allocation allowed -> device globals) ----------
// Split layout (segmented): A-side rows = [hi(K) | lo(K) | hi(K)],
//                           B-side rows = [hi(K) | hi(K) | lo(K)]
// so  sum over K3 = hi.hi + lo.hi + hi.lo  =  x.w - lo.lo  (~2^-18 rel err)
__device__ __nv_bfloat16 g_xn3 [(size_t)TB_T * TB_D3];
__device__ __nv_bfloat16 g_att3[(size_t)TB_T * TB_D3];
__device__ __nv_bfloat16 g_ff3 [(size_t)TB_T * TB_F3];
__device__ float g_q [(size_t)TB_T * TB_D];
__device__ float g_k [(size_t)TB_T * TB_D];
__device__ float g_v [(size_t)TB_T * TB_D];
__device__ float g_h [(size_t)TB_T * TB_D];
__device__ __nv_bfloat16 g_wq3 [(size_t)TB_D * TB_D3];  // [n][3K]
__device__ __nv_bfloat16 g_wk3 [(size_t)TB_D * TB_D3];
__device__ __nv_bfloat16 g_wv3 [(size_t)TB_D * TB_D3];
__device__ __nv_bfloat16 g_wo3 [(size_t)TB_D * TB_D3];
__device__ __nv_bfloat16 g_win3[(size_t)TB_F * TB_D3];  // [4096][3072]
__device__ __nv_bfloat16 g_wout3[(size_t)TB_D * TB_F3]; // [1024][12288]

// ---------------- helpers ----------------------------------------------------
__device__ __forceinline__ uint32_t smem_u32(const void* p) {
    uint32_t a;
    asm("{ .reg .u64 t; cvta.to.shared.u64 t, %1; cvt.u32.u64 %0, t; }" : "=r"(a) : "l"(p));
    return a;
}
__device__ __forceinline__ void split_bf16(float x, __nv_bfloat16& hi, __nv_bfloat16& lo) {
    hi = __float2bfloat16(x);
    lo = __float2bfloat16(x - __bfloat162float(hi));
}
__device__ __forceinline__ float gelu_tanh(float v) {
    const float c = 0.79788456080286535588f;
    float t = c * (v + 0.044715f * v * v * v);
    return 0.5f * v * (1.0f + tanhf(t));
}
__device__ __forceinline__ uint2 pack4bf(__nv_bfloat16 a, __nv_bfloat16 b,
                                         __nv_bfloat16 c, __nv_bfloat16 d) {
    uint2 r;
    r.x = (uint32_t)__bfloat16_as_ushort(a) | ((uint32_t)__bfloat16_as_ushort(b) << 16);
    r.y = (uint32_t)__bfloat16_as_ushort(c) | ((uint32_t)__bfloat16_as_ushort(d) << 16);
    return r;
}

// ---- packed f32x2 math (sm_103a) --------------------------------------------
#if HAS_TCGEN05
typedef uint64_t pk2;
__device__ __forceinline__ pk2 pkzero() { return 0ull; }
__device__ __forceinline__ pk2 pk(float x, float y) {
    pk2 r; asm("mov.b64 %0, {%1, %2};" : "=l"(r) : "f"(x), "f"(y)); return r;
}
__device__ __forceinline__ void fma2(pk2& d, pk2 a, pk2 b) {
    asm("fma.rn.f32x2 %0, %1, %2, %0;" : "+l"(d) : "l"(a), "l"(b));
}
__device__ __forceinline__ void mul2(pk2& d, pk2 a) {
    asm("mul.rn.f32x2 %0, %0, %1;" : "+l"(d) : "l"(a));
}
__device__ __forceinline__ void unpk(pk2 v, float& x, float& y) {
    asm("mov.b64 {%0, %1}, %2;" : "=f"(x), "=f"(y) : "l"(v));
}
#else
typedef float2 pk2;
__device__ __forceinline__ pk2 pkzero() { return make_float2(0.f, 0.f); }
__device__ __forceinline__ pk2 pk(float x, float y) { return make_float2(x, y); }
__device__ __forceinline__ void fma2(pk2& d, pk2 a, pk2 b) {
    d.x = fmaf(a.x, b.x, d.x); d.y = fmaf(a.y, b.y, d.y);
}
__device__ __forceinline__ void mul2(pk2& d, pk2 a) { d.x *= a.x; d.y *= a.y; }
__device__ __forceinline__ void unpk(pk2 v, float& x, float& y) { x = v.x; y = v.y; }
#endif

#if HAS_TCGEN05
__device__ __forceinline__ uint32_t elect_one() {
    uint32_t p;
    asm volatile("{ .reg .pred p; elect.sync _|p, 0xFFFFFFFF; selp.b32 %0, 1, 0, p; }" : "=r"(p));
    return p;
}
__device__ __forceinline__ void mbar_init(uint32_t a, uint32_t cnt) {
    asm volatile("mbarrier.init.shared.b64 [%0], %1;" :: "r"(a), "r"(cnt) : "memory");
}
__device__ __forceinline__ void mbar_wait(uint32_t a, uint32_t parity) {
    asm volatile(
        "{\n\t.reg .pred P;\n\t"
        "LW%=:\n\t"
        "mbarrier.try_wait.parity.acquire.cta.shared::cta.b64 P, [%0], %1, 0x989680;\n\t"
        "@P bra LD%=;\n\t"
        "bra LW%=;\n\t"
        "LD%=:\n\t}"
        :: "r"(a), "r"(parity) : "memory");
}
__device__ __forceinline__ void cp_async16(uint32_t dst, const void* src) {
    asm volatile("cp.async.cg.shared.global [%0], [%1], 16;" :: "r"(dst), "l"(src) : "memory");
}
__device__ __forceinline__ void cp_async_arrive(uint32_t mbar) {
    asm volatile("cp.async.mbarrier.arrive.noinc.shared::cta.b64 [%0];" :: "r"(mbar) : "memory");
}
__device__ __forceinline__ void mma_f16_ss(uint32_t d, uint64_t ad, uint64_t bd,
                                           uint32_t idesc, uint32_t en) {
    asm volatile(
        "{\n\t.reg .pred p;\n\tsetp.ne.u32 p, %4, 0;\n\t"
        "tcgen05.mma.cta_group::1.kind::f16 [%0], %1, %2, %3, {%5, %5, %5, %5}, p;\n\t}"
        :: "r"(d), "l"(ad), "l"(bd), "r"(idesc), "r"(en), "r"(0u) : "memory");
}
#define TCGEN05_LD_32X32B_X32(r, tmem_addr) \
    asm volatile( \
        "tcgen05.ld.sync.aligned.32x32b.x32.b32 " \
        "{%0, %1, %2, %3, %4, %5, %6, %7, " \
        " %8, %9, %10, %11, %12, %13, %14, %15, " \
        " %16, %17, %18, %19, %20, %21, %22, %23, " \
        " %24, %25, %26, %27, %28, %29, %30, %31}, [%32];" \
        : "=r"((r)[0]),  "=r"((r)[1]),  "=r"((r)[2]),  "=r"((r)[3]), \
          "=r"((r)[4]),  "=r"((r)[5]),  "=r"((r)[6]),  "=r"((r)[7]), \
          "=r"((r)[8]),  "=r"((r)[9]),  "=r"((r)[10]), "=r"((r)[11]), \
          "=r"((r)[12]), "=r"((r)[13]), "=r"((r)[14]), "=r"((r)[15]), \
          "=r"((r)[16]), "=r"((r)[17]), "=r"((r)[18]), "=r"((r)[19]), \
          "=r"((r)[20]), "=r"((r)[21]), "=r"((r)[22]), "=r"((r)[23]), \
          "=r"((r)[24]), "=r"((r)[25]), "=r"((r)[26]), "=r"((r)[27]), \
          "=r"((r)[28]), "=r"((r)[29]), "=r"((r)[30]), "=r"((r)[31]) \
        : "r"(tmem_addr))
#endif // HAS_TCGEN05

#define SWZ(o) ((o) ^ (((o) >> 3) & 0x70))
#define SMEM_DESC_BASE ((uint64_t(2) << 61) | (uint64_t(1) << 46) | (uint64_t(64) << 32) | (uint64_t(1) << 16))
#define MK_DESC(addr) (SMEM_DESC_BASE | ((uint64_t)((addr) >> 4) & 0x3FFF))
// idesc: F32 accum, A=BF16, B=BF16, N=128, M=128
#define MMA_IDESC 0x8200490u

// ---------------- weight convert+transpose: W[K][N] -> o[N][3K] seg [hi|hi|lo]
__device__ __forceinline__ void conv_w_body(const float* __restrict__ W,
                                            __nv_bfloat16* __restrict__ o, int K, int N) {
    __shared__ float t[32][33];
    int n0 = blockIdx.x * 32, k0 = blockIdx.y * 32;
    if (n0 >= N || k0 >= K) return;
    int tx = threadIdx.x, ty = threadIdx.y; // 32 x 8
    #pragma unroll
    for (int i = 0; i < 4; i++)
        t[ty + 8 * i][tx] = W[(size_t)(k0 + ty + 8 * i) * N + n0 + tx];
    __syncthreads();
    size_t K3 = 3 * (size_t)K;
    #pragma unroll
    for (int i = 0; i < 4; i++) {
        int nn = ty + 8 * i, kk = tx;
        float x = t[kk][nn];
        __nv_bfloat16 hi, lo; split_bf16(x, hi, lo);
        size_t base = (size_t)(n0 + nn) * K3 + (size_t)(k0 + kk);
        o[base] = hi; o[base + K] = hi; o[base + 2 * K] = lo;   // [hi|hi|lo]
    }
}
// 4 square weights in one launch (grid.z selects)
__global__ void conv_w4_kernel(const float* __restrict__ w0, const float* __restrict__ w1,
                               const float* __restrict__ w2, const float* __restrict__ w3,
                               __nv_bfloat16* o0, __nv_bfloat16* o1,
                               __nv_bfloat16* o2, __nv_bfloat16* o3) {
    const float* W = (blockIdx.z == 0) ? w0 : (blockIdx.z == 1) ? w1 : (blockIdx.z == 2) ? w2 : w3;
    __nv_bfloat16* O = (blockIdx.z == 0) ? o0 : (blockIdx.z == 1) ? o1 : (blockIdx.z == 2) ? o2 : o3;
    conv_w_body(W, O, TB_D, TB_D);
}
// the two FFN weights in one launch
__global__ void conv_wff_kernel(const float* __restrict__ w_in, const float* __restrict__ w_out,
                                __nv_bfloat16* win3, __nv_bfloat16* wout3) {
    if (blockIdx.z == 0) conv_w_body(w_in,  win3,  TB_D, TB_F);
    else                 conv_w_body(w_out, wout3, TB_F, TB_D);
}

// ---------------- srmsnorm -> split-bf16 segmented [hi|lo|hi] ----------------
__global__ void srmsnorm3_kernel(const float* __restrict__ x, __nv_bfloat16* __restrict__ y) {
    int row = blockIdx.x;
    int tid = threadIdx.x;
    const float* xr = x + (size_t)row * TB_D;
    float4 v = *(const float4*)(xr + tid * 4);
    float ss = v.x*v.x + v.y*v.y + v.z*v.z + v.w*v.w;
    #pragma unroll
    for (int o = 16; o; o >>= 1) ss += __shfl_xor_sync(0xffffffffu, ss, o);
    __shared__ float wred[8];
    __shared__ float s_scale;
    if ((tid & 31) == 0) wred[tid >> 5] = ss;
    __syncthreads();
    if (tid == 0) {
        float tot = 0.f;
        #pragma unroll
        for (int i = 0; i < 8; i++) tot += wred[i];
        s_scale = 32.0f / fmaxf(sqrtf(tot), 1e-12f);
    }
    __syncthreads();
    float sc = s_scale;
    float vals[4] = {v.x * sc, v.y * sc, v.z * sc, v.w * sc};
    __nv_bfloat16 hi[4], lo[4];
    #pragma unroll
    for (int j = 0; j < 4; j++) split_bf16(vals[j], hi[j], lo[j]);
    uint2 h2 = pack4bf(hi[0], hi[1], hi[2], hi[3]);
    uint2 l2 = pack4bf(lo[0], lo[1], lo[2], lo[3]);
    size_t base = (size_t)row * TB_D3 + tid * 4;
    *(uint2*)(y + base)              = h2;
    *(uint2*)(y + base + TB_D)       = l2;
    *(uint2*)(y + base + 2 * TB_D)   = h2;
}

// ---------------- tcgen05 split-bf16 GEMM ------------------------------------
// C[M,N] = A3[M,K3] x B3[N,K3]^T ; CTA tile 128x256, 4-stage cp.async pipeline.
// EPI: 0 = fp32 out, 1 = fp32 + residual, 2 = gelu -> segmented split-bf16 out
#define GNST 4
#define STAGE_A 16384
#define STAGE_BYTES 49152
#define GEMM_SMEM (GNST * STAGE_BYTES + 1024)

template<int EPI>
__device__ __forceinline__ void tc_gemm_body(
    const __nv_bfloat16* __restrict__ A3, const __nv_bfloat16* __restrict__ B3,
    const float* __restrict__ res, void* __restrict__ Cout,
    int N, int K3, int m0, int n0)
{
#if HAS_TCGEN05
    extern __shared__ char dsm_raw[];
    __shared__ uint32_t s_tmem;
    __shared__ __align__(8) uint64_t s_bars[2 * GNST]; // full[4], empty[4]
    uint32_t dsm = (smem_u32(dsm_raw) + 1023) & ~1023u;
    int tid = threadIdx.x, wid = tid >> 5, lane = tid & 31;

    if (wid == 0) {
        asm volatile("tcgen05.alloc.cta_group::1.sync.aligned.shared::cta.b32 [%0], %1;"
                     :: "r"(smem_u32((void*)&s_tmem)), "r"(256u) : "memory");
    }
    if (tid == 0) {
        #pragma unroll
        for (int s = 0; s < GNST; s++) {
            mbar_init(smem_u32(&s_bars[s]), 128);        // full: 128 cp.async arrivals
            mbar_init(smem_u32(&s_bars[GNST + s]), 1);   // empty: 1 tcgen05.commit
        }
    }
    __syncthreads();
    uint32_t tmem = s_tmem;

    const __nv_bfloat16* Ab = A3 + (size_t)m0 * K3;
    const __nv_bfloat16* Bb = B3 + (size_t)n0 * K3;
    int nch = K3 >> 6;   // 64 bf16 per chunk (128B SW128 row); multiple of 4

    for (int c = 0; c < nch; c++) {
        int s = c & 3;
        uint32_t sA = dsm + s * STAGE_BYTES;
        uint32_t sB = sA + STAGE_A;
        if (c >= GNST)
            mbar_wait(smem_u32(&s_bars[GNST + s]), ((c >> 2) - 1) & 1);
        const __nv_bfloat16* ga = Ab + ((size_t)c << 6);
        const __nv_bfloat16* gb = Bb + ((size_t)c << 6);
        #pragma unroll
        for (int i = 0; i < 8; i++) {          // A: 128 rows x 128B
            int u = tid + (i << 7);
            int r = u >> 3, q = u & 7;
            cp_async16(sA + SWZ(r * 128 + q * 16), ga + (size_t)r * K3 + q * 8);
        }
        #pragma unroll
        for (int i = 0; i < 16; i++) {         // B: 256 rows x 128B
            int u = tid + (i << 7);
            int r = u >> 3, q = u & 7;
            cp_async16(sB + SWZ(r * 128 + q * 16), gb + (size_t)r * K3 + q * 8);
        }
        cp_async_arrive(smem_u32(&s_bars[s]));
        if (wid == 0) {
            mbar_wait(smem_u32(&s_bars[s]), (c >> 2) & 1);
            if (elect_one()) {
                uint64_t ad  = MK_DESC(sA);
                uint64_t bd0 = MK_DESC(sB);
                uint64_t bd1 = MK_DESC(sB + 16384);   // B rows 128..255
                #pragma unroll
                for (int k = 0; k < 4; k++) {
                    uint32_t en = (c | k) ? 1u : 0u;
                    mma_f16_ss(tmem,       ad + 2*k, bd0 + 2*k, MMA_IDESC, en);
                    mma_f16_ss(tmem + 128, ad + 2*k, bd1 + 2*k, MMA_IDESC, en);
                }
                asm volatile(
                    "tcgen05.commit.cta_group::1.mbarrier::arrive::one.shared::cluster.b64 [%0];"
                    :: "r"(smem_u32(&s_bars[GNST + s])) : "memory");
            }
        }
    }
    // drain: last 4 commits (one per stage, parity ((nch>>2)-1)&1) were never
    // consumed in-loop; waiting them guarantees ALL MMAs completed.
    {
        uint32_t pe = ((uint32_t)(nch >> 2) - 1u) & 1u;
        #pragma unroll
        for (int s = 0; s < GNST; s++)
            mbar_wait(smem_u32(&s_bars[GNST + s]), pe);
    }
    asm volatile("tcgen05.fence::after_thread_sync;" ::: "memory");

    // epilogue: each warp reads its 32-lane TMEM subpartition, 32 cols at a time
    int mrow = m0 + wid * 32 + lane;
    for (int cb = 0; cb < 256; cb += 32) {
        uint32_t dr[32];
        TCGEN05_LD_32X32B_X32(dr, tmem + cb);
        asm volatile("tcgen05.wait::ld.sync.aligned;" ::: "memory");
        int n = n0 + cb;
        if (EPI == 2) {
            __nv_bfloat16* C = (__nv_bfloat16*)Cout;
            size_t rb = (size_t)mrow * (3 * (size_t)N);
            __nv_bfloat16 hiA[32], loA[32];
            #pragma unroll
            for (int j = 0; j < 32; j++) {
                float f = gelu_tanh(__uint_as_float(dr[j]));
                split_bf16(f, hiA[j], loA[j]);
            }
            uint4* ph  = (uint4*)(C + rb + n);
            uint4* pl  = (uint4*)(C + rb + (size_t)N + n);
            uint4* ph2 = (uint4*)(C + rb + 2 * (size_t)N + n);
            #pragma unroll
            for (int t2 = 0; t2 < 4; t2++) {
                uint4 vh = ((uint4*)hiA)[t2];
                ph[t2] = vh; ph2[t2] = vh;
                pl[t2] = ((uint4*)loA)[t2];
            }
        } else {
            float* C = (float*)Cout;
            size_t base = (size_t)mrow * N + n;
            #pragma unroll
            for (int j = 0; j < 32; j += 4) {
                float4 v = make_float4(__uint_as_float(dr[j]),   __uint_as_float(dr[j+1]),
                                       __uint_as_float(dr[j+2]), __uint_as_float(dr[j+3]));
                if (EPI == 1) {
                    float4 r4 = *(const float4*)(res + base + j);
                    v.x += r4.x; v.y += r4.y; v.z += r4.z; v.w += r4.w;
                }
                *(float4*)(C + base + j) = v;
            }
        }
    }
    __syncthreads();
    if (wid == 0) {
        asm volatile("tcgen05.relinquish_alloc_permit.cta_group::1.sync.aligned;");
        asm volatile("tcgen05.dealloc.cta_group::1.sync.aligned.b32 %0, %1;"
                     :: "r"(tmem), "r"(256u));
    }
#else
    // ---------------- SIMT fallback (non-sm_103a cubin only) -----------------
    extern __shared__ char dsm_raw[];
    __nv_bfloat16* As = (__nv_bfloat16*)dsm_raw;
    const int CH = 2048;
    int tid = threadIdx.x;
    int n_a = n0 + 2 * tid, n_b = n_a + 1;
    for (int m = 0; m < 128; m++) {
        const __nv_bfloat16* arow = A3 + (size_t)(m0 + m) * K3;
        float acc0 = 0.f, acc1 = 0.f;
        for (int c0 = 0; c0 < K3; c0 += CH) {
            int len = min(CH, K3 - c0);
            for (int i = tid; i < len / 8; i += 128)
                ((float4*)As)[i] = ((const float4*)(arow + c0))[i];
            __syncthreads();
            const __nv_bfloat16* b0 = B3 + (size_t)n_a * K3 + c0;
            const __nv_bfloat16* b1 = B3 + (size_t)n_b * K3 + c0;
            for (int k = 0; k < len; k++) {
                float a = __bfloat162float(As[k]);
                acc0 = fmaf(a, __bfloat162float(b0[k]), acc0);
                acc1 = fmaf(a, __bfloat162float(b1[k]), acc1);
            }
            __syncthreads();
        }
        int mrow = m0 + m;
        if (EPI == 2) {
            __nv_bfloat16* C = (__nv_bfloat16*)Cout;
            size_t base = (size_t)mrow * (3 * (size_t)N);
            float f0 = gelu_tanh(acc0), f1 = gelu_tanh(acc1);
            __nv_bfloat16 hi, lo;
            split_bf16(f0, hi, lo);
            C[base + n_a] = hi; C[base + N + n_a] = lo; C[base + 2 * N + n_a] = hi;
            split_bf16(f1, hi, lo);
            C[base + n_b] = hi; C[base + N + n_b] = lo; C[base + 2 * N + n_b] = hi;
        } else {
            float* C = (float*)Cout;
            size_t base = (size_t)mrow * N;
            if (EPI == 1) { acc0 += res[base + n_a]; acc1 += res[base + n_b]; }
            C[base + n_a] = acc0; C[base + n_b] = acc1;
        }
    }
#endif
}

template<int EPI>
__global__ __launch_bounds__(128, 1) void tc_gemm(
    const __nv_bfloat16* __restrict__ A3, const __nv_bfloat16* __restrict__ B3,
    const float* __restrict__ res, void* __restrict__ C, int N, int K3)
{
    tc_gemm_body<EPI>(A3, B3, res, C, N, K3, blockIdx.y * 128, blockIdx.x * 256);
}

__global__ __launch_bounds__(128, 1) void tc_gemm_qkv(
    const __nv_bfloat16* __restrict__ A3,
    const __nv_bfloat16* __restrict__ b0, const __nv_bfloat16* __restrict__ b1,
    const __nv_bfloat16* __restrict__ b2,
    float* __restrict__ c0, float* __restrict__ c1, float* __restrict__ c2)
{
    const __nv_bfloat16* B3 = (blockIdx.z == 0) ? b0 : ((blockIdx.z == 1) ? b1 : b2);
    float* C = (blockIdx.z == 0) ? c0 : ((blockIdx.z == 1) ? c1 : c2);
    tc_gemm_body<0>(A3, B3, nullptr, C, TB_D, TB_D3, blockIdx.y * 128, blockIdx.x * 256);
}

// ---------------- causal flash attention, fp32+f32x2, 64x64 tiles ------------
__global__ __launch_bounds__(256) void attn_kernel(
    const float* __restrict__ Q, const float* __restrict__ Km,
    const float* __restrict__ Vm, __nv_bfloat16* __restrict__ O3)
{
    extern __shared__ float sm[];
    float* Qt  = sm;              // [64][68] Qt[d][q]
    float* KP  = Qt + 64 * 68;    // [64][68] Kt[d][k], later Pt[k][q]
    float* Vs  = KP + 64 * 68;    // [64][64]
    float* red = Vs + 64 * 64;    // [64][17]
    float* m_s = red + 64 * 17;
    float* l_s = m_s + 64;

    int tid = threadIdx.x;
    int tx = tid & 15, ty = tid >> 4;
    int qt0 = blockIdx.x * 64;
    int hh = blockIdx.y, bb = blockIdx.z;
    size_t base = ((size_t)bb * TB_S) * TB_D + (size_t)hh * TB_HD;
    const float* Qb = Q + base;
    const float* Kb = Km + base;
    const float* Vb = Vm + base;

    for (int i = tid; i < 1024; i += 256) {
        int r = i >> 4, c4 = (i & 15) << 2;
        float4 q4 = *(const float4*)(Qb + (size_t)(qt0 + r) * TB_D + c4);
        Qt[(c4 + 0) * 68 + r] = q4.x; Qt[(c4 + 1) * 68 + r] = q4.y;
        Qt[(c4 + 2) * 68 + r] = q4.z; Qt[(c4 + 3) * 68 + r] = q4.w;
    }
    if (tid < 64) { m_s[tid] = -1e30f; l_s[tid] = 0.f; }

    pk2 o2[4][2];
    #pragma unroll
    for (int i = 0; i < 4; i++) { o2[i][0] = pkzero(); o2[i][1] = pkzero(); }

    int ntiles = blockIdx.x + 1;
    for (int kt = 0; kt < ntiles; kt++) {
        int k0 = kt * 64;
        __syncthreads();
        for (int i = tid; i < 1024; i += 256) {
            int r = i >> 4, c4 = (i & 15) << 2;
            float4 k4 = *(const float4*)(Kb + (size_t)(k0 + r) * TB_D + c4);
            KP[(c4 + 0) * 68 + r] = k4.x; KP[(c4 + 1) * 68 + r] = k4.y;
            KP[(c4 + 2) * 68 + r] = k4.z; KP[(c4 + 3) * 68 + r] = k4.w;
            float4 v4 = *(const float4*)(Vb + (size_t)(k0 + r) * TB_D + c4);
            *(float4*)(&Vs[r * 64 + c4]) = v4;
        }
        __syncthreads();

        // S = (Q K^T) * scale  — packed f32x2 inner product
        pk2 acc2[4][2];
        #pragma unroll
        for (int i = 0; i < 4; i++) { acc2[i][0] = pkzero(); acc2[i][1] = pkzero(); }
        #pragma unroll 8
        for (int d = 0; d < 64; d++) {
            float4 a = *(const float4*)(&Qt[d * 68 + ty * 4]);
            float4 b = *(const float4*)(&KP[d * 68 + tx * 4]);
            pk2 b01 = pk(b.x, b.y), b23 = pk(b.z, b.w);
            float av[4] = {a.x, a.y, a.z, a.w};
            #pragma unroll
            for (int i = 0; i < 4; i++) {
                pk2 aa = pk(av[i], av[i]);
                fma2(acc2[i][0], aa, b01);
                fma2(acc2[i][1], aa, b23);
            }
        }
        float sfr[4][4];
        #pragma unroll
        for (int i = 0; i < 4; i++) {
            unpk(acc2[i][0], sfr[i][0], sfr[i][1]);
            unpk(acc2[i][1], sfr[i][2], sfr[i][3]);
        }
        #pragma unroll
        for (int i = 0; i < 4; i++) {
            int qg = qt0 + ty * 4 + i;
            #pragma unroll
            for (int j = 0; j < 4; j++) {
                sfr[i][j] *= 0.125f;
                int kg = k0 + tx * 4 + j;
                if (kg > qg) sfr[i][j] = -1e30f;
            }
        }
        #pragma unroll
        for (int i = 0; i < 4; i++) {
            float mx = fmaxf(fmaxf(sfr[i][0], sfr[i][1]), fmaxf(sfr[i][2], sfr[i][3]));
            red[(ty * 4 + i) * 17 + tx] = mx;
        }
        __syncthreads();
        float mnew[4], alpha[4], psum[4];
        #pragma unroll
        for (int i = 0; i < 4; i++) {
            int qr = ty * 4 + i;
            float mt = red[qr * 17];
            #pragma unroll
            for (int t = 1; t < 16; t++) mt = fmaxf(mt, red[qr * 17 + t]);
            float mo = m_s[qr];
            float mn = fmaxf(mo, mt);
            mnew[i] = mn;
            alpha[i] = __expf(mo - mn);
            float ps = 0.f;
            #pragma unroll
            for (int j = 0; j < 4; j++) {
                float p = __expf(sfr[i][j] - mn);
                ps += p;
                KP[(tx * 4 + j) * 68 + qr] = p;
            }
            psum[i] = ps;
        }
        __syncthreads();
        #pragma unroll
        for (int i = 0; i < 4; i++) red[(ty * 4 + i) * 17 + tx] = psum[i];
        if (tx == 0) {
            #pragma unroll
            for (int i = 0; i < 4; i++) m_s[ty * 4 + i] = mnew[i];
        }
        __syncthreads();
        if (tx == 0) {
            #pragma unroll
            for (int i = 0; i < 4; i++) {
                int qr = ty * 4 + i;
                float s = 0.f;
                #pragma unroll
                for (int t = 0; t < 16; t++) s += red[qr * 17 + t];
                l_s[qr] = l_s[qr] * alpha[i] + s;
            }
        }
        // rescale O (packed) and accumulate P@V (packed)
        #pragma unroll
        for (int i = 0; i < 4; i++) {
            pk2 ap = pk(alpha[i], alpha[i]);
            mul2(o2[i][0], ap);
            mul2(o2[i][1], ap);
        }
        #pragma unroll 8
        for (int kk = 0; kk < 64; kk++) {
            float4 a = *(const float4*)(&KP[kk * 68 + ty * 4]);
            float4 b = *(const float4*)(&Vs[kk * 64 + tx * 4]);
            pk2 b01 = pk(b.x, b.y), b23 = pk(b.z, b.w);
            float av[4] = {a.x, a.y, a.z, a.w};
            #pragma unroll
            for (int i = 0; i < 4; i++) {
                pk2 aa = pk(av[i], av[i]);
                fma2(o2[i][0], aa, b01);
                fma2(o2[i][1], aa, b23);
            }
        }
    }
    __syncthreads();
    float inv[4];
    #pragma unroll
    for (int i = 0; i < 4; i++) inv[i] = 1.0f / l_s[ty * 4 + i];
    #pragma unroll
    for (int i = 0; i < 4; i++) {
        float o[4];
        unpk(o2[i][0], o[0], o[1]);
        unpk(o2[i][1], o[2], o[3]);
        int s_idx = qt0 + ty * 4 + i;
        size_t rb = ((size_t)bb * TB_S + s_idx) * TB_D3;
        int ct = hh * TB_HD + tx * 4;
        __nv_bfloat16 hi[4], lo[4];
        #pragma unroll
        for (int j = 0; j < 4; j++) split_bf16(o[j] * inv[i], hi[j], lo[j]);
        uint2 h2 = pack4bf(hi[0], hi[1], hi[2], hi[3]);
        uint2 l2 = pack4bf(lo[0], lo[1], lo[2], lo[3]);
        *(uint2*)(O3 + rb + ct)              = h2;   // [hi|lo|hi] A-side
        *(uint2*)(O3 + rb + TB_D + ct)       = l2;
        *(uint2*)(O3 + rb + 2 * TB_D + ct)   = h2;
    }
}

// ---------------- launch ------------------------------------------------------
static const int ATTN_SMEM = (64 * 68 * 2 + 64 * 64 + 64 * 17 + 128) * (int)sizeof(float);

extern "C" void kernel_launch(void* const* d_in, const int* in_sizes, int n_in,
                              void* d_out, int out_size) {
    const float* x     = (const float*)d_in[0];
    const float* wq    = (const float*)d_in[1];
    const float* wk    = (const float*)d_in[2];
    const float* wv    = (const float*)d_in[3];
    const float* wo    = (const float*)d_in[4];
    const float* w_in  = (const float*)d_in[5];
    const float* w_out = (const float*)d_in[6];
    float* out = (float*)d_out;
    (void)in_sizes; (void)n_in; (void)out_size;

    __nv_bfloat16 *xn3, *att3, *ff3, *wq3, *wk3, *wv3, *wo3, *win3, *wout3;
    float *q, *k, *v, *h;
    cudaGetSymbolAddress((void**)&xn3,  g_xn3);
    cudaGetSymbolAddress((void**)&att3, g_att3);
    cudaGetSymbolAddress((void**)&ff3,  g_ff3);
    cudaGetSymbolAddress((void**)&q,    g_q);
    cudaGetSymbolAddress((void**)&k,    g_k);
    cudaGetSymbolAddress((void**)&v,    g_v);
    cudaGetSymbolAddress((void**)&h,    g_h);
    cudaGetSymbolAddress((void**)&wq3,  g_wq3);
    cudaGetSymbolAddress((void**)&wk3,  g_wk3);
    cudaGetSymbolAddress((void**)&wv3,  g_wv3);
    cudaGetSymbolAddress((void**)&wo3,  g_wo3);
    cudaGetSymbolAddress((void**)&win3, g_win3);
    cudaGetSymbolAddress((void**)&wout3, g_wout3);

    cudaFuncSetAttribute(attn_kernel, cudaFuncAttributeMaxDynamicSharedMemorySize, ATTN_SMEM);
    cudaFuncSetAttribute(tc_gemm_qkv, cudaFuncAttributeMaxDynamicSharedMemorySize, GEMM_SMEM);
    cudaFuncSetAttribute(tc_gemm<1>,  cudaFuncAttributeMaxDynamicSharedMemorySize, GEMM_SMEM);
    cudaFuncSetAttribute(tc_gemm<2>,  cudaFuncAttributeMaxDynamicSharedMemorySize, GEMM_SMEM);

    dim3 cwb(32, 8);
    // launch order arranged so ncu (-s 5 -c 1) captures launch #6 = O-proj GEMM
    // 1. convert the four DxD weights
    conv_w4_kernel<<<dim3(32, 32, 4), cwb>>>(wq, wk, wv, wo, wq3, wk3, wv3, wo3);
    // 2. convert the two FFN weights (oversized grid, bounds-checked)
    conv_wff_kernel<<<dim3(128, 128, 2), cwb>>>(w_in, w_out, win3, wout3);
    // 3. xn3 = split(srmsnorm(x))
    srmsnorm3_kernel<<<TB_T, 256>>>(x, xn3);
    // 4. q,k,v = xn @ {wq,wk,wv}  (fp32 out)
    tc_gemm_qkv<<<dim3(TB_D / 256, TB_T / 128, 3), 128, GEMM_SMEM>>>(xn3, wq3, wk3, wv3, q, k, v);
    // 5. causal attention -> att3 (segmented split-bf16)
    attn_kernel<<<dim3(TB_S / 64, TB_H, TB_B), 256, ATTN_SMEM>>>(q, k, v, att3);
    // 6. h = x + att @ wo            <-- ncu capture window
    tc_gemm<1><<<dim3(TB_D / 256, TB_T / 128), 128, GEMM_SMEM>>>(att3, wo3, x, h, TB_D, TB_D3);
    // 7. xn3 = split(srmsnorm(h))
    srmsnorm3_kernel<<<TB_T, 256>>>(h, xn3);
    // 8. ff3 = split(gelu(hn @ w_in))
    tc_gemm<2><<<dim3(TB_F / 256, TB_T / 128), 128, GEMM_SMEM>>>(xn3, win3, nullptr, ff3, TB_F, TB_D3);
    // 9. out = h + ff @ w_out
    tc_gemm<1><<<dim3(TB_D / 256, TB_T / 128), 128, GEMM_SMEM>>>(ff3, wout3, h, out, TB_D, TB_F3);
}

// round 7
// speedup vs baseline: 2.7099x; 1.3430x over previous
#include <cuda_runtime.h>
#include <cuda_bf16.h>
#include <math.h>
#include <stdint.h>

// Problem dims (fixed by the reference)
#define TB_B 2
#define TB_S 2048
#define TB_D 1024
#define TB_F 4096
#define TB_H 16
#define TB_HD 64
#define TB_T (TB_B * TB_S)   // 4096 tokens
#define TB_D3 (3 * TB_D)     // 3072 (split-bf16 expanded K)
#define TB_F3 (3 * TB_F)     // 12288

#if defined(__CUDA_ARCH_FEAT_SM103_ALL) || defined(__CUDA_ARCH_FEAT_SM100_ALL)
#define HAS_TCGEN05 1
#else
#define HAS_TCGEN05 0
#endif

// ---------------- scratch ----------------------------------------------------
// Segmented split: A rows = [hi(K) | lo(K) | hi(K)], B rows = [hi(K) | hi(K) | lo(K)]
// sum over 3K = hi.hi + lo.hi + hi.lo = x.w - lo.lo  (~2^-18 rel err)
__device__ __nv_bfloat16 g_xn3 [(size_t)TB_T * TB_D3];
__device__ __nv_bfloat16 g_att3[(size_t)TB_T * TB_D3];
__device__ __nv_bfloat16 g_ff3 [(size_t)TB_T * TB_F3];
__device__ float g_q [(size_t)TB_T * TB_D];
__device__ float g_k [(size_t)TB_T * TB_D];
__device__ float g_v [(size_t)TB_T * TB_D];
__device__ float g_h [(size_t)TB_T * TB_D];
__device__ __nv_bfloat16 g_wq3 [(size_t)TB_D * TB_D3];
__device__ __nv_bfloat16 g_wk3 [(size_t)TB_D * TB_D3];
__device__ __nv_bfloat16 g_wv3 [(size_t)TB_D * TB_D3];
__device__ __nv_bfloat16 g_wo3 [(size_t)TB_D * TB_D3];
__device__ __nv_bfloat16 g_win3[(size_t)TB_F * TB_D3];
__device__ __nv_bfloat16 g_wout3[(size_t)TB_D * TB_F3];

// ---------------- helpers ----------------------------------------------------
__device__ __forceinline__ uint32_t smem_u32(const void* p) {
    uint32_t a;
    asm("{ .reg .u64 t; cvta.to.shared.u64 t, %1; cvt.u32.u64 %0, t; }" : "=r"(a) : "l"(p));
    return a;
}
__device__ __forceinline__ void split_bf16(float x, __nv_bfloat16& hi, __nv_bfloat16& lo) {
    hi = __float2bfloat16(x);
    lo = __float2bfloat16(x - __bfloat162float(hi));
}
__device__ __forceinline__ float gelu_tanh(float v) {
    const float c = 0.79788456080286535588f;
    float t = c * (v + 0.044715f * v * v * v);
    return 0.5f * v * (1.0f + tanhf(t));
}
__device__ __forceinline__ uint2 pack4bf(__nv_bfloat16 a, __nv_bfloat16 b,
                                         __nv_bfloat16 c, __nv_bfloat16 d) {
    uint2 r;
    r.x = (uint32_t)__bfloat16_as_ushort(a) | ((uint32_t)__bfloat16_as_ushort(b) << 16);
    r.y = (uint32_t)__bfloat16_as_ushort(c) | ((uint32_t)__bfloat16_as_ushort(d) << 16);
    return r;
}

// ---- packed f32x2 math ------------------------------------------------------
#if HAS_TCGEN05
typedef uint64_t pk2;
__device__ __forceinline__ pk2 pkzero() { return 0ull; }
__device__ __forceinline__ pk2 pk(float x, float y) {
    pk2 r; asm("mov.b64 %0, {%1, %2};" : "=l"(r) : "f"(x), "f"(y)); return r;
}
__device__ __forceinline__ void fma2(pk2& d, pk2 a, pk2 b) {
    asm("fma.rn.f32x2 %0, %1, %2, %0;" : "+l"(d) : "l"(a), "l"(b));
}
__device__ __forceinline__ void mul2(pk2& d, pk2 a) {
    asm("mul.rn.f32x2 %0, %0, %1;" : "+l"(d) : "l"(a));
}
__device__ __forceinline__ void unpk(pk2 v, float& x, float& y) {
    asm("mov.b64 {%0, %1}, %2;" : "=f"(x), "=f"(y) : "l"(v));
}
#else
typedef float2 pk2;
__device__ __forceinline__ pk2 pkzero() { return make_float2(0.f, 0.f); }
__device__ __forceinline__ pk2 pk(float x, float y) { return make_float2(x, y); }
__device__ __forceinline__ void fma2(pk2& d, pk2 a, pk2 b) {
    d.x = fmaf(a.x, b.x, d.x); d.y = fmaf(a.y, b.y, d.y);
}
__device__ __forceinline__ void mul2(pk2& d, pk2 a) { d.x *= a.x; d.y *= a.y; }
__device__ __forceinline__ void unpk(pk2 v, float& x, float& y) { x = v.x; y = v.y; }
#endif

#if HAS_TCGEN05
__device__ __forceinline__ uint32_t elect_one() {
    uint32_t p;
    asm volatile("{ .reg .pred p; elect.sync _|p, 0xFFFFFFFF; selp.b32 %0, 1, 0, p; }" : "=r"(p));
    return p;
}
__device__ __forceinline__ void mbar_init(uint32_t a, uint32_t cnt) {
    asm volatile("mbarrier.init.shared.b64 [%0], %1;" :: "r"(a), "r"(cnt) : "memory");
}
__device__ __forceinline__ void mbar_wait(uint32_t a, uint32_t parity) {
    asm volatile(
        "{\n\t.reg .pred P;\n\t"
        "LW%=:\n\t"
        "mbarrier.try_wait.parity.acquire.cta.shared::cta.b64 P, [%0], %1, 0x989680;\n\t"
        "@P bra LD%=;\n\t"
        "bra LW%=;\n\t"
        "LD%=:\n\t}"
        :: "r"(a), "r"(parity) : "memory");
}
__device__ __forceinline__ void cp_async16(uint32_t dst, const void* src) {
    asm volatile("cp.async.cg.shared.global [%0], [%1], 16;" :: "r"(dst), "l"(src) : "memory");
}
__device__ __forceinline__ void cp_async_arrive(uint32_t mbar) {
    asm volatile("cp.async.mbarrier.arrive.noinc.shared::cta.b64 [%0];" :: "r"(mbar) : "memory");
}
__device__ __forceinline__ void mma_f16_ss(uint32_t d, uint64_t ad, uint64_t bd,
                                           uint32_t idesc, uint32_t en) {
    asm volatile(
        "{\n\t.reg .pred p;\n\tsetp.ne.u32 p, %4, 0;\n\t"
        "tcgen05.mma.cta_group::1.kind::f16 [%0], %1, %2, %3, {%5, %5, %5, %5}, p;\n\t}"
        :: "r"(d), "l"(ad), "l"(bd), "r"(idesc), "r"(en), "r"(0u) : "memory");
}
#define TCGEN05_LD_32X32B_X32(r, tmem_addr) \
    asm volatile( \
        "tcgen05.ld.sync.aligned.32x32b.x32.b32 " \
        "{%0, %1, %2, %3, %4, %5, %6, %7, " \
        " %8, %9, %10, %11, %12, %13, %14, %15, " \
        " %16, %17, %18, %19, %20, %21, %22, %23, " \
        " %24, %25, %26, %27, %28, %29, %30, %31}, [%32];" \
        : "=r"((r)[0]),  "=r"((r)[1]),  "=r"((r)[2]),  "=r"((r)[3]), \
          "=r"((r)[4]),  "=r"((r)[5]),  "=r"((r)[6]),  "=r"((r)[7]), \
          "=r"((r)[8]),  "=r"((r)[9]),  "=r"((r)[10]), "=r"((r)[11]), \
          "=r"((r)[12]), "=r"((r)[13]), "=r"((r)[14]), "=r"((r)[15]), \
          "=r"((r)[16]), "=r"((r)[17]), "=r"((r)[18]), "=r"((r)[19]), \
          "=r"((r)[20]), "=r"((r)[21]), "=r"((r)[22]), "=r"((r)[23]), \
          "=r"((r)[24]), "=r"((r)[25]), "=r"((r)[26]), "=r"((r)[27]), \
          "=r"((r)[28]), "=r"((r)[29]), "=r"((r)[30]), "=r"((r)[31]) \
        : "r"(tmem_addr))
#endif // HAS_TCGEN05

#define SWZ(o) ((o) ^ (((o) >> 3) & 0x70))
#define SMEM_DESC_BASE ((uint64_t(2) << 61) | (uint64_t(1) << 46) | (uint64_t(64) << 32) | (uint64_t(1) << 16))
#define MK_DESC(addr) (SMEM_DESC_BASE | ((uint64_t)((addr) >> 4) & 0x3FFF))
// idesc: F32 accum, A=BF16, B=BF16, N=128, M=128
#define MMA_IDESC 0x8200490u

// ---------------- weight convert+transpose: W[K][N] -> o[N][3K] [hi|hi|lo] ---
__device__ __forceinline__ void conv_w_body(const float* __restrict__ W,
                                            __nv_bfloat16* __restrict__ o, int K, int N) {
    __shared__ float t[32][33];
    int n0 = blockIdx.x * 32, k0 = blockIdx.y * 32;
    if (n0 >= N || k0 >= K) return;
    int tx = threadIdx.x, ty = threadIdx.y; // 32 x 8
    #pragma unroll
    for (int i = 0; i < 4; i++)
        t[ty + 8 * i][tx] = W[(size_t)(k0 + ty + 8 * i) * N + n0 + tx];
    __syncthreads();
    size_t K3 = 3 * (size_t)K;
    #pragma unroll
    for (int i = 0; i < 4; i++) {
        int nn = ty + 8 * i, kk = tx;
        float x = t[kk][nn];
        __nv_bfloat16 hi, lo; split_bf16(x, hi, lo);
        size_t base = (size_t)(n0 + nn) * K3 + (size_t)(k0 + kk);
        o[base] = hi; o[base + K] = hi; o[base + 2 * K] = lo;
    }
}
__global__ void conv_w4_kernel(const float* __restrict__ w0, const float* __restrict__ w1,
                               const float* __restrict__ w2, const float* __restrict__ w3,
                               __nv_bfloat16* o0, __nv_bfloat16* o1,
                               __nv_bfloat16* o2, __nv_bfloat16* o3) {
    const float* W = (blockIdx.z == 0) ? w0 : (blockIdx.z == 1) ? w1 : (blockIdx.z == 2) ? w2 : w3;
    __nv_bfloat16* O = (blockIdx.z == 0) ? o0 : (blockIdx.z == 1) ? o1 : (blockIdx.z == 2) ? o2 : o3;
    conv_w_body(W, O, TB_D, TB_D);
}
__global__ void conv_wff_kernel(const float* __restrict__ w_in, const float* __restrict__ w_out,
                                __nv_bfloat16* win3, __nv_bfloat16* wout3) {
    if (blockIdx.z == 0) conv_w_body(w_in,  win3,  TB_D, TB_F);
    else                 conv_w_body(w_out, wout3, TB_F, TB_D);
}

// ---------------- srmsnorm -> split-bf16 segmented [hi|lo|hi] ----------------
__global__ void srmsnorm3_kernel(const float* __restrict__ x, __nv_bfloat16* __restrict__ y) {
    int row = blockIdx.x;
    int tid = threadIdx.x;
    const float* xr = x + (size_t)row * TB_D;
    float4 v = *(const float4*)(xr + tid * 4);
    float ss = v.x*v.x + v.y*v.y + v.z*v.z + v.w*v.w;
    #pragma unroll
    for (int o = 16; o; o >>= 1) ss += __shfl_xor_sync(0xffffffffu, ss, o);
    __shared__ float wred[8];
    __shared__ float s_scale;
    if ((tid & 31) == 0) wred[tid >> 5] = ss;
    __syncthreads();
    if (tid == 0) {
        float tot = 0.f;
        #pragma unroll
        for (int i = 0; i < 8; i++) tot += wred[i];
        s_scale = 32.0f / fmaxf(sqrtf(tot), 1e-12f);
    }
    __syncthreads();
    float sc = s_scale;
    float vals[4] = {v.x * sc, v.y * sc, v.z * sc, v.w * sc};
    __nv_bfloat16 hi[4], lo[4];
    #pragma unroll
    for (int j = 0; j < 4; j++) split_bf16(vals[j], hi[j], lo[j]);
    uint2 h2 = pack4bf(hi[0], hi[1], hi[2], hi[3]);
    uint2 l2 = pack4bf(lo[0], lo[1], lo[2], lo[3]);
    size_t base = (size_t)row * TB_D3 + tid * 4;
    *(uint2*)(y + base)              = h2;
    *(uint2*)(y + base + TB_D)       = l2;
    *(uint2*)(y + base + 2 * TB_D)   = h2;
}

// ---------------- tcgen05 split-bf16 GEMM, warp-specialized ------------------
// 256 threads: warps 0-3 = loaders, warp 7 = MMA issuer, all 8 warps epilogue.
// Drain discipline: ONLY the producer warps (correct per-thread phase history)
// wait the final empty phases; __syncthreads() releases the rest. A bare
// parity wait from a thread that skipped earlier phases is UB (1-bit phase).
#define GNST 4
#define STAGE_A 16384
#define STAGE_BYTES 49152
#define GEMM_SMEM (GNST * STAGE_BYTES + 1024)

template<int EPI>
__device__ __forceinline__ void tc_gemm_body(
    const __nv_bfloat16* __restrict__ A3, const __nv_bfloat16* __restrict__ B3,
    const float* __restrict__ res, void* __restrict__ Cout,
    int N, int K3, int m0, int n0)
{
#if HAS_TCGEN05
    extern __shared__ char dsm_raw[];
    __shared__ uint32_t s_tmem;
    __shared__ __align__(8) uint64_t s_bars[2 * GNST]; // full[4], empty[4]
    uint32_t dsm = (smem_u32(dsm_raw) + 1023) & ~1023u;
    int tid = threadIdx.x, wid = tid >> 5, lane = tid & 31;

    if (wid == 0) {
        asm volatile("tcgen05.alloc.cta_group::1.sync.aligned.shared::cta.b32 [%0], %1;"
                     :: "r"(smem_u32((void*)&s_tmem)), "r"(256u) : "memory");
    }
    if (tid == 0) {
        #pragma unroll
        for (int s = 0; s < GNST; s++) {
            mbar_init(smem_u32(&s_bars[s]), 128);        // full: 128 loader arrivals
            mbar_init(smem_u32(&s_bars[GNST + s]), 1);   // empty: 1 tcgen05.commit
        }
    }
    __syncthreads();
    uint32_t tmem = s_tmem;

    const __nv_bfloat16* Ab = A3 + (size_t)m0 * K3;
    const __nv_bfloat16* Bb = B3 + (size_t)n0 * K3;
    int nch = K3 >> 6;   // 64 bf16 per chunk (128B SW128 row); multiple of 4

    if (wid < 4) {
        // ---------------- producer: pure load pipeline, depth 4 --------------
        for (int c = 0; c < nch; c++) {
            int s = c & 3;
            uint32_t sA = dsm + s * STAGE_BYTES;
            uint32_t sB = sA + STAGE_A;
            if (c >= GNST)
                mbar_wait(smem_u32(&s_bars[GNST + s]), ((c >> 2) - 1) & 1);
            const __nv_bfloat16* ga = Ab + ((size_t)c << 6);
            const __nv_bfloat16* gb = Bb + ((size_t)c << 6);
            #pragma unroll
            for (int i = 0; i < 8; i++) {          // A: 128 rows x 128B
                int u = tid + (i << 7);
                int r = u >> 3, q = u & 7;
                cp_async16(sA + SWZ(r * 128 + q * 16), ga + (size_t)r * K3 + q * 8);
            }
            #pragma unroll
            for (int i = 0; i < 16; i++) {         // B: 256 rows x 128B
                int u = tid + (i << 7);
                int r = u >> 3, q = u & 7;
                cp_async16(sB + SWZ(r * 128 + q * 16), gb + (size_t)r * K3 + q * 8);
            }
            cp_async_arrive(smem_u32(&s_bars[s]));
        }
        // drain by producers ONLY: their wait sequence consumed phases
        // 0..(nphase-2) in-loop, so the final-parity wait truly means the
        // last phase (= last 4 chunks' MMA commits -> ALL MMAs complete).
        uint32_t pe = ((uint32_t)(nch >> 2) - 1u) & 1u;
        #pragma unroll
        for (int s = 0; s < GNST; s++)
            mbar_wait(smem_u32(&s_bars[GNST + s]), pe);
    } else if (wid == 7) {
        // ---------------- consumer: dedicated MMA warp ------------------------
        for (int c = 0; c < nch; c++) {
            int s = c & 3;
            uint32_t sA = dsm + s * STAGE_BYTES;
            uint32_t sB = sA + STAGE_A;
            mbar_wait(smem_u32(&s_bars[s]), (c >> 2) & 1);
            if (elect_one()) {
                uint64_t ad  = MK_DESC(sA);
                uint64_t bd0 = MK_DESC(sB);
                uint64_t bd1 = MK_DESC(sB + 16384);   // B rows 128..255
                #pragma unroll
                for (int k = 0; k < 4; k++) {
                    uint32_t en = (c | k) ? 1u : 0u;
                    mma_f16_ss(tmem,       ad + 2*k, bd0 + 2*k, MMA_IDESC, en);
                    mma_f16_ss(tmem + 128, ad + 2*k, bd1 + 2*k, MMA_IDESC, en);
                }
                asm volatile(
                    "tcgen05.commit.cta_group::1.mbarrier::arrive::one.shared::cluster.b64 [%0];"
                    :: "r"(smem_u32(&s_bars[GNST + s])) : "memory");
            }
        }
    }
    // release all warps only after producers verified full MMA completion
    __syncthreads();
    asm volatile("tcgen05.fence::after_thread_sync;" ::: "memory");

    // epilogue: 8 warps; warp w -> rows (w&3)*32 (its TMEM subpartition),
    // column half (w>>2)*128. 4 x 32-col blocks per warp.
    int sub = wid & 3, half = wid >> 2;
    int mrow = m0 + sub * 32 + lane;
    for (int cb = 0; cb < 128; cb += 32) {
        uint32_t dr[32];
        TCGEN05_LD_32X32B_X32(dr, tmem + half * 128 + cb);
        asm volatile("tcgen05.wait::ld.sync.aligned;" ::: "memory");
        int n = n0 + half * 128 + cb;
        if (EPI == 2) {
            __nv_bfloat16* C = (__nv_bfloat16*)Cout;
            size_t rb = (size_t)mrow * (3 * (size_t)N);
            __nv_bfloat16 hiA[32], loA[32];
            #pragma unroll
            for (int j = 0; j < 32; j++) {
                float f = gelu_tanh(__uint_as_float(dr[j]));
                split_bf16(f, hiA[j], loA[j]);
            }
            uint4* ph  = (uint4*)(C + rb + n);
            uint4* pl  = (uint4*)(C + rb + (size_t)N + n);
            uint4* ph2 = (uint4*)(C + rb + 2 * (size_t)N + n);
            #pragma unroll
            for (int t2 = 0; t2 < 4; t2++) {
                uint4 vh = ((uint4*)hiA)[t2];
                ph[t2] = vh; ph2[t2] = vh;
                pl[t2] = ((uint4*)loA)[t2];
            }
        } else {
            float* C = (float*)Cout;
            size_t base = (size_t)mrow * N + n;
            #pragma unroll
            for (int j = 0; j < 32; j += 4) {
                float4 v = make_float4(__uint_as_float(dr[j]),   __uint_as_float(dr[j+1]),
                                       __uint_as_float(dr[j+2]), __uint_as_float(dr[j+3]));
                if (EPI == 1) {
                    float4 r4 = *(const float4*)(res + base + j);
                    v.x += r4.x; v.y += r4.y; v.z += r4.z; v.w += r4.w;
                }
                *(float4*)(C + base + j) = v;
            }
        }
    }
    __syncthreads();
    if (wid == 0) {
        asm volatile("tcgen05.relinquish_alloc_permit.cta_group::1.sync.aligned;");
        asm volatile("tcgen05.dealloc.cta_group::1.sync.aligned.b32 %0, %1;"
                     :: "r"(tmem), "r"(256u));
    }
#else
    // ---------------- SIMT fallback (non-sm_103a cubin only) -----------------
    extern __shared__ char dsm_raw[];
    __nv_bfloat16* As = (__nv_bfloat16*)dsm_raw;
    const int CH = 2048;
    int tid = threadIdx.x;
    int n_c = n0 + tid;             // 256 threads -> 1 col each
    for (int m = 0; m < 128; m++) {
        const __nv_bfloat16* arow = A3 + (size_t)(m0 + m) * K3;
        float acc = 0.f;
        for (int c0 = 0; c0 < K3; c0 += CH) {
            int len = min(CH, K3 - c0);
            for (int i = tid; i < len / 8; i += 256)
                ((float4*)As)[i] = ((const float4*)(arow + c0))[i];
            __syncthreads();
            const __nv_bfloat16* b0 = B3 + (size_t)n_c * K3 + c0;
            for (int k = 0; k < len; k++)
                acc = fmaf(__bfloat162float(As[k]), __bfloat162float(b0[k]), acc);
            __syncthreads();
        }
        int mrow = m0 + m;
        if (EPI == 2) {
            __nv_bfloat16* C = (__nv_bfloat16*)Cout;
            size_t base = (size_t)mrow * (3 * (size_t)N);
            float f = gelu_tanh(acc);
            __nv_bfloat16 hi, lo; split_bf16(f, hi, lo);
            C[base + n_c] = hi; C[base + N + n_c] = lo; C[base + 2 * N + n_c] = hi;
        } else {
            float* C = (float*)Cout;
            size_t base = (size_t)mrow * N;
            if (EPI == 1) acc += res[base + n_c];
            C[base + n_c] = acc;
        }
    }
#endif
}

template<int EPI>
__global__ __launch_bounds__(256, 1) void tc_gemm(
    const __nv_bfloat16* __restrict__ A3, const __nv_bfloat16* __restrict__ B3,
    const float* __restrict__ res, void* __restrict__ C, int N, int K3)
{
    tc_gemm_body<EPI>(A3, B3, res, C, N, K3, blockIdx.y * 128, blockIdx.x * 256);
}

__global__ __launch_bounds__(256, 1) void tc_gemm_qkv(
    const __nv_bfloat16* __restrict__ A3,
    const __nv_bfloat16* __restrict__ b0, const __nv_bfloat16* __restrict__ b1,
    const __nv_bfloat16* __restrict__ b2,
    float* __restrict__ c0, float* __restrict__ c1, float* __restrict__ c2)
{
    const __nv_bfloat16* B3 = (blockIdx.z == 0) ? b0 : ((blockIdx.z == 1) ? b1 : b2);
    float* C = (blockIdx.z == 0) ? c0 : ((blockIdx.z == 1) ? c1 : c2);
    tc_gemm_body<0>(A3, B3, nullptr, C, TB_D, TB_D3, blockIdx.y * 128, blockIdx.x * 256);
}

// ---------------- causal flash attention, fp32+f32x2, 64x64 tiles ------------
__global__ __launch_bounds__(256) void attn_kernel(
    const float* __restrict__ Q, const float* __restrict__ Km,
    const float* __restrict__ Vm, __nv_bfloat16* __restrict__ O3)
{
    extern __shared__ float sm[];
    float* Qt  = sm;              // [64][68] Qt[d][q]
    float* KP  = Qt + 64 * 68;    // [64][68] Kt[d][k], later Pt[k][q]
    float* Vs  = KP + 64 * 68;    // [64][64]
    float* red = Vs + 64 * 64;    // [64][17]
    float* m_s = red + 64 * 17;
    float* l_s = m_s + 64;

    int tid = threadIdx.x;
    int tx = tid & 15, ty = tid >> 4;
    int qt0 = blockIdx.x * 64;
    int hh = blockIdx.y, bb = blockIdx.z;
    size_t base = ((size_t)bb * TB_S) * TB_D + (size_t)hh * TB_HD;
    const float* Qb = Q + base;
    const float* Kb = Km + base;
    const float* Vb = Vm + base;

    for (int i = tid; i < 1024; i += 256) {
        int r = i >> 4, c4 = (i & 15) << 2;
        float4 q4 = *(const float4*)(Qb + (size_t)(qt0 + r) * TB_D + c4);
        Qt[(c4 + 0) * 68 + r] = q4.x; Qt[(c4 + 1) * 68 + r] = q4.y;
        Qt[(c4 + 2) * 68 + r] = q4.z; Qt[(c4 + 3) * 68 + r] = q4.w;
    }
    if (tid < 64) { m_s[tid] = -1e30f; l_s[tid] = 0.f; }

    pk2 o2[4][2];
    #pragma unroll
    for (int i = 0; i < 4; i++) { o2[i][0] = pkzero(); o2[i][1] = pkzero(); }

    int ntiles = blockIdx.x + 1;
    for (int kt = 0; kt < ntiles; kt++) {
        int k0 = kt * 64;
        __syncthreads();
        for (int i = tid; i < 1024; i += 256) {
            int r = i >> 4, c4 = (i & 15) << 2;
            float4 k4 = *(const float4*)(Kb + (size_t)(k0 + r) * TB_D + c4);
            KP[(c4 + 0) * 68 + r] = k4.x; KP[(c4 + 1) * 68 + r] = k4.y;
            KP[(c4 + 2) * 68 + r] = k4.z; KP[(c4 + 3) * 68 + r] = k4.w;
            float4 v4 = *(const float4*)(Vb + (size_t)(k0 + r) * TB_D + c4);
            *(float4*)(&Vs[r * 64 + c4]) = v4;
        }
        __syncthreads();

        pk2 acc2[4][2];
        #pragma unroll
        for (int i = 0; i < 4; i++) { acc2[i][0] = pkzero(); acc2[i][1] = pkzero(); }
        #pragma unroll 8
        for (int d = 0; d < 64; d++) {
            float4 a = *(const float4*)(&Qt[d * 68 + ty * 4]);
            float4 b = *(const float4*)(&KP[d * 68 + tx * 4]);
            pk2 b01 = pk(b.x, b.y), b23 = pk(b.z, b.w);
            float av[4] = {a.x, a.y, a.z, a.w};
            #pragma unroll
            for (int i = 0; i < 4; i++) {
                pk2 aa = pk(av[i], av[i]);
                fma2(acc2[i][0], aa, b01);
                fma2(acc2[i][1], aa, b23);
            }
        }
        float sfr[4][4];
        #pragma unroll
        for (int i = 0; i < 4; i++) {
            unpk(acc2[i][0], sfr[i][0], sfr[i][1]);
            unpk(acc2[i][1], sfr[i][2], sfr[i][3]);
        }
        #pragma unroll
        for (int i = 0; i < 4; i++) {
            int qg = qt0 + ty * 4 + i;
            #pragma unroll
            for (int j = 0; j < 4; j++) {
                sfr[i][j] *= 0.125f;
                int kg = k0 + tx * 4 + j;
                if (kg > qg) sfr[i][j] = -1e30f;
            }
        }
        #pragma unroll
        for (int i = 0; i < 4; i++) {
            float mx = fmaxf(fmaxf(sfr[i][0], sfr[i][1]), fmaxf(sfr[i][2], sfr[i][3]));
            red[(ty * 4 + i) * 17 + tx] = mx;
        }
        __syncthreads();
        float mnew[4], alpha[4], psum[4];
        #pragma unroll
        for (int i = 0; i < 4; i++) {
            int qr = ty * 4 + i;
            float mt = red[qr * 17];
            #pragma unroll
            for (int t = 1; t < 16; t++) mt = fmaxf(mt, red[qr * 17 + t]);
            float mo = m_s[qr];
            float mn = fmaxf(mo, mt);
            mnew[i] = mn;
            alpha[i] = __expf(mo - mn);
            float ps = 0.f;
            #pragma unroll
            for (int j = 0; j < 4; j++) {
                float p = __expf(sfr[i][j] - mn);
                ps += p;
                KP[(tx * 4 + j) * 68 + qr] = p;
            }
            psum[i] = ps;
        }
        __syncthreads();
        #pragma unroll
        for (int i = 0; i < 4; i++) red[(ty * 4 + i) * 17 + tx] = psum[i];
        if (tx == 0) {
            #pragma unroll
            for (int i = 0; i < 4; i++) m_s[ty * 4 + i] = mnew[i];
        }
        __syncthreads();
        if (tx == 0) {
            #pragma unroll
            for (int i = 0; i < 4; i++) {
                int qr = ty * 4 + i;
                float s = 0.f;
                #pragma unroll
                for (int t = 0; t < 16; t++) s += red[qr * 17 + t];
                l_s[qr] = l_s[qr] * alpha[i] + s;
            }
        }
        #pragma unroll
        for (int i = 0; i < 4; i++) {
            pk2 ap = pk(alpha[i], alpha[i]);
            mul2(o2[i][0], ap);
            mul2(o2[i][1], ap);
        }
        #pragma unroll 8
        for (int kk = 0; kk < 64; kk++) {
            float4 a = *(const float4*)(&KP[kk * 68 + ty * 4]);
            float4 b = *(const float4*)(&Vs[kk * 64 + tx * 4]);
            pk2 b01 = pk(b.x, b.y), b23 = pk(b.z, b.w);
            float av[4] = {a.x, a.y, a.z, a.w};
            #pragma unroll
            for (int i = 0; i < 4; i++) {
                pk2 aa = pk(av[i], av[i]);
                fma2(o2[i][0], aa, b01);
                fma2(o2[i][1], aa, b23);
            }
        }
    }
    __syncthreads();
    float inv[4];
    #pragma unroll
    for (int i = 0; i < 4; i++) inv[i] = 1.0f / l_s[ty * 4 + i];
    #pragma unroll
    for (int i = 0; i < 4; i++) {
        float o[4];
        unpk(o2[i][0], o[0], o[1]);
        unpk(o2[i][1], o[2], o[3]);
        int s_idx = qt0 + ty * 4 + i;
        size_t rb = ((size_t)bb * TB_S + s_idx) * TB_D3;
        int ct = hh * TB_HD + tx * 4;
        __nv_bfloat16 hi[4], lo[4];
        #pragma unroll
        for (int j = 0; j < 4; j++) split_bf16(o[j] * inv[i], hi[j], lo[j]);
        uint2 h2 = pack4bf(hi[0], hi[1], hi[2], hi[3]);
        uint2 l2 = pack4bf(lo[0], lo[1], lo[2], lo[3]);
        *(uint2*)(O3 + rb + ct)              = h2;
        *(uint2*)(O3 + rb + TB_D + ct)       = l2;
        *(uint2*)(O3 + rb + 2 * TB_D + ct)   = h2;
    }
}

// ---------------- launch ------------------------------------------------------
static const int ATTN_SMEM = (64 * 68 * 2 + 64 * 64 + 64 * 17 + 128) * (int)sizeof(float);

extern "C" void kernel_launch(void* const* d_in, const int* in_sizes, int n_in,
                              void* d_out, int out_size) {
    const float* x     = (const float*)d_in[0];
    const float* wq    = (const float*)d_in[1];
    const float* wk    = (const float*)d_in[2];
    const float* wv    = (const float*)d_in[3];
    const float* wo    = (const float*)d_in[4];
    const float* w_in  = (const float*)d_in[5];
    const float* w_out = (const float*)d_in[6];
    float* out = (float*)d_out;
    (void)in_sizes; (void)n_in; (void)out_size;

    __nv_bfloat16 *xn3, *att3, *ff3, *wq3, *wk3, *wv3, *wo3, *win3, *wout3;
    float *q, *k, *v, *h;
    cudaGetSymbolAddress((void**)&xn3,  g_xn3);
    cudaGetSymbolAddress((void**)&att3, g_att3);
    cudaGetSymbolAddress((void**)&ff3,  g_ff3);
    cudaGetSymbolAddress((void**)&q,    g_q);
    cudaGetSymbolAddress((void**)&k,    g_k);
    cudaGetSymbolAddress((void**)&v,    g_v);
    cudaGetSymbolAddress((void**)&h,    g_h);
    cudaGetSymbolAddress((void**)&wq3,  g_wq3);
    cudaGetSymbolAddress((void**)&wk3,  g_wk3);
    cudaGetSymbolAddress((void**)&wv3,  g_wv3);
    cudaGetSymbolAddress((void**)&wo3,  g_wo3);
    cudaGetSymbolAddress((void**)&win3, g_win3);
    cudaGetSymbolAddress((void**)&wout3, g_wout3);

    cudaFuncSetAttribute(attn_kernel, cudaFuncAttributeMaxDynamicSharedMemorySize, ATTN_SMEM);
    cudaFuncSetAttribute(tc_gemm_qkv, cudaFuncAttributeMaxDynamicSharedMemorySize, GEMM_SMEM);
    cudaFuncSetAttribute(tc_gemm<1>,  cudaFuncAttributeMaxDynamicSharedMemorySize, GEMM_SMEM);
    cudaFuncSetAttribute(tc_gemm<2>,  cudaFuncAttributeMaxDynamicSharedMemorySize, GEMM_SMEM);

    dim3 cwb(32, 8);
    // launch order keeps launch #6 = O-proj GEMM (ncu -s 5 -c 1 window)
    conv_w4_kernel<<<dim3(32, 32, 4), cwb>>>(wq, wk, wv, wo, wq3, wk3, wv3, wo3);
    conv_wff_kernel<<<dim3(128, 128, 2), cwb>>>(w_in, w_out, win3, wout3);
    srmsnorm3_kernel<<<TB_T, 256>>>(x, xn3);
    tc_gemm_qkv<<<dim3(TB_D / 256, TB_T / 128, 3), 256, GEMM_SMEM>>>(xn3, wq3, wk3, wv3, q, k, v);
    attn_kernel<<<dim3(TB_S / 64, TB_H, TB_B), 256, ATTN_SMEM>>>(q, k, v, att3);
    // #6: h = x + att @ wo            <-- ncu capture window
    tc_gemm<1><<<dim3(TB_D / 256, TB_T / 128), 256, GEMM_SMEM>>>(att3, wo3, x, h, TB_D, TB_D3);
    srmsnorm3_kernel<<<TB_T, 256>>>(h, xn3);
    tc_gemm<2><<<dim3(TB_F / 256, TB_T / 128), 256, GEMM_SMEM>>>(xn3, win3, nullptr, ff3, TB_F, TB_D3);
    tc_gemm<1><<<dim3(TB_D / 256, TB_T / 128), 256, GEMM_SMEM>>>(ff3, wout3, h, out, TB_D, TB_F3);
}

// round 11
// speedup vs baseline: 4.8361x; 1.7846x over previous
#include <cuda_runtime.h>
#include <cuda_bf16.h>
#include <math.h>
#include <stdint.h>

// Problem dims (fixed by the reference)
#define TB_B 2
#define TB_S 2048
#define TB_D 1024
#define TB_F 4096
#define TB_H 16
#define TB_HD 64
#define TB_T (TB_B * TB_S)   // 4096 tokens
#define TB_D3 (3 * TB_D)     // 3072 (split-bf16 expanded K)
#define TB_F3 (3 * TB_F)     // 12288

#if defined(__CUDA_ARCH_FEAT_SM103_ALL) || defined(__CUDA_ARCH_FEAT_SM100_ALL)
#define HAS_TCGEN05 1
#else
#define HAS_TCGEN05 0
#endif

// ---------------- scratch ----------------------------------------------------
// GEMM segmented split: A rows [hi(K)|lo(K)|hi(K)], B rows [hi(K)|hi(K)|lo(K)]
__device__ __nv_bfloat16 g_xn3 [(size_t)TB_T * TB_D3];
__device__ __nv_bfloat16 g_att3[(size_t)TB_T * TB_D3];
__device__ __nv_bfloat16 g_ff3 [(size_t)TB_T * TB_F3];
__device__ float g_h [(size_t)TB_T * TB_D];
// attention operands (per (b,h)):
//   q3,k3: [b][h][t][128] = [hi(64)|lo(64)] over head dims (K-major rows)
//   vt3:   [b][h][128 d-rows][2048 tokens]; d-rows 0..63 = hi, 64..127 = lo
//          (V TRANSPOSED -> PV is a plain K-major MMA, no TransB)
__device__ __nv_bfloat16 g_q3 [(size_t)TB_T * TB_H * 128];
__device__ __nv_bfloat16 g_k3 [(size_t)TB_T * TB_H * 128];
__device__ __nv_bfloat16 g_vt3[(size_t)TB_B * TB_H * 128 * TB_S];
__device__ __nv_bfloat16 g_wq3 [(size_t)TB_D * TB_D3];
__device__ __nv_bfloat16 g_wk3 [(size_t)TB_D * TB_D3];
__device__ __nv_bfloat16 g_wv3 [(size_t)TB_D * TB_D3];
__device__ __nv_bfloat16 g_wo3 [(size_t)TB_D * TB_D3];
__device__ __nv_bfloat16 g_win3[(size_t)TB_F * TB_D3];
__device__ __nv_bfloat16 g_wout3[(size_t)TB_D * TB_F3];

// ---------------- helpers ----------------------------------------------------
__device__ __forceinline__ uint32_t smem_u32(const void* p) {
    uint32_t a;
    asm("{ .reg .u64 t; cvta.to.shared.u64 t, %1; cvt.u32.u64 %0, t; }" : "=r"(a) : "l"(p));
    return a;
}
__device__ __forceinline__ void split_bf16(float x, __nv_bfloat16& hi, __nv_bfloat16& lo) {
    hi = __float2bfloat16(x);
    lo = __float2bfloat16(x - __bfloat162float(hi));
}
__device__ __forceinline__ float gelu_tanh(float v) {
    const float c = 0.79788456080286535588f;
    float t = c * (v + 0.044715f * v * v * v);
    return 0.5f * v * (1.0f + tanhf(t));
}
__device__ __forceinline__ uint2 pack4bf(__nv_bfloat16 a, __nv_bfloat16 b,
                                         __nv_bfloat16 c, __nv_bfloat16 d) {
    uint2 r;
    r.x = (uint32_t)__bfloat16_as_ushort(a) | ((uint32_t)__bfloat16_as_ushort(b) << 16);
    r.y = (uint32_t)__bfloat16_as_ushort(c) | ((uint32_t)__bfloat16_as_ushort(d) << 16);
    return r;
}

#if HAS_TCGEN05
__device__ __forceinline__ uint32_t elect_one() {
    uint32_t p;
    asm volatile("{ .reg .pred p; elect.sync _|p, 0xFFFFFFFF; selp.b32 %0, 1, 0, p; }" : "=r"(p));
    return p;
}
__device__ __forceinline__ void mbar_init(uint32_t a, uint32_t cnt) {
    asm volatile("mbarrier.init.shared.b64 [%0], %1;" :: "r"(a), "r"(cnt) : "memory");
}
__device__ __forceinline__ void mbar_arrive(uint32_t a) {
    asm volatile("mbarrier.arrive.shared.b64 _, [%0];" :: "r"(a) : "memory");
}
__device__ __forceinline__ void mbar_wait(uint32_t a, uint32_t parity) {
    asm volatile(
        "{\n\t.reg .pred P;\n\t"
        "LW%=:\n\t"
        "mbarrier.try_wait.parity.acquire.cta.shared::cta.b64 P, [%0], %1, 0x989680;\n\t"
        "@P bra LD%=;\n\t"
        "bra LW%=;\n\t"
        "LD%=:\n\t}"
        :: "r"(a), "r"(parity) : "memory");
}
__device__ __forceinline__ void cp_async16(uint32_t dst, const void* src) {
    asm volatile("cp.async.cg.shared.global [%0], [%1], 16;" :: "r"(dst), "l"(src) : "memory");
}
__device__ __forceinline__ void cp_async_arrive(uint32_t mbar) {
    asm volatile("cp.async.mbarrier.arrive.noinc.shared::cta.b64 [%0];" :: "r"(mbar) : "memory");
}
__device__ __forceinline__ void mma_f16_ss(uint32_t d, uint64_t ad, uint64_t bd,
                                           uint32_t idesc, uint32_t en) {
    asm volatile(
        "{\n\t.reg .pred p;\n\tsetp.ne.u32 p, %4, 0;\n\t"
        "tcgen05.mma.cta_group::1.kind::f16 [%0], %1, %2, %3, {%5, %5, %5, %5}, p;\n\t}"
        :: "r"(d), "l"(ad), "l"(bd), "r"(idesc), "r"(en), "r"(0u) : "memory");
}
__device__ __forceinline__ void tc_commit(uint32_t mbar) {
    asm volatile(
        "tcgen05.commit.cta_group::1.mbarrier::arrive::one.shared::cluster.b64 [%0];"
        :: "r"(mbar) : "memory");
}
#define TC_FENCE_AFTER()  asm volatile("tcgen05.fence::after_thread_sync;" ::: "memory")
#define TC_WAIT_LD()      asm volatile("tcgen05.wait::ld.sync.aligned;" ::: "memory")
#define FENCE_ASYNC()     asm volatile("fence.proxy.async.shared::cta;" ::: "memory")
#define TCGEN05_LD_32X32B_X32(r, tmem_addr) \
    asm volatile( \
        "tcgen05.ld.sync.aligned.32x32b.x32.b32 " \
        "{%0, %1, %2, %3, %4, %5, %6, %7, " \
        " %8, %9, %10, %11, %12, %13, %14, %15, " \
        " %16, %17, %18, %19, %20, %21, %22, %23, " \
        " %24, %25, %26, %27, %28, %29, %30, %31}, [%32];" \
        : "=r"((r)[0]),  "=r"((r)[1]),  "=r"((r)[2]),  "=r"((r)[3]), \
          "=r"((r)[4]),  "=r"((r)[5]),  "=r"((r)[6]),  "=r"((r)[7]), \
          "=r"((r)[8]),  "=r"((r)[9]),  "=r"((r)[10]), "=r"((r)[11]), \
          "=r"((r)[12]), "=r"((r)[13]), "=r"((r)[14]), "=r"((r)[15]), \
          "=r"((r)[16]), "=r"((r)[17]), "=r"((r)[18]), "=r"((r)[19]), \
          "=r"((r)[20]), "=r"((r)[21]), "=r"((r)[22]), "=r"((r)[23]), \
          "=r"((r)[24]), "=r"((r)[25]), "=r"((r)[26]), "=r"((r)[27]), \
          "=r"((r)[28]), "=r"((r)[29]), "=r"((r)[30]), "=r"((r)[31]) \
        : "r"(tmem_addr))
#endif // HAS_TCGEN05

#define SWZ(o) ((o) ^ (((o) >> 3) & 0x70))
#define SMEM_DESC_BASE ((uint64_t(2) << 61) | (uint64_t(1) << 46) | (uint64_t(64) << 32) | (uint64_t(1) << 16))
#define MK_DESC(addr) (SMEM_DESC_BASE | ((uint64_t)((addr) >> 4) & 0x3FFF))
// idescs: F32 accum, A=BF16, B=BF16, M=128; N=128 (QK) / N=64 (PV), all K-major
#define MMA_IDESC   0x8200490u
#define IDESC_PV    0x8100490u

// ---------------- weight convert+transpose: W[K][N] -> o[N][3K] [hi|hi|lo] ---
__device__ __forceinline__ void conv_w_body(const float* __restrict__ W,
                                            __nv_bfloat16* __restrict__ o, int K, int N) {
    __shared__ float t[32][33];
    int n0 = blockIdx.x * 32, k0 = blockIdx.y * 32;
    if (n0 >= N || k0 >= K) return;
    int tx = threadIdx.x, ty = threadIdx.y; // 32 x 8
    #pragma unroll
    for (int i = 0; i < 4; i++)
        t[ty + 8 * i][tx] = W[(size_t)(k0 + ty + 8 * i) * N + n0 + tx];
    __syncthreads();
    size_t K3 = 3 * (size_t)K;
    #pragma unroll
    for (int i = 0; i < 4; i++) {
        int nn = ty + 8 * i, kk = tx;
        float x = t[kk][nn];
        __nv_bfloat16 hi, lo; split_bf16(x, hi, lo);
        size_t base = (size_t)(n0 + nn) * K3 + (size_t)(k0 + kk);
        o[base] = hi; o[base + K] = hi; o[base + 2 * K] = lo;
    }
}
__global__ void conv_w4_kernel(const float* __restrict__ w0, const float* __restrict__ w1,
                               const float* __restrict__ w2, const float* __restrict__ w3,
                               __nv_bfloat16* o0, __nv_bfloat16* o1,
                               __nv_bfloat16* o2, __nv_bfloat16* o3) {
    const float* W = (blockIdx.z == 0) ? w0 : (blockIdx.z == 1) ? w1 : (blockIdx.z == 2) ? w2 : w3;
    __nv_bfloat16* O = (blockIdx.z == 0) ? o0 : (blockIdx.z == 1) ? o1 : (blockIdx.z == 2) ? o2 : o3;
    conv_w_body(W, O, TB_D, TB_D);
}
__global__ void conv_win_kernel(const float* __restrict__ w_in, __nv_bfloat16* win3) {
    conv_w_body(w_in, win3, TB_D, TB_F);
}
__global__ void conv_wout_kernel(const float* __restrict__ w_out, __nv_bfloat16* wout3) {
    conv_w_body(w_out, wout3, TB_F, TB_D);
}

// ---------------- srmsnorm -> split-bf16 segmented [hi|lo|hi] ----------------
__global__ void srmsnorm3_kernel(const float* __restrict__ x, __nv_bfloat16* __restrict__ y) {
    int row = blockIdx.x;
    int tid = threadIdx.x;
    const float* xr = x + (size_t)row * TB_D;
    float4 v = *(const float4*)(xr + tid * 4);
    float ss = v.x*v.x + v.y*v.y + v.z*v.z + v.w*v.w;
    #pragma unroll
    for (int o = 16; o; o >>= 1) ss += __shfl_xor_sync(0xffffffffu, ss, o);
    __shared__ float wred[8];
    __shared__ float s_scale;
    if ((tid & 31) == 0) wred[tid >> 5] = ss;
    __syncthreads();
    if (tid == 0) {
        float tot = 0.f;
        #pragma unroll
        for (int i = 0; i < 8; i++) tot += wred[i];
        s_scale = 32.0f / fmaxf(sqrtf(tot), 1e-12f);
    }
    __syncthreads();
    float sc = s_scale;
    float vals[4] = {v.x * sc, v.y * sc, v.z * sc, v.w * sc};
    __nv_bfloat16 hi[4], lo[4];
    #pragma unroll
    for (int j = 0; j < 4; j++) split_bf16(vals[j], hi[j], lo[j]);
    uint2 h2 = pack4bf(hi[0], hi[1], hi[2], hi[3]);
    uint2 l2 = pack4bf(lo[0], lo[1], lo[2], lo[3]);
    size_t base = (size_t)row * TB_D3 + tid * 4;
    *(uint2*)(y + base)              = h2;
    *(uint2*)(y + base + TB_D)       = l2;
    *(uint2*)(y + base + 2 * TB_D)   = h2;
}

// ---------------- tcgen05 split-bf16 GEMM, warp-specialized ------------------
// epi: 0 = fp32, 1 = fp32+res, 2 = gelu->segmented split, 3 = Q split,
//      4 = K split, 5 = V TRANSPOSED split (smem-staged 32x32 transpose)
#define GNST 4
#define STAGE_A 16384
#define STAGE_BYTES 49152
#define GEMM_SMEM (GNST * STAGE_BYTES + 1024)

__device__ __forceinline__ void tc_gemm_body(
    const __nv_bfloat16* __restrict__ A3, const __nv_bfloat16* __restrict__ B3,
    const float* __restrict__ res, void* __restrict__ Cout,
    int N, int K3, int m0, int n0, int epi)
{
#if HAS_TCGEN05
    extern __shared__ char dsm_raw[];
    __shared__ uint32_t s_tmem;
    __shared__ __align__(8) uint64_t s_bars[2 * GNST]; // full[4], empty[4]
    char* dsp = (char*)(((uintptr_t)dsm_raw + 1023) & ~(uintptr_t)1023);
    uint32_t dsm = smem_u32(dsp);
    int tid = threadIdx.x, wid = tid >> 5, lane = tid & 31;

    if (wid == 0) {
        asm volatile("tcgen05.alloc.cta_group::1.sync.aligned.shared::cta.b32 [%0], %1;"
                     :: "r"(smem_u32((void*)&s_tmem)), "r"(256u) : "memory");
    }
    if (tid == 0) {
        #pragma unroll
        for (int s = 0; s < GNST; s++) {
            mbar_init(smem_u32(&s_bars[s]), 128);        // full
            mbar_init(smem_u32(&s_bars[GNST + s]), 1);   // empty (commit)
        }
    }
    __syncthreads();
    uint32_t tmem = s_tmem;

    const __nv_bfloat16* Ab = A3 + (size_t)m0 * K3;
    const __nv_bfloat16* Bb = B3 + (size_t)n0 * K3;
    int nch = K3 >> 6;

    if (wid < 4) {
        for (int c = 0; c < nch; c++) {
            int s = c & 3;
            uint32_t sA = dsm + s * STAGE_BYTES;
            uint32_t sB = sA + STAGE_A;
            if (c >= GNST)
                mbar_wait(smem_u32(&s_bars[GNST + s]), ((c >> 2) - 1) & 1);
            const __nv_bfloat16* ga = Ab + ((size_t)c << 6);
            const __nv_bfloat16* gb = Bb + ((size_t)c << 6);
            #pragma unroll
            for (int i = 0; i < 8; i++) {
                int u = tid + (i << 7);
                int r = u >> 3, q = u & 7;
                cp_async16(sA + SWZ(r * 128 + q * 16), ga + (size_t)r * K3 + q * 8);
            }
            #pragma unroll
            for (int i = 0; i < 16; i++) {
                int u = tid + (i << 7);
                int r = u >> 3, q = u & 7;
                cp_async16(sB + SWZ(r * 128 + q * 16), gb + (size_t)r * K3 + q * 8);
            }
            cp_async_arrive(smem_u32(&s_bars[s]));
        }
        uint32_t pe = ((uint32_t)(nch >> 2) - 1u) & 1u;
        #pragma unroll
        for (int s = 0; s < GNST; s++)
            mbar_wait(smem_u32(&s_bars[GNST + s]), pe);
    } else if (wid == 7) {
        for (int c = 0; c < nch; c++) {
            int s = c & 3;
            uint32_t sA = dsm + s * STAGE_BYTES;
            uint32_t sB = sA + STAGE_A;
            mbar_wait(smem_u32(&s_bars[s]), (c >> 2) & 1);
            if (elect_one()) {
                uint64_t ad  = MK_DESC(sA);
                uint64_t bd0 = MK_DESC(sB);
                uint64_t bd1 = MK_DESC(sB + 16384);
                #pragma unroll
                for (int k = 0; k < 4; k++) {
                    uint32_t en = (c | k) ? 1u : 0u;
                    mma_f16_ss(tmem,       ad + 2*k, bd0 + 2*k, MMA_IDESC, en);
                    mma_f16_ss(tmem + 128, ad + 2*k, bd1 + 2*k, MMA_IDESC, en);
                }
                tc_commit(smem_u32(&s_bars[GNST + s]));   // ONE commit per group
            }
        }
    }
    __syncthreads();
    TC_FENCE_AFTER();

    int sub = wid & 3, half = wid >> 2;
    int mrow = m0 + sub * 32 + lane;
    for (int cb = 0; cb < 128; cb += 32) {
        uint32_t dr[32];
        TCGEN05_LD_32X32B_X32(dr, tmem + half * 128 + cb);
        TC_WAIT_LD();
        int n = n0 + half * 128 + cb;
        if (epi == 2) {
            __nv_bfloat16* C = (__nv_bfloat16*)Cout;
            size_t rb = (size_t)mrow * (3 * (size_t)N);
            __nv_bfloat16 hiA[32], loA[32];
            #pragma unroll
            for (int j = 0; j < 32; j++) {
                float f = gelu_tanh(__uint_as_float(dr[j]));
                split_bf16(f, hiA[j], loA[j]);
            }
            uint4* ph  = (uint4*)(C + rb + n);
            uint4* pl  = (uint4*)(C + rb + (size_t)N + n);
            uint4* ph2 = (uint4*)(C + rb + 2 * (size_t)N + n);
            #pragma unroll
            for (int t2 = 0; t2 < 4; t2++) {
                uint4 vh = ((uint4*)hiA)[t2];
                ph[t2] = vh; ph2[t2] = vh;
                pl[t2] = ((uint4*)loA)[t2];
            }
        } else if (epi == 3 || epi == 4) {
            __nv_bfloat16* C = (__nv_bfloat16*)Cout;
            int bb = mrow >> 11, tl = mrow & 2047;
            int head = n >> 6, d0 = n & 63;
            __nv_bfloat16 hiA[32], loA[32];
            #pragma unroll
            for (int j = 0; j < 32; j++)
                split_bf16(__uint_as_float(dr[j]), hiA[j], loA[j]);
            __nv_bfloat16* dst = C + (((size_t)(bb * 16 + head)) * 2048 + tl) * 128;
            uint4* ph = (uint4*)(dst + d0);
            uint4* pl = (uint4*)(dst + 64 + d0);
            #pragma unroll
            for (int t2 = 0; t2 < 4; t2++) {
                ph[t2] = ((uint4*)hiA)[t2];
                pl[t2] = ((uint4*)loA)[t2];
            }
        } else if (epi == 5) {
            // V transposed: vt3[b*16+h][128 d-rows (hi 0..63, lo 64..127)][2048]
            __nv_bfloat16* C = (__nv_bfloat16*)Cout;
            int bb = mrow >> 11;
            int head = n >> 6, d0 = n & 63;
            int tl0 = (m0 & 2047) + sub * 32;     // token base of this warp
            __nv_bfloat16 hiA[32], loA[32];
            #pragma unroll
            for (int j = 0; j < 32; j++)
                split_bf16(__uint_as_float(dr[j]), hiA[j], loA[j]);
            // per-warp 32x32 transpose through smem (stages are free now)
            uint16_t* sc  = (uint16_t*)(dsp + (size_t)wid * 4352);
            uint16_t* scl = sc + 1088;
            #pragma unroll
            for (int j = 0; j < 32; j++) {
                sc [lane * 34 + j] = __bfloat16_as_ushort(hiA[j]);
                scl[lane * 34 + j] = __bfloat16_as_ushort(loA[j]);
            }
            __syncwarp();
            uint32_t wh[16], wl[16];
            #pragma unroll
            for (int g = 0; g < 16; g++) {
                wh[g] = (uint32_t)sc [(2*g) * 34 + lane] | ((uint32_t)sc [(2*g+1) * 34 + lane] << 16);
                wl[g] = (uint32_t)scl[(2*g) * 34 + lane] | ((uint32_t)scl[(2*g+1) * 34 + lane] << 16);
            }
            size_t base_hb = (size_t)(bb * 16 + head) * 262144;  // 128*2048
            __nv_bfloat16* dh = C + base_hb + (size_t)(d0 + lane) * 2048 + tl0;
            __nv_bfloat16* dl = C + base_hb + (size_t)(64 + d0 + lane) * 2048 + tl0;
            #pragma unroll
            for (int g = 0; g < 4; g++) {
                ((uint4*)dh)[g] = ((uint4*)wh)[g];
                ((uint4*)dl)[g] = ((uint4*)wl)[g];
            }
            __syncwarp();
        } else {
            float* C = (float*)Cout;
            size_t base = (size_t)mrow * N + n;
            #pragma unroll
            for (int j = 0; j < 32; j += 4) {
                float4 v = make_float4(__uint_as_float(dr[j]),   __uint_as_float(dr[j+1]),
                                       __uint_as_float(dr[j+2]), __uint_as_float(dr[j+3]));
                if (epi == 1) {
                    float4 r4 = *(const float4*)(res + base + j);
                    v.x += r4.x; v.y += r4.y; v.z += r4.z; v.w += r4.w;
                }
                *(float4*)(C + base + j) = v;
            }
        }
    }
    __syncthreads();
    if (wid == 0) {
        asm volatile("tcgen05.relinquish_alloc_permit.cta_group::1.sync.aligned;");
        asm volatile("tcgen05.dealloc.cta_group::1.sync.aligned.b32 %0, %1;"
                     :: "r"(tmem), "r"(256u));
    }
#else
    // ---------------- SIMT fallback (non-sm_103a cubin only) -----------------
    extern __shared__ char dsm_raw[];
    __nv_bfloat16* As = (__nv_bfloat16*)dsm_raw;
    const int CH = 2048;
    int tid = threadIdx.x;
    int n_c = n0 + tid;
    for (int m = 0; m < 128; m++) {
        const __nv_bfloat16* arow = A3 + (size_t)(m0 + m) * K3;
        float acc = 0.f;
        for (int c0 = 0; c0 < K3; c0 += CH) {
            int len = min(CH, K3 - c0);
            for (int i = tid; i < len / 8; i += 256)
                ((float4*)As)[i] = ((const float4*)(arow + c0))[i];
            __syncthreads();
            const __nv_bfloat16* b0 = B3 + (size_t)n_c * K3 + c0;
            for (int k = 0; k < len; k++)
                acc = fmaf(__bfloat162float(As[k]), __bfloat162float(b0[k]), acc);
            __syncthreads();
        }
        int mrow = m0 + m;
        if (epi == 2) {
            __nv_bfloat16* C = (__nv_bfloat16*)Cout;
            size_t base = (size_t)mrow * (3 * (size_t)N);
            float f = gelu_tanh(acc);
            __nv_bfloat16 hi, lo; split_bf16(f, hi, lo);
            C[base + n_c] = hi; C[base + N + n_c] = lo; C[base + 2 * N + n_c] = hi;
        } else if (epi == 3 || epi == 4) {
            __nv_bfloat16* C = (__nv_bfloat16*)Cout;
            int bb = mrow >> 11, tl = mrow & 2047;
            int head = n_c >> 6, d = n_c & 63;
            __nv_bfloat16 hi, lo; split_bf16(acc, hi, lo);
            size_t base = (((size_t)(bb * 16 + head)) * 2048 + tl) * 128;
            C[base + d] = hi; C[base + 64 + d] = lo;
        } else if (epi == 5) {
            __nv_bfloat16* C = (__nv_bfloat16*)Cout;
            int bb = mrow >> 11, tl = mrow & 2047;
            int head = n_c >> 6, d = n_c & 63;
            __nv_bfloat16 hi, lo; split_bf16(acc, hi, lo);
            size_t base = (size_t)(bb * 16 + head) * 262144;
            C[base + (size_t)d * 2048 + tl] = hi;
            C[base + (size_t)(64 + d) * 2048 + tl] = lo;
        } else {
            float* C = (float*)Cout;
            size_t base = (size_t)mrow * N;
            if (epi == 1) acc += res[base + n_c];
            C[base + n_c] = acc;
        }
    }
#endif
}

template<int EPI>
__global__ __launch_bounds__(256, 1) void tc_gemm(
    const __nv_bfloat16* __restrict__ A3, const __nv_bfloat16* __restrict__ B3,
    const float* __restrict__ res, void* __restrict__ C, int N, int K3)
{
    tc_gemm_body(A3, B3, res, C, N, K3, blockIdx.y * 128, blockIdx.x * 256, EPI);
}

__global__ __launch_bounds__(256, 1) void tc_gemm_qkv(
    const __nv_bfloat16* __restrict__ A3,
    const __nv_bfloat16* __restrict__ b0, const __nv_bfloat16* __restrict__ b1,
    const __nv_bfloat16* __restrict__ b2,
    __nv_bfloat16* __restrict__ c0, __nv_bfloat16* __restrict__ c1,
    __nv_bfloat16* __restrict__ c2)
{
    const __nv_bfloat16* B3 = (blockIdx.z == 0) ? b0 : ((blockIdx.z == 1) ? b1 : b2);
    __nv_bfloat16* C = (blockIdx.z == 0) ? c0 : ((blockIdx.z == 1) ? c1 : c2);
    tc_gemm_body(A3, B3, nullptr, C, TB_D, TB_D3,
                 blockIdx.y * 128, blockIdx.x * 256, 3 + (int)blockIdx.z);
}

// ---------------- tcgen05 causal flash attention ------------------------------
// CTA = (q-tile 128, head, batch). 256 threads:
//   warps 0-3: softmax + O accumulation (lane owns row), 4-5: K loaders,
//   6: V loader, 7: MMA issuer.
// smem (16KB chunks, SW128): Q hi|lo (32K) | K double-buffered hi|lo (64K) |
//   Vt 4x8K = hi c0,c1, lo c0,c1 (32K) | P hi0,hi1,lo0,lo1 (64K). +1K align slack.
// Barriers: bK[2] (K full), bV (V full), bP (P written, 128), bO (PV commit),
//   bSK[2] (QK commit = S ready AND K buffer free). ONE commit per MMA group.
#define ATT_DSMEM (192 * 1024 + 1024)

__global__ __launch_bounds__(256, 1) void tc_attn(
    const __nv_bfloat16* __restrict__ q3, const __nv_bfloat16* __restrict__ k3,
    const __nv_bfloat16* __restrict__ vt3, __nv_bfloat16* __restrict__ att3)
{
    int qtile = 15 - (int)blockIdx.x;          // heavy tiles first
    int h = blockIdx.y, b = blockIdx.z;
    int ntiles = qtile + 1;
    int q0 = qtile * 128;
    size_t hb = (size_t)b * 16 + h;
    const __nv_bfloat16* qh = q3 + hb * (size_t)2048 * 128;
    const __nv_bfloat16* kh = k3 + hb * (size_t)2048 * 128;
    const __nv_bfloat16* vh = vt3 + hb * (size_t)262144;
#if HAS_TCGEN05
    extern __shared__ char dsm_raw[];
    __shared__ uint32_t s_tmem;
    __shared__ __align__(8) uint64_t bars[7]; // bK0 bK1 bV bP bO bSK0 bSK1
    char* dsmp = (char*)(((uintptr_t)dsm_raw + 1023) & ~(uintptr_t)1023);
    uint32_t dsm = smem_u32(dsmp);
    uint32_t Q0c = dsm, Q1c = dsm + 16384;
    uint32_t Kst = dsm + 32768;                 // + buf*32768 ; lo at +16384
    uint32_t Vt  = dsm + 98304;                 // 4 chunks of 8KB
    uint32_t Pb  = dsm + 131072;                // Phi0,Phi1,Plo0,Plo1
    uint32_t bK[2]  = { smem_u32(&bars[0]), smem_u32(&bars[1]) };
    uint32_t bV = smem_u32(&bars[2]), bP = smem_u32(&bars[3]);
    uint32_t bO = smem_u32(&bars[4]);
    uint32_t bSK[2] = { smem_u32(&bars[5]), smem_u32(&bars[6]) };
    int tid = threadIdx.x, wid = tid >> 5, lane = tid & 31;

    if (wid == 0) {
        asm volatile("tcgen05.alloc.cta_group::1.sync.aligned.shared::cta.b32 [%0], %1;"
                     :: "r"(smem_u32((void*)&s_tmem)), "r"(256u) : "memory");
    }
    if (tid == 0) {
        mbar_init(bK[0], 64); mbar_init(bK[1], 64);
        mbar_init(bV, 32); mbar_init(bP, 128); mbar_init(bO, 1);
        mbar_init(bSK[0], 1); mbar_init(bSK[1], 1);
    }
    __syncthreads();
    uint32_t tmem = s_tmem;

    // Q preload (warps 4-7)
    if (wid >= 4) {
        int t4 = tid - 128;
        #pragma unroll
        for (int i = 0; i < 8; i++) {
            int u = t4 + 128 * i, r = u >> 3, q = u & 7;
            cp_async16(Q0c + SWZ(r * 128 + q * 16), qh + (size_t)(q0 + r) * 128 + q * 8);
        }
        #pragma unroll
        for (int i = 0; i < 8; i++) {
            int u = t4 + 128 * i, r = u >> 3, q = u & 7;
            cp_async16(Q1c + SWZ(r * 128 + q * 16), qh + (size_t)(q0 + r) * 128 + 64 + q * 8);
        }
        asm volatile("cp.async.wait_all;" ::: "memory");
    }
    __syncthreads();

    if (wid == 4 || wid == 5) {
        // ---------------- K loaders (64 threads), double-buffered -------------
        int t2 = tid - 128;
        for (int t = 0; t < ntiles; t++) {
            if (t >= 2) mbar_wait(bSK[t & 1], ((t >> 1) - 1) & 1);  // QK(t-2) done
            uint32_t Ks = Kst + (t & 1) * 32768;
            int k0 = t * 128;
            #pragma unroll
            for (int i = 0; i < 16; i++) {
                int u = t2 + 64 * i, r = u >> 3, q = u & 7;
                cp_async16(Ks + SWZ(r * 128 + q * 16), kh + (size_t)(k0 + r) * 128 + q * 8);
            }
            #pragma unroll
            for (int i = 0; i < 16; i++) {
                int u = t2 + 64 * i, r = u >> 3, q = u & 7;
                cp_async16(Ks + 16384 + SWZ(r * 128 + q * 16), kh + (size_t)(k0 + r) * 128 + 64 + q * 8);
            }
            cp_async_arrive(bK[t & 1]);
        }
    } else if (wid == 6) {
        // ---------------- V loader (32 threads), single buffer ----------------
        int t3 = tid - 192;
        for (int t = 0; t < ntiles; t++) {
            if (t >= 1) mbar_wait(bO, (t - 1) & 1);   // PV(t-1) done reading Vt
            int k0 = t * 128;
            #pragma unroll
            for (int p = 0; p < 2; p++)
                #pragma unroll
                for (int cc = 0; cc < 2; cc++) {
                    uint32_t cb = Vt + (p * 2 + cc) * 8192;
                    #pragma unroll
                    for (int i = 0; i < 16; i++) {
                        int u = t3 + 32 * i, r = u >> 3, q = u & 7;
                        cp_async16(cb + SWZ(r * 128 + q * 16),
                                   vh + (size_t)(p * 64 + r) * 2048 + k0 + cc * 64 + q * 8);
                    }
                }
            cp_async_arrive(bV);
        }
    } else if (wid == 7) {
        // ---------------- MMA issuer -------------------------------------------
        // QK(t) is safe vs compute's S(t-1) reads: bP(t-1) was waited before
        // PV(t-1) in the previous iteration.
        for (int t = 0; t < ntiles; t++) {
            mbar_wait(bK[t & 1], (t >> 1) & 1);
            if (elect_one()) {
                uint32_t Ks = Kst + (t & 1) * 32768;
                uint64_t qd[3] = { MK_DESC(Q0c), MK_DESC(Q1c), MK_DESC(Q0c) };
                uint64_t kd[3] = { MK_DESC(Ks), MK_DESC(Ks), MK_DESC(Ks + 16384) };
                #pragma unroll
                for (int seg = 0; seg < 3; seg++)
                    #pragma unroll
                    for (int s = 0; s < 4; s++)
                        mma_f16_ss(tmem, qd[seg] + 2 * s, kd[seg] + 2 * s,
                                   MMA_IDESC, (seg | s) ? 1u : 0u);
                tc_commit(bSK[t & 1]);     // single commit: S ready + K free
            }
            mbar_wait(bV, t & 1);
            mbar_wait(bP, t & 1);          // P(t) written + O(t-1) folded
            if (elect_one()) {
                uint64_t pa[3][2] = {
                    { MK_DESC(Pb),         MK_DESC(Pb + 16384) },
                    { MK_DESC(Pb + 32768), MK_DESC(Pb + 49152) },
                    { MK_DESC(Pb),         MK_DESC(Pb + 16384) } };
                const int vpart[3] = { 0, 0, 1 };   // Phi*Vhi + Plo*Vhi + Phi*Vlo
                #pragma unroll
                for (int seg = 0; seg < 3; seg++)
                    #pragma unroll
                    for (int s = 0; s < 8; s++) {
                        int cc = s >> 2;
                        mma_f16_ss(tmem + 128,
                                   pa[seg][cc] + 2 * (s & 3),
                                   MK_DESC(Vt + (vpart[seg] * 2 + cc) * 8192) + 2 * (s & 3),
                                   IDESC_PV, (seg | s) ? 1u : 0u);
                    }
                tc_commit(bO);
            }
        }
    } else {
        // ---------------- compute warps 0-3: lane owns row ---------------------
        int rloc = wid * 32 + lane;
        int rg = q0 + rloc;
        float m = -1e30f, l = 0.f, alpha_prev = 0.f;
        float O[64];
        #pragma unroll
        for (int j = 0; j < 64; j++) O[j] = 0.f;

        for (int t = 0; t < ntiles; t++) {
            mbar_wait(bSK[t & 1], (t >> 1) & 1);   // S(t) ready
            TC_FENCE_AFTER();
            int k0 = t * 128;
            int lim = rg - k0;   // valid cols c <= lim
            // pass 1: row max (S stays in TMEM)
            float mt = -1e30f;
            #pragma unroll
            for (int cb = 0; cb < 4; cb++) {
                uint32_t dr[32];
                TCGEN05_LD_32X32B_X32(dr, tmem + cb * 32);
                TC_WAIT_LD();
                #pragma unroll
                for (int j = 0; j < 32; j++) {
                    int c = cb * 32 + j;
                    float v = (c <= lim) ? __uint_as_float(dr[j]) * 0.125f : -1e30f;
                    mt = fmaxf(mt, v);
                }
            }
            float mn = fmaxf(m, mt);
            float al = __expf(m - mn);
            // fold previous PV result BEFORE writing P (PV(t-1) reads Pb)
            if (t > 0) {
                mbar_wait(bO, (t - 1) & 1);
                TC_FENCE_AFTER();
                uint32_t du[32];
                TCGEN05_LD_32X32B_X32(du, tmem + 128);
                TC_WAIT_LD();
                #pragma unroll
                for (int j = 0; j < 32; j++)
                    O[j] = O[j] * alpha_prev + __uint_as_float(du[j]);
                TCGEN05_LD_32X32B_X32(du, tmem + 160);
                TC_WAIT_LD();
                #pragma unroll
                for (int j = 0; j < 32; j++)
                    O[32 + j] = O[32 + j] * alpha_prev + __uint_as_float(du[j]);
            }
            // pass 2: exp + split-store P into smem
            float ps = 0.f;
            #pragma unroll
            for (int cb = 0; cb < 4; cb++) {
                uint32_t dr[32];
                TCGEN05_LD_32X32B_X32(dr, tmem + cb * 32);
                TC_WAIT_LD();
                #pragma unroll
                for (int j = 0; j < 32; j += 4) {
                    int c = cb * 32 + j;
                    float v0 = (c     <= lim) ? __uint_as_float(dr[j])     * 0.125f : -1e30f;
                    float v1 = (c + 1 <= lim) ? __uint_as_float(dr[j + 1]) * 0.125f : -1e30f;
                    float v2 = (c + 2 <= lim) ? __uint_as_float(dr[j + 2]) * 0.125f : -1e30f;
                    float v3 = (c + 3 <= lim) ? __uint_as_float(dr[j + 3]) * 0.125f : -1e30f;
                    float p0 = __expf(v0 - mn), p1 = __expf(v1 - mn);
                    float p2 = __expf(v2 - mn), p3 = __expf(v3 - mn);
                    ps += (p0 + p1) + (p2 + p3);
                    __nv_bfloat16 h0,l0,h1,l1,h2,l2,h3,l3;
                    split_bf16(p0, h0, l0); split_bf16(p1, h1, l1);
                    split_bf16(p2, h2, l2); split_bf16(p3, h3, l3);
                    uint2 hv = pack4bf(h0, h1, h2, h3);
                    uint2 lv = pack4bf(l0, l1, l2, l3);
                    int subo = (c >> 6) * 16384;
                    uint32_t so = SWZ(rloc * 128 + (c & 63) * 2);
                    *(uint2*)(dsmp + 131072 + subo + so) = hv;   // Phi
                    *(uint2*)(dsmp + 163840 + subo + so) = lv;   // Plo
                }
            }
            l = l * al + ps;
            alpha_prev = al;
            m = mn;
            FENCE_ASYNC();
            mbar_arrive(bP);
        }
        // final fold + output
        mbar_wait(bO, (ntiles - 1) & 1);
        TC_FENCE_AFTER();
        {
            uint32_t du[32];
            TCGEN05_LD_32X32B_X32(du, tmem + 128);
            TC_WAIT_LD();
            #pragma unroll
            for (int j = 0; j < 32; j++)
                O[j] = O[j] * alpha_prev + __uint_as_float(du[j]);
            TCGEN05_LD_32X32B_X32(du, tmem + 160);
            TC_WAIT_LD();
            #pragma unroll
            for (int j = 0; j < 32; j++)
                O[32 + j] = O[32 + j] * alpha_prev + __uint_as_float(du[j]);
        }
        float inv = 1.0f / l;
        __nv_bfloat16 hi[64], lo[64];
        #pragma unroll
        for (int j = 0; j < 64; j++) split_bf16(O[j] * inv, hi[j], lo[j]);
        size_t rb = ((size_t)b * 2048 + rg) * TB_D3 + h * 64;
        uint4* ph  = (uint4*)(att3 + rb);
        uint4* pl  = (uint4*)(att3 + rb + 1024);
        uint4* ph2 = (uint4*)(att3 + rb + 2048);
        #pragma unroll
        for (int i = 0; i < 8; i++) {
            uint4 vh2 = ((uint4*)hi)[i];
            ph[i] = vh2; ph2[i] = vh2;
            pl[i] = ((uint4*)lo)[i];
        }
    }
    __syncthreads();
    if (wid == 0) {
        asm volatile("tcgen05.relinquish_alloc_permit.cta_group::1.sync.aligned;");
        asm volatile("tcgen05.dealloc.cta_group::1.sync.aligned.b32 %0, %1;"
                     :: "r"(tmem), "r"(256u));
    }
#else
    // ---------------- SIMT fallback (non-sm_103a cubin only) ------------------
    int tid = threadIdx.x;
    if (tid < 128) {
        int rg = q0 + tid;
        float q[64];
        #pragma unroll
        for (int d = 0; d < 64; d++)
            q[d] = __bfloat162float(qh[(size_t)rg * 128 + d]) +
                   __bfloat162float(qh[(size_t)rg * 128 + 64 + d]);
        float m = -1e30f;
        for (int k = 0; k <= rg; k++) {
            float s = 0.f;
            for (int d = 0; d < 64; d++)
                s += q[d] * (__bfloat162float(kh[(size_t)k * 128 + d]) +
                             __bfloat162float(kh[(size_t)k * 128 + 64 + d]));
            m = fmaxf(m, s * 0.125f);
        }
        float l = 0.f, O[64];
        for (int d = 0; d < 64; d++) O[d] = 0.f;
        for (int k = 0; k <= rg; k++) {
            float s = 0.f;
            for (int d = 0; d < 64; d++)
                s += q[d] * (__bfloat162float(kh[(size_t)k * 128 + d]) +
                             __bfloat162float(kh[(size_t)k * 128 + 64 + d]));
            float p = expf(s * 0.125f - m);
            l += p;
            for (int d = 0; d < 64; d++)
                O[d] += p * (__bfloat162float(vh[(size_t)d * 2048 + k]) +
                             __bfloat162float(vh[(size_t)(64 + d) * 2048 + k]));
        }
        float inv = 1.0f / l;
        size_t rb = ((size_t)b * 2048 + rg) * TB_D3 + h * 64;
        for (int d = 0; d < 64; d++) {
            __nv_bfloat16 hi, lo; split_bf16(O[d] * inv, hi, lo);
            att3[rb + d] = hi; att3[rb + 1024 + d] = lo; att3[rb + 2048 + d] = hi;
        }
    }
#endif
}

// ---------------- launch ------------------------------------------------------
extern "C" void kernel_launch(void* const* d_in, const int* in_sizes, int n_in,
                              void* d_out, int out_size) {
    const float* x     = (const float*)d_in[0];
    const float* wq    = (const float*)d_in[1];
    const float* wk    = (const float*)d_in[2];
    const float* wv    = (const float*)d_in[3];
    const float* wo    = (const float*)d_in[4];
    const float* w_in  = (const float*)d_in[5];
    const float* w_out = (const float*)d_in[6];
    float* out = (float*)d_out;
    (void)in_sizes; (void)n_in; (void)out_size;

    __nv_bfloat16 *xn3, *att3, *ff3, *q3, *k3, *vt3;
    __nv_bfloat16 *wq3, *wk3, *wv3, *wo3, *win3, *wout3;
    float *h;
    cudaGetSymbolAddress((void**)&xn3,  g_xn3);
    cudaGetSymbolAddress((void**)&att3, g_att3);
    cudaGetSymbolAddress((void**)&ff3,  g_ff3);
    cudaGetSymbolAddress((void**)&q3,   g_q3);
    cudaGetSymbolAddress((void**)&k3,   g_k3);
    cudaGetSymbolAddress((void**)&vt3,  g_vt3);
    cudaGetSymbolAddress((void**)&h,    g_h);
    cudaGetSymbolAddress((void**)&wq3,  g_wq3);
    cudaGetSymbolAddress((void**)&wk3,  g_wk3);
    cudaGetSymbolAddress((void**)&wv3,  g_wv3);
    cudaGetSymbolAddress((void**)&wo3,  g_wo3);
    cudaGetSymbolAddress((void**)&win3, g_win3);
    cudaGetSymbolAddress((void**)&wout3, g_wout3);

    cudaFuncSetAttribute(tc_attn,     cudaFuncAttributeMaxDynamicSharedMemorySize, ATT_DSMEM);
    cudaFuncSetAttribute(tc_gemm_qkv, cudaFuncAttributeMaxDynamicSharedMemorySize, GEMM_SMEM);
    cudaFuncSetAttribute(tc_gemm<1>,  cudaFuncAttributeMaxDynamicSharedMemorySize, GEMM_SMEM);
    cudaFuncSetAttribute(tc_gemm<2>,  cudaFuncAttributeMaxDynamicSharedMemorySize, GEMM_SMEM);

    dim3 cwb(32, 8);
    // launch #6 = tc_attn (ncu -s 5 -c 1 window)
    conv_w4_kernel<<<dim3(32, 32, 4), cwb>>>(wq, wk, wv, wo, wq3, wk3, wv3, wo3);   // 1
    conv_win_kernel<<<dim3(128, 32), cwb>>>(w_in, win3);                            // 2
    conv_wout_kernel<<<dim3(32, 128), cwb>>>(w_out, wout3);                         // 3
    srmsnorm3_kernel<<<TB_T, 256>>>(x, xn3);                                        // 4
    tc_gemm_qkv<<<dim3(TB_D / 256, TB_T / 128, 3), 256, GEMM_SMEM>>>(               // 5
        xn3, wq3, wk3, wv3, q3, k3, vt3);
    tc_attn<<<dim3(16, TB_H, TB_B), 256, ATT_DSMEM>>>(q3, k3, vt3, att3);           // 6
    tc_gemm<1><<<dim3(TB_D / 256, TB_T / 128), 256, GEMM_SMEM>>>(                   // 7
        att3, wo3, x, h, TB_D, TB_D3);
    srmsnorm3_kernel<<<TB_T, 256>>>(h, xn3);                                        // 8
    tc_gemm<2><<<dim3(TB_F / 256, TB_T / 128), 256, GEMM_SMEM>>>(                   // 9
        xn3, win3, nullptr, ff3, TB_F, TB_D3);
    tc_gemm<1><<<dim3(TB_D / 256, TB_T / 128), 256, GEMM_SMEM>>>(                   // 10
        ff3, wout3, h, out, TB_D, TB_F3);
}

// round 12
// speedup vs baseline: 5.1570x; 1.0664x over previous
#include <cuda_runtime.h>
#include <cuda_bf16.h>
#include <math.h>
#include <stdint.h>

// Problem dims (fixed by the reference)
#define TB_B 2
#define TB_S 2048
#define TB_D 1024
#define TB_F 4096
#define TB_H 16
#define TB_HD 64
#define TB_T (TB_B * TB_S)   // 4096 tokens
#define TB_D2 (2 * TB_D)     // 2048 ([hi|lo] split layout)
#define TB_F2 (2 * TB_F)     // 8192

#if defined(__CUDA_ARCH_FEAT_SM103_ALL) || defined(__CUDA_ARCH_FEAT_SM100_ALL)
#define HAS_TCGEN05 1
#else
#define HAS_TCGEN05 0
#endif

// ---------------- scratch ----------------------------------------------------
// 2x split layout: rows = [hi(K) | lo(K)] for BOTH operands.
// GEMM computes Ahi.Bhi + Alo.Bhi + Ahi.Blo via 3 MMA segments reusing smem
// (same math as before: x.w - lo.lo, ~2^-18 rel err) -> 33% less L2 traffic.
__device__ __nv_bfloat16 g_xn3 [(size_t)TB_T * TB_D2];
__device__ __nv_bfloat16 g_att3[(size_t)TB_T * TB_D2];
__device__ __nv_bfloat16 g_ff3 [(size_t)TB_T * TB_F2];
__device__ float g_h [(size_t)TB_T * TB_D];
// attention operands (per (b,h)):
//   q3,k3: [b][h][t][128] = [hi(64)|lo(64)] over head dims (K-major rows)
//   vt3:   [b][h][128 d-rows][2048 tokens]; d-rows 0..63 = hi, 64..127 = lo
__device__ __nv_bfloat16 g_q3 [(size_t)TB_T * TB_H * 128];
__device__ __nv_bfloat16 g_k3 [(size_t)TB_T * TB_H * 128];
__device__ __nv_bfloat16 g_vt3[(size_t)TB_B * TB_H * 128 * TB_S];
__device__ __nv_bfloat16 g_wq3 [(size_t)TB_D * TB_D2];
__device__ __nv_bfloat16 g_wk3 [(size_t)TB_D * TB_D2];
__device__ __nv_bfloat16 g_wv3 [(size_t)TB_D * TB_D2];
__device__ __nv_bfloat16 g_wo3 [(size_t)TB_D * TB_D2];
__device__ __nv_bfloat16 g_win3[(size_t)TB_F * TB_D2];
__device__ __nv_bfloat16 g_wout3[(size_t)TB_D * TB_F2];

// ---------------- helpers ----------------------------------------------------
__device__ __forceinline__ uint32_t smem_u32(const void* p) {
    uint32_t a;
    asm("{ .reg .u64 t; cvta.to.shared.u64 t, %1; cvt.u32.u64 %0, t; }" : "=r"(a) : "l"(p));
    return a;
}
__device__ __forceinline__ void split_bf16(float x, __nv_bfloat16& hi, __nv_bfloat16& lo) {
    hi = __float2bfloat16(x);
    lo = __float2bfloat16(x - __bfloat162float(hi));
}
__device__ __forceinline__ float gelu_tanh(float v) {
    const float c = 0.79788456080286535588f;
    float t = c * (v + 0.044715f * v * v * v);
    return 0.5f * v * (1.0f + tanhf(t));
}
__device__ __forceinline__ uint2 pack4bf(__nv_bfloat16 a, __nv_bfloat16 b,
                                         __nv_bfloat16 c, __nv_bfloat16 d) {
    uint2 r;
    r.x = (uint32_t)__bfloat16_as_ushort(a) | ((uint32_t)__bfloat16_as_ushort(b) << 16);
    r.y = (uint32_t)__bfloat16_as_ushort(c) | ((uint32_t)__bfloat16_as_ushort(d) << 16);
    return r;
}

#if HAS_TCGEN05
__device__ __forceinline__ uint32_t elect_one() {
    uint32_t p;
    asm volatile("{ .reg .pred p; elect.sync _|p, 0xFFFFFFFF; selp.b32 %0, 1, 0, p; }" : "=r"(p));
    return p;
}
__device__ __forceinline__ void mbar_init(uint32_t a, uint32_t cnt) {
    asm volatile("mbarrier.init.shared.b64 [%0], %1;" :: "r"(a), "r"(cnt) : "memory");
}
__device__ __forceinline__ void mbar_arrive(uint32_t a) {
    asm volatile("mbarrier.arrive.shared.b64 _, [%0];" :: "r"(a) : "memory");
}
__device__ __forceinline__ void mbar_wait(uint32_t a, uint32_t parity) {
    asm volatile(
        "{\n\t.reg .pred P;\n\t"
        "LW%=:\n\t"
        "mbarrier.try_wait.parity.acquire.cta.shared::cta.b64 P, [%0], %1, 0x989680;\n\t"
        "@P bra LD%=;\n\t"
        "bra LW%=;\n\t"
        "LD%=:\n\t}"
        :: "r"(a), "r"(parity) : "memory");
}
__device__ __forceinline__ void cp_async16(uint32_t dst, const void* src) {
    asm volatile("cp.async.cg.shared.global [%0], [%1], 16;" :: "r"(dst), "l"(src) : "memory");
}
__device__ __forceinline__ void cp_async_arrive(uint32_t mbar) {
    asm volatile("cp.async.mbarrier.arrive.noinc.shared::cta.b64 [%0];" :: "r"(mbar) : "memory");
}
__device__ __forceinline__ void mma_f16_ss(uint32_t d, uint64_t ad, uint64_t bd,
                                           uint32_t idesc, uint32_t en) {
    asm volatile(
        "{\n\t.reg .pred p;\n\tsetp.ne.u32 p, %4, 0;\n\t"
        "tcgen05.mma.cta_group::1.kind::f16 [%0], %1, %2, %3, {%5, %5, %5, %5}, p;\n\t}"
        :: "r"(d), "l"(ad), "l"(bd), "r"(idesc), "r"(en), "r"(0u) : "memory");
}
__device__ __forceinline__ void tc_commit(uint32_t mbar) {
    asm volatile(
        "tcgen05.commit.cta_group::1.mbarrier::arrive::one.shared::cluster.b64 [%0];"
        :: "r"(mbar) : "memory");
}
#define TC_FENCE_AFTER()  asm volatile("tcgen05.fence::after_thread_sync;" ::: "memory")
#define TC_WAIT_LD()      asm volatile("tcgen05.wait::ld.sync.aligned;" ::: "memory")
#define FENCE_ASYNC()     asm volatile("fence.proxy.async.shared::cta;" ::: "memory")
#define TCGEN05_LD_32X32B_X32(r, tmem_addr) \
    asm volatile( \
        "tcgen05.ld.sync.aligned.32x32b.x32.b32 " \
        "{%0, %1, %2, %3, %4, %5, %6, %7, " \
        " %8, %9, %10, %11, %12, %13, %14, %15, " \
        " %16, %17, %18, %19, %20, %21, %22, %23, " \
        " %24, %25, %26, %27, %28, %29, %30, %31}, [%32];" \
        : "=r"((r)[0]),  "=r"((r)[1]),  "=r"((r)[2]),  "=r"((r)[3]), \
          "=r"((r)[4]),  "=r"((r)[5]),  "=r"((r)[6]),  "=r"((r)[7]), \
          "=r"((r)[8]),  "=r"((r)[9]),  "=r"((r)[10]), "=r"((r)[11]), \
          "=r"((r)[12]), "=r"((r)[13]), "=r"((r)[14]), "=r"((r)[15]), \
          "=r"((r)[16]), "=r"((r)[17]), "=r"((r)[18]), "=r"((r)[19]), \
          "=r"((r)[20]), "=r"((r)[21]), "=r"((r)[22]), "=r"((r)[23]), \
          "=r"((r)[24]), "=r"((r)[25]), "=r"((r)[26]), "=r"((r)[27]), \
          "=r"((r)[28]), "=r"((r)[29]), "=r"((r)[30]), "=r"((r)[31]) \
        : "r"(tmem_addr))
#endif // HAS_TCGEN05

#define SWZ(o) ((o) ^ (((o) >> 3) & 0x70))
#define SMEM_DESC_BASE ((uint64_t(2) << 61) | (uint64_t(1) << 46) | (uint64_t(64) << 32) | (uint64_t(1) << 16))
#define MK_DESC(addr) (SMEM_DESC_BASE | ((uint64_t)((addr) >> 4) & 0x3FFF))
// idescs: F32 accum, A=BF16, B=BF16, M=128; N=128 (QK/GEMM) / N=64 (PV), K-major
#define MMA_IDESC   0x8200490u
#define IDESC_PV    0x8100490u

// ---------------- weight convert+transpose: W[K][N] -> o[N][2K] [hi|lo] ------
__device__ __forceinline__ void conv_w_body(const float* __restrict__ W,
                                            __nv_bfloat16* __restrict__ o, int K, int N) {
    __shared__ float t[32][33];
    int n0 = blockIdx.x * 32, k0 = blockIdx.y * 32;
    if (n0 >= N || k0 >= K) return;
    int tx = threadIdx.x, ty = threadIdx.y; // 32 x 8
    #pragma unroll
    for (int i = 0; i < 4; i++)
        t[ty + 8 * i][tx] = W[(size_t)(k0 + ty + 8 * i) * N + n0 + tx];
    __syncthreads();
    size_t K2 = 2 * (size_t)K;
    #pragma unroll
    for (int i = 0; i < 4; i++) {
        int nn = ty + 8 * i, kk = tx;
        float x = t[kk][nn];
        __nv_bfloat16 hi, lo; split_bf16(x, hi, lo);
        size_t base = (size_t)(n0 + nn) * K2 + (size_t)(k0 + kk);
        o[base] = hi; o[base + K] = lo;
    }
}
__global__ void conv_w4_kernel(const float* __restrict__ w0, const float* __restrict__ w1,
                               const float* __restrict__ w2, const float* __restrict__ w3,
                               __nv_bfloat16* o0, __nv_bfloat16* o1,
                               __nv_bfloat16* o2, __nv_bfloat16* o3) {
    const float* W = (blockIdx.z == 0) ? w0 : (blockIdx.z == 1) ? w1 : (blockIdx.z == 2) ? w2 : w3;
    __nv_bfloat16* O = (blockIdx.z == 0) ? o0 : (blockIdx.z == 1) ? o1 : (blockIdx.z == 2) ? o2 : o3;
    conv_w_body(W, O, TB_D, TB_D);
}
__global__ void conv_win_kernel(const float* __restrict__ w_in, __nv_bfloat16* win3) {
    conv_w_body(w_in, win3, TB_D, TB_F);
}
__global__ void conv_wout_kernel(const float* __restrict__ w_out, __nv_bfloat16* wout3) {
    conv_w_body(w_out, wout3, TB_F, TB_D);
}

// ---------------- srmsnorm -> split-bf16 [hi(D)|lo(D)] -----------------------
__global__ void srmsnorm3_kernel(const float* __restrict__ x, __nv_bfloat16* __restrict__ y) {
    int row = blockIdx.x;
    int tid = threadIdx.x;
    const float* xr = x + (size_t)row * TB_D;
    float4 v = *(const float4*)(xr + tid * 4);
    float ss = v.x*v.x + v.y*v.y + v.z*v.z + v.w*v.w;
    #pragma unroll
    for (int o = 16; o; o >>= 1) ss += __shfl_xor_sync(0xffffffffu, ss, o);
    __shared__ float wred[8];
    __shared__ float s_scale;
    if ((tid & 31) == 0) wred[tid >> 5] = ss;
    __syncthreads();
    if (tid == 0) {
        float tot = 0.f;
        #pragma unroll
        for (int i = 0; i < 8; i++) tot += wred[i];
        s_scale = 32.0f / fmaxf(sqrtf(tot), 1e-12f);
    }
    __syncthreads();
    float sc = s_scale;
    float vals[4] = {v.x * sc, v.y * sc, v.z * sc, v.w * sc};
    __nv_bfloat16 hi[4], lo[4];
    #pragma unroll
    for (int j = 0; j < 4; j++) split_bf16(vals[j], hi[j], lo[j]);
    uint2 h2 = pack4bf(hi[0], hi[1], hi[2], hi[3]);
    uint2 l2 = pack4bf(lo[0], lo[1], lo[2], lo[3]);
    size_t base = (size_t)row * TB_D2 + tid * 4;
    *(uint2*)(y + base)        = h2;
    *(uint2*)(y + base + TB_D) = l2;
}

// ---------------- tcgen05 split-bf16 GEMM, warp-specialized ------------------
// Operands [hi(K)|lo(K)]. Per 64-chunk: load Ahi,Alo,Bhi,Blo (96KB stage, 2
// stages) and issue 3 MMA segments (Ahi.Bhi, Alo.Bhi, Ahi.Blo) reusing smem.
// epi: 0 = fp32, 1 = fp32+res, 2 = gelu->[hi|lo], 3 = Q split, 4 = K split,
//      5 = V TRANSPOSED split
#define ST_A 32768
#define ST_B 65536
#define STAGE2 (ST_A + ST_B)            // 96KB
#define GEMM_SMEM (2 * STAGE2 + 1024)   // 193KB

__device__ __forceinline__ void tc_gemm_body(
    const __nv_bfloat16* __restrict__ A2, const __nv_bfloat16* __restrict__ B2,
    const float* __restrict__ res, void* __restrict__ Cout,
    int N, int K, int m0, int n0, int epi)
{
    int K2 = 2 * K;
#if HAS_TCGEN05
    extern __shared__ char dsm_raw[];
    __shared__ uint32_t s_tmem;
    __shared__ __align__(8) uint64_t s_bars[4]; // full[2], empty[2]
    char* dsp = (char*)(((uintptr_t)dsm_raw + 1023) & ~(uintptr_t)1023);
    uint32_t dsm = smem_u32(dsp);
    int tid = threadIdx.x, wid = tid >> 5, lane = tid & 31;

    if (wid == 0) {
        asm volatile("tcgen05.alloc.cta_group::1.sync.aligned.shared::cta.b32 [%0], %1;"
                     :: "r"(smem_u32((void*)&s_tmem)), "r"(256u) : "memory");
    }
    if (tid == 0) {
        #pragma unroll
        for (int s = 0; s < 2; s++) {
            mbar_init(smem_u32(&s_bars[s]), 128);      // full
            mbar_init(smem_u32(&s_bars[2 + s]), 1);    // empty (commit)
        }
    }
    __syncthreads();
    uint32_t tmem = s_tmem;

    const __nv_bfloat16* Ab = A2 + (size_t)m0 * K2;
    const __nv_bfloat16* Bb = B2 + (size_t)n0 * K2;
    int nch = K >> 6;    // chunks over ORIGINAL K; even (16 or 64)

    if (wid < 4) {
        for (int c = 0; c < nch; c++) {
            int s = c & 1;
            uint32_t sb = dsm + s * STAGE2;
            if (c >= 2)
                mbar_wait(smem_u32(&s_bars[2 + s]), ((c >> 1) - 1) & 1);
            const __nv_bfloat16* ga = Ab + (c << 6);
            const __nv_bfloat16* gb = Bb + (c << 6);
            #pragma unroll
            for (int i = 0; i < 8; i++) {              // A hi: 128 x 128B
                int u = tid + (i << 7);
                int r = u >> 3, q = u & 7;
                cp_async16(sb + SWZ(r * 128 + q * 16), ga + (size_t)r * K2 + q * 8);
            }
            #pragma unroll
            for (int i = 0; i < 8; i++) {              // A lo
                int u = tid + (i << 7);
                int r = u >> 3, q = u & 7;
                cp_async16(sb + 16384 + SWZ(r * 128 + q * 16), ga + (size_t)r * K2 + K + q * 8);
            }
            #pragma unroll
            for (int i = 0; i < 16; i++) {             // B hi: 256 x 128B
                int u = tid + (i << 7);
                int r = u >> 3, q = u & 7;
                cp_async16(sb + 32768 + SWZ(r * 128 + q * 16), gb + (size_t)r * K2 + q * 8);
            }
            #pragma unroll
            for (int i = 0; i < 16; i++) {             // B lo
                int u = tid + (i << 7);
                int r = u >> 3, q = u & 7;
                cp_async16(sb + 65536 + SWZ(r * 128 + q * 16), gb + (size_t)r * K2 + K + q * 8);
            }
            cp_async_arrive(smem_u32(&s_bars[s]));
        }
        uint32_t pe = ((uint32_t)(nch >> 1) - 1u) & 1u;
        #pragma unroll
        for (int s = 0; s < 2; s++)
            mbar_wait(smem_u32(&s_bars[2 + s]), pe);
    } else if (wid == 7) {
        for (int c = 0; c < nch; c++) {
            int s = c & 1;
            uint32_t sb = dsm + s * STAGE2;
            mbar_wait(smem_u32(&s_bars[s]), (c >> 1) & 1);
            if (elect_one()) {
                uint64_t ah  = MK_DESC(sb);
                uint64_t al  = MK_DESC(sb + 16384);
                uint64_t bh0 = MK_DESC(sb + 32768);
                uint64_t bh1 = MK_DESC(sb + 49152);
                uint64_t bl0 = MK_DESC(sb + 65536);
                uint64_t bl1 = MK_DESC(sb + 81920);
                #pragma unroll
                for (int seg = 0; seg < 3; seg++) {
                    uint64_t a  = (seg == 1) ? al : ah;
                    uint64_t b0 = (seg == 2) ? bl0 : bh0;
                    uint64_t b1 = (seg == 2) ? bl1 : bh1;
                    #pragma unroll
                    for (int k = 0; k < 4; k++) {
                        uint32_t en = (c | seg | k) ? 1u : 0u;
                        mma_f16_ss(tmem,       a + 2*k, b0 + 2*k, MMA_IDESC, en);
                        mma_f16_ss(tmem + 128, a + 2*k, b1 + 2*k, MMA_IDESC, en);
                    }
                }
                tc_commit(smem_u32(&s_bars[2 + s]));   // ONE commit per group
            }
        }
    }
    __syncthreads();
    TC_FENCE_AFTER();

    int sub = wid & 3, half = wid >> 2;
    int mrow = m0 + sub * 32 + lane;
    for (int cb = 0; cb < 128; cb += 32) {
        uint32_t dr[32];
        TCGEN05_LD_32X32B_X32(dr, tmem + half * 128 + cb);
        TC_WAIT_LD();
        int n = n0 + half * 128 + cb;
        if (epi == 2) {
            __nv_bfloat16* C = (__nv_bfloat16*)Cout;
            size_t rb = (size_t)mrow * (2 * (size_t)N);
            __nv_bfloat16 hiA[32], loA[32];
            #pragma unroll
            for (int j = 0; j < 32; j++) {
                float f = gelu_tanh(__uint_as_float(dr[j]));
                split_bf16(f, hiA[j], loA[j]);
            }
            uint4* ph = (uint4*)(C + rb + n);
            uint4* pl = (uint4*)(C + rb + (size_t)N + n);
            #pragma unroll
            for (int t2 = 0; t2 < 4; t2++) {
                ph[t2] = ((uint4*)hiA)[t2];
                pl[t2] = ((uint4*)loA)[t2];
            }
        } else if (epi == 3 || epi == 4) {
            __nv_bfloat16* C = (__nv_bfloat16*)Cout;
            int bb = mrow >> 11, tl = mrow & 2047;
            int head = n >> 6, d0 = n & 63;
            __nv_bfloat16 hiA[32], loA[32];
            #pragma unroll
            for (int j = 0; j < 32; j++)
                split_bf16(__uint_as_float(dr[j]), hiA[j], loA[j]);
            __nv_bfloat16* dst = C + (((size_t)(bb * 16 + head)) * 2048 + tl) * 128;
            uint4* ph = (uint4*)(dst + d0);
            uint4* pl = (uint4*)(dst + 64 + d0);
            #pragma unroll
            for (int t2 = 0; t2 < 4; t2++) {
                ph[t2] = ((uint4*)hiA)[t2];
                pl[t2] = ((uint4*)loA)[t2];
            }
        } else if (epi == 5) {
            // V transposed: vt3[b*16+h][128 d-rows (hi 0..63, lo 64..127)][2048]
            __nv_bfloat16* C = (__nv_bfloat16*)Cout;
            int bb = mrow >> 11;
            int head = n >> 6, d0 = n & 63;
            int tl0 = (m0 & 2047) + sub * 32;
            __nv_bfloat16 hiA[32], loA[32];
            #pragma unroll
            for (int j = 0; j < 32; j++)
                split_bf16(__uint_as_float(dr[j]), hiA[j], loA[j]);
            uint16_t* sc  = (uint16_t*)(dsp + (size_t)wid * 4352);
            uint16_t* scl = sc + 1088;
            #pragma unroll
            for (int j = 0; j < 32; j++) {
                sc [lane * 34 + j] = __bfloat16_as_ushort(hiA[j]);
                scl[lane * 34 + j] = __bfloat16_as_ushort(loA[j]);
            }
            __syncwarp();
            uint32_t wh[16], wl[16];
            #pragma unroll
            for (int g = 0; g < 16; g++) {
                wh[g] = (uint32_t)sc [(2*g) * 34 + lane] | ((uint32_t)sc [(2*g+1) * 34 + lane] << 16);
                wl[g] = (uint32_t)scl[(2*g) * 34 + lane] | ((uint32_t)scl[(2*g+1) * 34 + lane] << 16);
            }
            size_t base_hb = (size_t)(bb * 16 + head) * 262144;
            __nv_bfloat16* dh = C + base_hb + (size_t)(d0 + lane) * 2048 + tl0;
            __nv_bfloat16* dl = C + base_hb + (size_t)(64 + d0 + lane) * 2048 + tl0;
            #pragma unroll
            for (int g = 0; g < 4; g++) {
                ((uint4*)dh)[g] = ((uint4*)wh)[g];
                ((uint4*)dl)[g] = ((uint4*)wl)[g];
            }
            __syncwarp();
        } else {
            float* C = (float*)Cout;
            size_t base = (size_t)mrow * N + n;
            #pragma unroll
            for (int j = 0; j < 32; j += 4) {
                float4 v = make_float4(__uint_as_float(dr[j]),   __uint_as_float(dr[j+1]),
                                       __uint_as_float(dr[j+2]), __uint_as_float(dr[j+3]));
                if (epi == 1) {
                    float4 r4 = *(const float4*)(res + base + j);
                    v.x += r4.x; v.y += r4.y; v.z += r4.z; v.w += r4.w;
                }
                *(float4*)(C + base + j) = v;
            }
        }
    }
    __syncthreads();
    if (wid == 0) {
        asm volatile("tcgen05.relinquish_alloc_permit.cta_group::1.sync.aligned;");
        asm volatile("tcgen05.dealloc.cta_group::1.sync.aligned.b32 %0, %1;"
                     :: "r"(tmem), "r"(256u));
    }
#else
    // ---------------- SIMT fallback (non-sm_103a cubin only) -----------------
    int tid = threadIdx.x;
    int n_c = n0 + tid;
    for (int m = 0; m < 128; m++) {
        int mrow = m0 + m;
        const __nv_bfloat16* ar = A2 + (size_t)mrow * K2;
        const __nv_bfloat16* br = B2 + (size_t)n_c * K2;
        float acc = 0.f;
        for (int k = 0; k < K; k++) {
            float ah = __bfloat162float(ar[k]), al = __bfloat162float(ar[K + k]);
            float bh = __bfloat162float(br[k]), bl = __bfloat162float(br[K + k]);
            acc += ah * bh + al * bh + ah * bl;
        }
        if (epi == 2) {
            __nv_bfloat16* C = (__nv_bfloat16*)Cout;
            size_t base = (size_t)mrow * (2 * (size_t)N);
            float f = gelu_tanh(acc);
            __nv_bfloat16 hi, lo; split_bf16(f, hi, lo);
            C[base + n_c] = hi; C[base + N + n_c] = lo;
        } else if (epi == 3 || epi == 4) {
            __nv_bfloat16* C = (__nv_bfloat16*)Cout;
            int bb = mrow >> 11, tl = mrow & 2047;
            int head = n_c >> 6, d = n_c & 63;
            __nv_bfloat16 hi, lo; split_bf16(acc, hi, lo);
            size_t base = (((size_t)(bb * 16 + head)) * 2048 + tl) * 128;
            C[base + d] = hi; C[base + 64 + d] = lo;
        } else if (epi == 5) {
            __nv_bfloat16* C = (__nv_bfloat16*)Cout;
            int bb = mrow >> 11, tl = mrow & 2047;
            int head = n_c >> 6, d = n_c & 63;
            __nv_bfloat16 hi, lo; split_bf16(acc, hi, lo);
            size_t base = (size_t)(bb * 16 + head) * 262144;
            C[base + (size_t)d * 2048 + tl] = hi;
            C[base + (size_t)(64 + d) * 2048 + tl] = lo;
        } else {
            float* C = (float*)Cout;
            size_t base = (size_t)mrow * N;
            if (epi == 1) acc += res[base + n_c];
            C[base + n_c] = acc;
        }
    }
#endif
}

template<int EPI>
__global__ __launch_bounds__(256, 1) void tc_gemm(
    const __nv_bfloat16* __restrict__ A2, const __nv_bfloat16* __restrict__ B2,
    const float* __restrict__ res, void* __restrict__ C, int N, int K)
{
    tc_gemm_body(A2, B2, res, C, N, K, blockIdx.y * 128, blockIdx.x * 256, EPI);
}

__global__ __launch_bounds__(256, 1) void tc_gemm_qkv(
    const __nv_bfloat16* __restrict__ A2,
    const __nv_bfloat16* __restrict__ b0, const __nv_bfloat16* __restrict__ b1,
    const __nv_bfloat16* __restrict__ b2,
    __nv_bfloat16* __restrict__ c0, __nv_bfloat16* __restrict__ c1,
    __nv_bfloat16* __restrict__ c2)
{
    const __nv_bfloat16* B2 = (blockIdx.z == 0) ? b0 : ((blockIdx.z == 1) ? b1 : b2);
    __nv_bfloat16* C = (blockIdx.z == 0) ? c0 : ((blockIdx.z == 1) ? c1 : c2);
    tc_gemm_body(A2, B2, nullptr, C, TB_D, TB_D,
                 blockIdx.y * 128, blockIdx.x * 256, 3 + (int)blockIdx.z);
}

// ---------------- tcgen05 causal flash attention (unchanged from R11 win) -----
#define ATT_DSMEM (192 * 1024 + 1024)

__global__ __launch_bounds__(256, 1) void tc_attn(
    const __nv_bfloat16* __restrict__ q3, const __nv_bfloat16* __restrict__ k3,
    const __nv_bfloat16* __restrict__ vt3, __nv_bfloat16* __restrict__ att3)
{
    int qtile = 15 - (int)blockIdx.x;          // heavy tiles first
    int h = blockIdx.y, b = blockIdx.z;
    int ntiles = qtile + 1;
    int q0 = qtile * 128;
    size_t hb = (size_t)b * 16 + h;
    const __nv_bfloat16* qh = q3 + hb * (size_t)2048 * 128;
    const __nv_bfloat16* kh = k3 + hb * (size_t)2048 * 128;
    const __nv_bfloat16* vh = vt3 + hb * (size_t)262144;
#if HAS_TCGEN05
    extern __shared__ char dsm_raw[];
    __shared__ uint32_t s_tmem;
    __shared__ __align__(8) uint64_t bars[7]; // bK0 bK1 bV bP bO bSK0 bSK1
    char* dsmp = (char*)(((uintptr_t)dsm_raw + 1023) & ~(uintptr_t)1023);
    uint32_t dsm = smem_u32(dsmp);
    uint32_t Q0c = dsm, Q1c = dsm + 16384;
    uint32_t Kst = dsm + 32768;
    uint32_t Vt  = dsm + 98304;
    uint32_t Pb  = dsm + 131072;
    uint32_t bK[2]  = { smem_u32(&bars[0]), smem_u32(&bars[1]) };
    uint32_t bV = smem_u32(&bars[2]), bP = smem_u32(&bars[3]);
    uint32_t bO = smem_u32(&bars[4]);
    uint32_t bSK[2] = { smem_u32(&bars[5]), smem_u32(&bars[6]) };
    int tid = threadIdx.x, wid = tid >> 5, lane = tid & 31;

    if (wid == 0) {
        asm volatile("tcgen05.alloc.cta_group::1.sync.aligned.shared::cta.b32 [%0], %1;"
                     :: "r"(smem_u32((void*)&s_tmem)), "r"(256u) : "memory");
    }
    if (tid == 0) {
        mbar_init(bK[0], 64); mbar_init(bK[1], 64);
        mbar_init(bV, 32); mbar_init(bP, 128); mbar_init(bO, 1);
        mbar_init(bSK[0], 1); mbar_init(bSK[1], 1);
    }
    __syncthreads();
    uint32_t tmem = s_tmem;

    // Q preload (warps 4-7)
    if (wid >= 4) {
        int t4 = tid - 128;
        #pragma unroll
        for (int i = 0; i < 8; i++) {
            int u = t4 + 128 * i, r = u >> 3, q = u & 7;
            cp_async16(Q0c + SWZ(r * 128 + q * 16), qh + (size_t)(q0 + r) * 128 + q * 8);
        }
        #pragma unroll
        for (int i = 0; i < 8; i++) {
            int u = t4 + 128 * i, r = u >> 3, q = u & 7;
            cp_async16(Q1c + SWZ(r * 128 + q * 16), qh + (size_t)(q0 + r) * 128 + 64 + q * 8);
        }
        asm volatile("cp.async.wait_all;" ::: "memory");
    }
    __syncthreads();

    if (wid == 4 || wid == 5) {
        int t2 = tid - 128;
        for (int t = 0; t < ntiles; t++) {
            if (t >= 2) mbar_wait(bSK[t & 1], ((t >> 1) - 1) & 1);
            uint32_t Ks = Kst + (t & 1) * 32768;
            int k0 = t * 128;
            #pragma unroll
            for (int i = 0; i < 16; i++) {
                int u = t2 + 64 * i, r = u >> 3, q = u & 7;
                cp_async16(Ks + SWZ(r * 128 + q * 16), kh + (size_t)(k0 + r) * 128 + q * 8);
            }
            #pragma unroll
            for (int i = 0; i < 16; i++) {
                int u = t2 + 64 * i, r = u >> 3, q = u & 7;
                cp_async16(Ks + 16384 + SWZ(r * 128 + q * 16), kh + (size_t)(k0 + r) * 128 + 64 + q * 8);
            }
            cp_async_arrive(bK[t & 1]);
        }
    } else if (wid == 6) {
        int t3 = tid - 192;
        for (int t = 0; t < ntiles; t++) {
            if (t >= 1) mbar_wait(bO, (t - 1) & 1);
            int k0 = t * 128;
            #pragma unroll
            for (int p = 0; p < 2; p++)
                #pragma unroll
                for (int cc = 0; cc < 2; cc++) {
                    uint32_t cb = Vt + (p * 2 + cc) * 8192;
                    #pragma unroll
                    for (int i = 0; i < 16; i++) {
                        int u = t3 + 32 * i, r = u >> 3, q = u & 7;
                        cp_async16(cb + SWZ(r * 128 + q * 16),
                                   vh + (size_t)(p * 64 + r) * 2048 + k0 + cc * 64 + q * 8);
                    }
                }
            cp_async_arrive(bV);
        }
    } else if (wid == 7) {
        for (int t = 0; t < ntiles; t++) {
            mbar_wait(bK[t & 1], (t >> 1) & 1);
            if (elect_one()) {
                uint32_t Ks = Kst + (t & 1) * 32768;
                uint64_t qd[3] = { MK_DESC(Q0c), MK_DESC(Q1c), MK_DESC(Q0c) };
                uint64_t kd[3] = { MK_DESC(Ks), MK_DESC(Ks), MK_DESC(Ks + 16384) };
                #pragma unroll
                for (int seg = 0; seg < 3; seg++)
                    #pragma unroll
                    for (int s = 0; s < 4; s++)
                        mma_f16_ss(tmem, qd[seg] + 2 * s, kd[seg] + 2 * s,
                                   MMA_IDESC, (seg | s) ? 1u : 0u);
                tc_commit(bSK[t & 1]);
            }
            mbar_wait(bV, t & 1);
            mbar_wait(bP, t & 1);
            if (elect_one()) {
                uint64_t pa[3][2] = {
                    { MK_DESC(Pb),         MK_DESC(Pb + 16384) },
                    { MK_DESC(Pb + 32768), MK_DESC(Pb + 49152) },
                    { MK_DESC(Pb),         MK_DESC(Pb + 16384) } };
                const int vpart[3] = { 0, 0, 1 };
                #pragma unroll
                for (int seg = 0; seg < 3; seg++)
                    #pragma unroll
                    for (int s = 0; s < 8; s++) {
                        int cc = s >> 2;
                        mma_f16_ss(tmem + 128,
                                   pa[seg][cc] + 2 * (s & 3),
                                   MK_DESC(Vt + (vpart[seg] * 2 + cc) * 8192) + 2 * (s & 3),
                                   IDESC_PV, (seg | s) ? 1u : 0u);
                    }
                tc_commit(bO);
            }
        }
    } else {
        int rloc = wid * 32 + lane;
        int rg = q0 + rloc;
        float m = -1e30f, l = 0.f, alpha_prev = 0.f;
        float O[64];
        #pragma unroll
        for (int j = 0; j < 64; j++) O[j] = 0.f;

        for (int t = 0; t < ntiles; t++) {
            mbar_wait(bSK[t & 1], (t >> 1) & 1);
            TC_FENCE_AFTER();
            int k0 = t * 128;
            int lim = rg - k0;
            float mt = -1e30f;
            #pragma unroll
            for (int cb = 0; cb < 4; cb++) {
                uint32_t dr[32];
                TCGEN05_LD_32X32B_X32(dr, tmem + cb * 32);
                TC_WAIT_LD();
                #pragma unroll
                for (int j = 0; j < 32; j++) {
                    int c = cb * 32 + j;
                    float v = (c <= lim) ? __uint_as_float(dr[j]) * 0.125f : -1e30f;
                    mt = fmaxf(mt, v);
                }
            }
            float mn = fmaxf(m, mt);
            float al = __expf(m - mn);
            if (t > 0) {
                mbar_wait(bO, (t - 1) & 1);
                TC_FENCE_AFTER();
                uint32_t du[32];
                TCGEN05_LD_32X32B_X32(du, tmem + 128);
                TC_WAIT_LD();
                #pragma unroll
                for (int j = 0; j < 32; j++)
                    O[j] = O[j] * alpha_prev + __uint_as_float(du[j]);
                TCGEN05_LD_32X32B_X32(du, tmem + 160);
                TC_WAIT_LD();
                #pragma unroll
                for (int j = 0; j < 32; j++)
                    O[32 + j] = O[32 + j] * alpha_prev + __uint_as_float(du[j]);
            }
            float ps = 0.f;
            #pragma unroll
            for (int cb = 0; cb < 4; cb++) {
                uint32_t dr[32];
                TCGEN05_LD_32X32B_X32(dr, tmem + cb * 32);
                TC_WAIT_LD();
                #pragma unroll
                for (int j = 0; j < 32; j += 4) {
                    int c = cb * 32 + j;
                    float v0 = (c     <= lim) ? __uint_as_float(dr[j])     * 0.125f : -1e30f;
                    float v1 = (c + 1 <= lim) ? __uint_as_float(dr[j + 1]) * 0.125f : -1e30f;
                    float v2 = (c + 2 <= lim) ? __uint_as_float(dr[j + 2]) * 0.125f : -1e30f;
                    float v3 = (c + 3 <= lim) ? __uint_as_float(dr[j + 3]) * 0.125f : -1e30f;
                    float p0 = __expf(v0 - mn), p1 = __expf(v1 - mn);
                    float p2 = __expf(v2 - mn), p3 = __expf(v3 - mn);
                    ps += (p0 + p1) + (p2 + p3);
                    __nv_bfloat16 h0,l0,h1,l1,h2,l2,h3,l3;
                    split_bf16(p0, h0, l0); split_bf16(p1, h1, l1);
                    split_bf16(p2, h2, l2); split_bf16(p3, h3, l3);
                    uint2 hv = pack4bf(h0, h1, h2, h3);
                    uint2 lv = pack4bf(l0, l1, l2, l3);
                    int subo = (c >> 6) * 16384;
                    uint32_t so = SWZ(rloc * 128 + (c & 63) * 2);
                    *(uint2*)(dsmp + 131072 + subo + so) = hv;   // Phi
                    *(uint2*)(dsmp + 163840 + subo + so) = lv;   // Plo
                }
            }
            l = l * al + ps;
            alpha_prev = al;
            m = mn;
            FENCE_ASYNC();
            mbar_arrive(bP);
        }
        mbar_wait(bO, (ntiles - 1) & 1);
        TC_FENCE_AFTER();
        {
            uint32_t du[32];
            TCGEN05_LD_32X32B_X32(du, tmem + 128);
            TC_WAIT_LD();
            #pragma unroll
            for (int j = 0; j < 32; j++)
                O[j] = O[j] * alpha_prev + __uint_as_float(du[j]);
            TCGEN05_LD_32X32B_X32(du, tmem + 160);
            TC_WAIT_LD();
            #pragma unroll
            for (int j = 0; j < 32; j++)
                O[32 + j] = O[32 + j] * alpha_prev + __uint_as_float(du[j]);
        }
        float inv = 1.0f / l;
        __nv_bfloat16 hi[64], lo[64];
        #pragma unroll
        for (int j = 0; j < 64; j++) split_bf16(O[j] * inv, hi[j], lo[j]);
        size_t rb = ((size_t)b * 2048 + rg) * TB_D2 + h * 64;
        uint4* ph = (uint4*)(att3 + rb);
        uint4* pl = (uint4*)(att3 + rb + TB_D);
        #pragma unroll
        for (int i = 0; i < 8; i++) {
            ph[i] = ((uint4*)hi)[i];
            pl[i] = ((uint4*)lo)[i];
        }
    }
    __syncthreads();
    if (wid == 0) {
        asm volatile("tcgen05.relinquish_alloc_permit.cta_group::1.sync.aligned;");
        asm volatile("tcgen05.dealloc.cta_group::1.sync.aligned.b32 %0, %1;"
                     :: "r"(tmem), "r"(256u));
    }
#else
    // ---------------- SIMT fallback (non-sm_103a cubin only) ------------------
    int tid = threadIdx.x;
    if (tid < 128) {
        int rg = q0 + tid;
        float q[64];
        #pragma unroll
        for (int d = 0; d < 64; d++)
            q[d] = __bfloat162float(qh[(size_t)rg * 128 + d]) +
                   __bfloat162float(qh[(size_t)rg * 128 + 64 + d]);
        float m = -1e30f;
        for (int k = 0; k <= rg; k++) {
            float s = 0.f;
            for (int d = 0; d < 64; d++)
                s += q[d] * (__bfloat162float(kh[(size_t)k * 128 + d]) +
                             __bfloat162float(kh[(size_t)k * 128 + 64 + d]));
            m = fmaxf(m, s * 0.125f);
        }
        float l = 0.f, O[64];
        for (int d = 0; d < 64; d++) O[d] = 0.f;
        for (int k = 0; k <= rg; k++) {
            float s = 0.f;
            for (int d = 0; d < 64; d++)
                s += q[d] * (__bfloat162float(kh[(size_t)k * 128 + d]) +
                             __bfloat162float(kh[(size_t)k * 128 + 64 + d]));
            float p = expf(s * 0.125f - m);
            l += p;
            for (int d = 0; d < 64; d++)
                O[d] += p * (__bfloat162float(vh[(size_t)d * 2048 + k]) +
                             __bfloat162float(vh[(size_t)(64 + d) * 2048 + k]));
        }
        float inv = 1.0f / l;
        size_t rb = ((size_t)b * 2048 + rg) * TB_D2 + h * 64;
        for (int d = 0; d < 64; d++) {
            __nv_bfloat16 hi, lo; split_bf16(O[d] * inv, hi, lo);
            att3[rb + d] = hi; att3[rb + TB_D + d] = lo;
        }
    }
#endif
}

// ---------------- launch ------------------------------------------------------
extern "C" void kernel_launch(void* const* d_in, const int* in_sizes, int n_in,
                              void* d_out, int out_size) {
    const float* x     = (const float*)d_in[0];
    const float* wq    = (const float*)d_in[1];
    const float* wk    = (const float*)d_in[2];
    const float* wv    = (const float*)d_in[3];
    const float* wo    = (const float*)d_in[4];
    const float* w_in  = (const float*)d_in[5];
    const float* w_out = (const float*)d_in[6];
    float* out = (float*)d_out;
    (void)in_sizes; (void)n_in; (void)out_size;

    __nv_bfloat16 *xn3, *att3, *ff3, *q3, *k3, *vt3;
    __nv_bfloat16 *wq3, *wk3, *wv3, *wo3, *win3, *wout3;
    float *h;
    cudaGetSymbolAddress((void**)&xn3,  g_xn3);
    cudaGetSymbolAddress((void**)&att3, g_att3);
    cudaGetSymbolAddress((void**)&ff3,  g_ff3);
    cudaGetSymbolAddress((void**)&q3,   g_q3);
    cudaGetSymbolAddress((void**)&k3,   g_k3);
    cudaGetSymbolAddress((void**)&vt3,  g_vt3);
    cudaGetSymbolAddress((void**)&h,    g_h);
    cudaGetSymbolAddress((void**)&wq3,  g_wq3);
    cudaGetSymbolAddress((void**)&wk3,  g_wk3);
    cudaGetSymbolAddress((void**)&wv3,  g_wv3);
    cudaGetSymbolAddress((void**)&wo3,  g_wo3);
    cudaGetSymbolAddress((void**)&win3, g_win3);
    cudaGetSymbolAddress((void**)&wout3, g_wout3);

    cudaFuncSetAttribute(tc_attn,     cudaFuncAttributeMaxDynamicSharedMemorySize, ATT_DSMEM);
    cudaFuncSetAttribute(tc_gemm_qkv, cudaFuncAttributeMaxDynamicSharedMemorySize, GEMM_SMEM);
    cudaFuncSetAttribute(tc_gemm<1>,  cudaFuncAttributeMaxDynamicSharedMemorySize, GEMM_SMEM);
    cudaFuncSetAttribute(tc_gemm<2>,  cudaFuncAttributeMaxDynamicSharedMemorySize, GEMM_SMEM);

    dim3 cwb(32, 8);
    conv_w4_kernel<<<dim3(32, 32, 4), cwb>>>(wq, wk, wv, wo, wq3, wk3, wv3, wo3);   // 1
    conv_win_kernel<<<dim3(128, 32), cwb>>>(w_in, win3);                            // 2
    conv_wout_kernel<<<dim3(32, 128), cwb>>>(w_out, wout3);                         // 3
    srmsnorm3_kernel<<<TB_T, 256>>>(x, xn3);                                        // 4
    tc_gemm_qkv<<<dim3(TB_D / 256, TB_T / 128, 3), 256, GEMM_SMEM>>>(               // 5
        xn3, wq3, wk3, wv3, q3, k3, vt3);
    tc_attn<<<dim3(16, TB_H, TB_B), 256, ATT_DSMEM>>>(q3, k3, vt3, att3);           // 6
    tc_gemm<1><<<dim3(TB_D / 256, TB_T / 128), 256, GEMM_SMEM>>>(                   // 7
        att3, wo3, x, h, TB_D, TB_D);
    srmsnorm3_kernel<<<TB_T, 256>>>(h, xn3);                                        // 8
    tc_gemm<2><<<dim3(TB_F / 256, TB_T / 128), 256, GEMM_SMEM>>>(                   // 9
        xn3, win3, nullptr, ff3, TB_F, TB_D);
    tc_gemm<1><<<dim3(TB_D / 256, TB_T / 128), 256, GEMM_SMEM>>>(                   // 10
        ff3, wout3, h, out, TB_D, TB_F);
}

// round 13
// speedup vs baseline: 5.6809x; 1.1016x over previous
#include <cuda_runtime.h>
#include <cuda_bf16.h>
#include <math.h>
#include <stdint.h>

// Problem dims (fixed by the reference)
#define TB_B 2
#define TB_S 2048
#define TB_D 1024
#define TB_F 4096
#define TB_H 16
#define TB_HD 64
#define TB_T (TB_B * TB_S)   // 4096 tokens
#define TB_D2 (2 * TB_D)     // 2048 ([hi|lo] split layout)
#define TB_F2 (2 * TB_F)     // 8192

#if defined(__CUDA_ARCH_FEAT_SM103_ALL) || defined(__CUDA_ARCH_FEAT_SM100_ALL)
#define HAS_TCGEN05 1
#else
#define HAS_TCGEN05 0
#endif

// ---------------- scratch ----------------------------------------------------
// 2x split layout: rows = [hi(K) | lo(K)] for BOTH operands.
// GEMM computes Ahi.Bhi + Alo.Bhi + Ahi.Blo via 3 MMA segments reusing smem.
__device__ __nv_bfloat16 g_xn3 [(size_t)TB_T * TB_D2];
__device__ __nv_bfloat16 g_att3[(size_t)TB_T * TB_D2];
__device__ __nv_bfloat16 g_ff3 [(size_t)TB_T * TB_F2];
__device__ float g_h [(size_t)TB_T * TB_D];
// attention operands (per (b,h)):
//   q3,k3: [b][h][t][128] = [hi(64)|lo(64)] over head dims (K-major rows)
//   vt3:   [b][h][128 d-rows][2048 tokens]; d-rows 0..63 = hi, 64..127 = lo
__device__ __nv_bfloat16 g_q3 [(size_t)TB_T * TB_H * 128];
__device__ __nv_bfloat16 g_k3 [(size_t)TB_T * TB_H * 128];
__device__ __nv_bfloat16 g_vt3[(size_t)TB_B * TB_H * 128 * TB_S];
__device__ __nv_bfloat16 g_wq3 [(size_t)TB_D * TB_D2];
__device__ __nv_bfloat16 g_wk3 [(size_t)TB_D * TB_D2];
__device__ __nv_bfloat16 g_wv3 [(size_t)TB_D * TB_D2];
__device__ __nv_bfloat16 g_wo3 [(size_t)TB_D * TB_D2];
__device__ __nv_bfloat16 g_win3[(size_t)TB_F * TB_D2];
__device__ __nv_bfloat16 g_wout3[(size_t)TB_D * TB_F2];

// ---------------- helpers ----------------------------------------------------
__device__ __forceinline__ uint32_t smem_u32(const void* p) {
    uint32_t a;
    asm("{ .reg .u64 t; cvta.to.shared.u64 t, %1; cvt.u32.u64 %0, t; }" : "=r"(a) : "l"(p));
    return a;
}
__device__ __forceinline__ void split_bf16(float x, __nv_bfloat16& hi, __nv_bfloat16& lo) {
    hi = __float2bfloat16(x);
    lo = __float2bfloat16(x - __bfloat162float(hi));
}
__device__ __forceinline__ float gelu_tanh(float v) {
    const float c = 0.79788456080286535588f;
    float t = c * (v + 0.044715f * v * v * v);
    return 0.5f * v * (1.0f + tanhf(t));
}
__device__ __forceinline__ uint2 pack4bf(__nv_bfloat16 a, __nv_bfloat16 b,
                                         __nv_bfloat16 c, __nv_bfloat16 d) {
    uint2 r;
    r.x = (uint32_t)__bfloat16_as_ushort(a) | ((uint32_t)__bfloat16_as_ushort(b) << 16);
    r.y = (uint32_t)__bfloat16_as_ushort(c) | ((uint32_t)__bfloat16_as_ushort(d) << 16);
    return r;
}

#if HAS_TCGEN05
__device__ __forceinline__ uint32_t elect_one() {
    uint32_t p;
    asm volatile("{ .reg .pred p; elect.sync _|p, 0xFFFFFFFF; selp.b32 %0, 1, 0, p; }" : "=r"(p));
    return p;
}
__device__ __forceinline__ void mbar_init(uint32_t a, uint32_t cnt) {
    asm volatile("mbarrier.init.shared.b64 [%0], %1;" :: "r"(a), "r"(cnt) : "memory");
}
__device__ __forceinline__ void mbar_arrive(uint32_t a) {
    asm volatile("mbarrier.arrive.shared.b64 _, [%0];" :: "r"(a) : "memory");
}
__device__ __forceinline__ void mbar_wait(uint32_t a, uint32_t parity) {
    asm volatile(
        "{\n\t.reg .pred P;\n\t"
        "LW%=:\n\t"
        "mbarrier.try_wait.parity.acquire.cta.shared::cta.b64 P, [%0], %1, 0x989680;\n\t"
        "@P bra LD%=;\n\t"
        "bra LW%=;\n\t"
        "LD%=:\n\t}"
        :: "r"(a), "r"(parity) : "memory");
}
__device__ __forceinline__ void cp_async16(uint32_t dst, const void* src) {
    asm volatile("cp.async.cg.shared.global [%0], [%1], 16;" :: "r"(dst), "l"(src) : "memory");
}
__device__ __forceinline__ void cp_async_arrive(uint32_t mbar) {
    asm volatile("cp.async.mbarrier.arrive.noinc.shared::cta.b64 [%0];" :: "r"(mbar) : "memory");
}
__device__ __forceinline__ void mma_f16_ss(uint32_t d, uint64_t ad, uint64_t bd,
                                           uint32_t idesc, uint32_t en) {
    asm volatile(
        "{\n\t.reg .pred p;\n\tsetp.ne.u32 p, %4, 0;\n\t"
        "tcgen05.mma.cta_group::1.kind::f16 [%0], %1, %2, %3, {%5, %5, %5, %5}, p;\n\t}"
        :: "r"(d), "l"(ad), "l"(bd), "r"(idesc), "r"(en), "r"(0u) : "memory");
}
__device__ __forceinline__ void tc_commit(uint32_t mbar) {
    asm volatile(
        "tcgen05.commit.cta_group::1.mbarrier::arrive::one.shared::cluster.b64 [%0];"
        :: "r"(mbar) : "memory");
}
#define TC_FENCE_AFTER()  asm volatile("tcgen05.fence::after_thread_sync;" ::: "memory")
#define TC_WAIT_LD()      asm volatile("tcgen05.wait::ld.sync.aligned;" ::: "memory")
#define FENCE_ASYNC()     asm volatile("fence.proxy.async.shared::cta;" ::: "memory")
#define TCGEN05_LD_32X32B_X32(r, tmem_addr) \
    asm volatile( \
        "tcgen05.ld.sync.aligned.32x32b.x32.b32 " \
        "{%0, %1, %2, %3, %4, %5, %6, %7, " \
        " %8, %9, %10, %11, %12, %13, %14, %15, " \
        " %16, %17, %18, %19, %20, %21, %22, %23, " \
        " %24, %25, %26, %27, %28, %29, %30, %31}, [%32];" \
        : "=r"((r)[0]),  "=r"((r)[1]),  "=r"((r)[2]),  "=r"((r)[3]), \
          "=r"((r)[4]),  "=r"((r)[5]),  "=r"((r)[6]),  "=r"((r)[7]), \
          "=r"((r)[8]),  "=r"((r)[9]),  "=r"((r)[10]), "=r"((r)[11]), \
          "=r"((r)[12]), "=r"((r)[13]), "=r"((r)[14]), "=r"((r)[15]), \
          "=r"((r)[16]), "=r"((r)[17]), "=r"((r)[18]), "=r"((r)[19]), \
          "=r"((r)[20]), "=r"((r)[21]), "=r"((r)[22]), "=r"((r)[23]), \
          "=r"((r)[24]), "=r"((r)[25]), "=r"((r)[26]), "=r"((r)[27]), \
          "=r"((r)[28]), "=r"((r)[29]), "=r"((r)[30]), "=r"((r)[31]) \
        : "r"(tmem_addr))
#endif // HAS_TCGEN05

#define SWZ(o) ((o) ^ (((o) >> 3) & 0x70))
#define SMEM_DESC_BASE ((uint64_t(2) << 61) | (uint64_t(1) << 46) | (uint64_t(64) << 32) | (uint64_t(1) << 16))
#define MK_DESC(addr) (SMEM_DESC_BASE | ((uint64_t)((addr) >> 4) & 0x3FFF))
// idescs: F32 accum, A=BF16, B=BF16, M=128; N=128 (QK/GEMM) / N=64 (PV), K-major
#define MMA_IDESC   0x8200490u
#define IDESC_PV    0x8100490u

// ---------------- weight convert+transpose: W[K][N] -> o[N][2K] [hi|lo] ------
__device__ __forceinline__ void conv_w_body(const float* __restrict__ W,
                                            __nv_bfloat16* __restrict__ o, int K, int N) {
    __shared__ float t[32][33];
    int n0 = blockIdx.x * 32, k0 = blockIdx.y * 32;
    if (n0 >= N || k0 >= K) return;
    int tx = threadIdx.x, ty = threadIdx.y; // 32 x 8
    #pragma unroll
    for (int i = 0; i < 4; i++)
        t[ty + 8 * i][tx] = W[(size_t)(k0 + ty + 8 * i) * N + n0 + tx];
    __syncthreads();
    size_t K2 = 2 * (size_t)K;
    #pragma unroll
    for (int i = 0; i < 4; i++) {
        int nn = ty + 8 * i, kk = tx;
        float x = t[kk][nn];
        __nv_bfloat16 hi, lo; split_bf16(x, hi, lo);
        size_t base = (size_t)(n0 + nn) * K2 + (size_t)(k0 + kk);
        o[base] = hi; o[base + K] = lo;
    }
}
__global__ void conv_w4_kernel(const float* __restrict__ w0, const float* __restrict__ w1,
                               const float* __restrict__ w2, const float* __restrict__ w3,
                               __nv_bfloat16* o0, __nv_bfloat16* o1,
                               __nv_bfloat16* o2, __nv_bfloat16* o3) {
    const float* W = (blockIdx.z == 0) ? w0 : (blockIdx.z == 1) ? w1 : (blockIdx.z == 2) ? w2 : w3;
    __nv_bfloat16* O = (blockIdx.z == 0) ? o0 : (blockIdx.z == 1) ? o1 : (blockIdx.z == 2) ? o2 : o3;
    conv_w_body(W, O, TB_D, TB_D);
}
__global__ void conv_win_kernel(const float* __restrict__ w_in, __nv_bfloat16* win3) {
    conv_w_body(w_in, win3, TB_D, TB_F);
}
__global__ void conv_wout_kernel(const float* __restrict__ w_out, __nv_bfloat16* wout3) {
    conv_w_body(w_out, wout3, TB_F, TB_D);
}

// ---------------- srmsnorm -> split-bf16 [hi(D)|lo(D)] -----------------------
__global__ void srmsnorm3_kernel(const float* __restrict__ x, __nv_bfloat16* __restrict__ y) {
    int row = blockIdx.x;
    int tid = threadIdx.x;
    const float* xr = x + (size_t)row * TB_D;
    float4 v = *(const float4*)(xr + tid * 4);
    float ss = v.x*v.x + v.y*v.y + v.z*v.z + v.w*v.w;
    #pragma unroll
    for (int o = 16; o; o >>= 1) ss += __shfl_xor_sync(0xffffffffu, ss, o);
    __shared__ float wred[8];
    __shared__ float s_scale;
    if ((tid & 31) == 0) wred[tid >> 5] = ss;
    __syncthreads();
    if (tid == 0) {
        float tot = 0.f;
        #pragma unroll
        for (int i = 0; i < 8; i++) tot += wred[i];
        s_scale = 32.0f / fmaxf(sqrtf(tot), 1e-12f);
    }
    __syncthreads();
    float sc = s_scale;
    float vals[4] = {v.x * sc, v.y * sc, v.z * sc, v.w * sc};
    __nv_bfloat16 hi[4], lo[4];
    #pragma unroll
    for (int j = 0; j < 4; j++) split_bf16(vals[j], hi[j], lo[j]);
    uint2 h2 = pack4bf(hi[0], hi[1], hi[2], hi[3]);
    uint2 l2 = pack4bf(lo[0], lo[1], lo[2], lo[3]);
    size_t base = (size_t)row * TB_D2 + tid * 4;
    *(uint2*)(y + base)        = h2;
    *(uint2*)(y + base + TB_D) = l2;
}

// ---------------- tcgen05 split-bf16 GEMM (unchanged from R12 win) -----------
#define ST_A 32768
#define ST_B 65536
#define STAGE2 (ST_A + ST_B)            // 96KB
#define GEMM_SMEM (2 * STAGE2 + 1024)   // 193KB

__device__ __forceinline__ void tc_gemm_body(
    const __nv_bfloat16* __restrict__ A2, const __nv_bfloat16* __restrict__ B2,
    const float* __restrict__ res, void* __restrict__ Cout,
    int N, int K, int m0, int n0, int epi)
{
    int K2 = 2 * K;
#if HAS_TCGEN05
    extern __shared__ char dsm_raw[];
    __shared__ uint32_t s_tmem;
    __shared__ __align__(8) uint64_t s_bars[4]; // full[2], empty[2]
    char* dsp = (char*)(((uintptr_t)dsm_raw + 1023) & ~(uintptr_t)1023);
    uint32_t dsm = smem_u32(dsp);
    int tid = threadIdx.x, wid = tid >> 5, lane = tid & 31;

    if (wid == 0) {
        asm volatile("tcgen05.alloc.cta_group::1.sync.aligned.shared::cta.b32 [%0], %1;"
                     :: "r"(smem_u32((void*)&s_tmem)), "r"(256u) : "memory");
    }
    if (tid == 0) {
        #pragma unroll
        for (int s = 0; s < 2; s++) {
            mbar_init(smem_u32(&s_bars[s]), 128);      // full
            mbar_init(smem_u32(&s_bars[2 + s]), 1);    // empty (commit)
        }
    }
    __syncthreads();
    uint32_t tmem = s_tmem;

    const __nv_bfloat16* Ab = A2 + (size_t)m0 * K2;
    const __nv_bfloat16* Bb = B2 + (size_t)n0 * K2;
    int nch = K >> 6;    // chunks over ORIGINAL K; even (16 or 64)

    if (wid < 4) {
        for (int c = 0; c < nch; c++) {
            int s = c & 1;
            uint32_t sb = dsm + s * STAGE2;
            if (c >= 2)
                mbar_wait(smem_u32(&s_bars[2 + s]), ((c >> 1) - 1) & 1);
            const __nv_bfloat16* ga = Ab + (c << 6);
            const __nv_bfloat16* gb = Bb + (c << 6);
            #pragma unroll
            for (int i = 0; i < 8; i++) {              // A hi: 128 x 128B
                int u = tid + (i << 7);
                int r = u >> 3, q = u & 7;
                cp_async16(sb + SWZ(r * 128 + q * 16), ga + (size_t)r * K2 + q * 8);
            }
            #pragma unroll
            for (int i = 0; i < 8; i++) {              // A lo
                int u = tid + (i << 7);
                int r = u >> 3, q = u & 7;
                cp_async16(sb + 16384 + SWZ(r * 128 + q * 16), ga + (size_t)r * K2 + K + q * 8);
            }
            #pragma unroll
            for (int i = 0; i < 16; i++) {             // B hi: 256 x 128B
                int u = tid + (i << 7);
                int r = u >> 3, q = u & 7;
                cp_async16(sb + 32768 + SWZ(r * 128 + q * 16), gb + (size_t)r * K2 + q * 8);
            }
            #pragma unroll
            for (int i = 0; i < 16; i++) {             // B lo
                int u = tid + (i << 7);
                int r = u >> 3, q = u & 7;
                cp_async16(sb + 65536 + SWZ(r * 128 + q * 16), gb + (size_t)r * K2 + K + q * 8);
            }
            cp_async_arrive(smem_u32(&s_bars[s]));
        }
        uint32_t pe = ((uint32_t)(nch >> 1) - 1u) & 1u;
        #pragma unroll
        for (int s = 0; s < 2; s++)
            mbar_wait(smem_u32(&s_bars[2 + s]), pe);
    } else if (wid == 7) {
        for (int c = 0; c < nch; c++) {
            int s = c & 1;
            uint32_t sb = dsm + s * STAGE2;
            mbar_wait(smem_u32(&s_bars[s]), (c >> 1) & 1);
            if (elect_one()) {
                uint64_t ah  = MK_DESC(sb);
                uint64_t al  = MK_DESC(sb + 16384);
                uint64_t bh0 = MK_DESC(sb + 32768);
                uint64_t bh1 = MK_DESC(sb + 49152);
                uint64_t bl0 = MK_DESC(sb + 65536);
                uint64_t bl1 = MK_DESC(sb + 81920);
                #pragma unroll
                for (int seg = 0; seg < 3; seg++) {
                    uint64_t a  = (seg == 1) ? al : ah;
                    uint64_t b0 = (seg == 2) ? bl0 : bh0;
                    uint64_t b1 = (seg == 2) ? bl1 : bh1;
                    #pragma unroll
                    for (int k = 0; k < 4; k++) {
                        uint32_t en = (c | seg | k) ? 1u : 0u;
                        mma_f16_ss(tmem,       a + 2*k, b0 + 2*k, MMA_IDESC, en);
                        mma_f16_ss(tmem + 128, a + 2*k, b1 + 2*k, MMA_IDESC, en);
                    }
                }
                tc_commit(smem_u32(&s_bars[2 + s]));   // ONE commit per group
            }
        }
    }
    __syncthreads();
    TC_FENCE_AFTER();

    int sub = wid & 3, half = wid >> 2;
    int mrow = m0 + sub * 32 + lane;
    for (int cb = 0; cb < 128; cb += 32) {
        uint32_t dr[32];
        TCGEN05_LD_32X32B_X32(dr, tmem + half * 128 + cb);
        TC_WAIT_LD();
        int n = n0 + half * 128 + cb;
        if (epi == 2) {
            __nv_bfloat16* C = (__nv_bfloat16*)Cout;
            size_t rb = (size_t)mrow * (2 * (size_t)N);
            __nv_bfloat16 hiA[32], loA[32];
            #pragma unroll
            for (int j = 0; j < 32; j++) {
                float f = gelu_tanh(__uint_as_float(dr[j]));
                split_bf16(f, hiA[j], loA[j]);
            }
            uint4* ph = (uint4*)(C + rb + n);
            uint4* pl = (uint4*)(C + rb + (size_t)N + n);
            #pragma unroll
            for (int t2 = 0; t2 < 4; t2++) {
                ph[t2] = ((uint4*)hiA)[t2];
                pl[t2] = ((uint4*)loA)[t2];
            }
        } else if (epi == 3 || epi == 4) {
            __nv_bfloat16* C = (__nv_bfloat16*)Cout;
            int bb = mrow >> 11, tl = mrow & 2047;
            int head = n >> 6, d0 = n & 63;
            __nv_bfloat16 hiA[32], loA[32];
            #pragma unroll
            for (int j = 0; j < 32; j++)
                split_bf16(__uint_as_float(dr[j]), hiA[j], loA[j]);
            __nv_bfloat16* dst = C + (((size_t)(bb * 16 + head)) * 2048 + tl) * 128;
            uint4* ph = (uint4*)(dst + d0);
            uint4* pl = (uint4*)(dst + 64 + d0);
            #pragma unroll
            for (int t2 = 0; t2 < 4; t2++) {
                ph[t2] = ((uint4*)hiA)[t2];
                pl[t2] = ((uint4*)loA)[t2];
            }
        } else if (epi == 5) {
            // V transposed: vt3[b*16+h][128 d-rows (hi 0..63, lo 64..127)][2048]
            __nv_bfloat16* C = (__nv_bfloat16*)Cout;
            int bb = mrow >> 11;
            int head = n >> 6, d0 = n & 63;
            int tl0 = (m0 & 2047) + sub * 32;
            __nv_bfloat16 hiA[32], loA[32];
            #pragma unroll
            for (int j = 0; j < 32; j++)
                split_bf16(__uint_as_float(dr[j]), hiA[j], loA[j]);
            uint16_t* sc  = (uint16_t*)(dsp + (size_t)wid * 4352);
            uint16_t* scl = sc + 1088;
            #pragma unroll
            for (int j = 0; j < 32; j++) {
                sc [lane * 34 + j] = __bfloat16_as_ushort(hiA[j]);
                scl[lane * 34 + j] = __bfloat16_as_ushort(loA[j]);
            }
            __syncwarp();
            uint32_t wh[16], wl[16];
            #pragma unroll
            for (int g = 0; g < 16; g++) {
                wh[g] = (uint32_t)sc [(2*g) * 34 + lane] | ((uint32_t)sc [(2*g+1) * 34 + lane] << 16);
                wl[g] = (uint32_t)scl[(2*g) * 34 + lane] | ((uint32_t)scl[(2*g+1) * 34 + lane] << 16);
            }
            size_t base_hb = (size_t)(bb * 16 + head) * 262144;
            __nv_bfloat16* dh = C + base_hb + (size_t)(d0 + lane) * 2048 + tl0;
            __nv_bfloat16* dl = C + base_hb + (size_t)(64 + d0 + lane) * 2048 + tl0;
            #pragma unroll
            for (int g = 0; g < 4; g++) {
                ((uint4*)dh)[g] = ((uint4*)wh)[g];
                ((uint4*)dl)[g] = ((uint4*)wl)[g];
            }
            __syncwarp();
        } else {
            float* C = (float*)Cout;
            size_t base = (size_t)mrow * N + n;
            #pragma unroll
            for (int j = 0; j < 32; j += 4) {
                float4 v = make_float4(__uint_as_float(dr[j]),   __uint_as_float(dr[j+1]),
                                       __uint_as_float(dr[j+2]), __uint_as_float(dr[j+3]));
                if (epi == 1) {
                    float4 r4 = *(const float4*)(res + base + j);
                    v.x += r4.x; v.y += r4.y; v.z += r4.z; v.w += r4.w;
                }
                *(float4*)(C + base + j) = v;
            }
        }
    }
    __syncthreads();
    if (wid == 0) {
        asm volatile("tcgen05.relinquish_alloc_permit.cta_group::1.sync.aligned;");
        asm volatile("tcgen05.dealloc.cta_group::1.sync.aligned.b32 %0, %1;"
                     :: "r"(tmem), "r"(256u));
    }
#else
    // ---------------- SIMT fallback (non-sm_103a cubin only) -----------------
    int tid = threadIdx.x;
    int n_c = n0 + tid;
    for (int m = 0; m < 128; m++) {
        int mrow = m0 + m;
        const __nv_bfloat16* ar = A2 + (size_t)mrow * K2;
        const __nv_bfloat16* br = B2 + (size_t)n_c * K2;
        float acc = 0.f;
        for (int k = 0; k < K; k++) {
            float ah = __bfloat162float(ar[k]), al = __bfloat162float(ar[K + k]);
            float bh = __bfloat162float(br[k]), bl = __bfloat162float(br[K + k]);
            acc += ah * bh + al * bh + ah * bl;
        }
        if (epi == 2) {
            __nv_bfloat16* C = (__nv_bfloat16*)Cout;
            size_t base = (size_t)mrow * (2 * (size_t)N);
            float f = gelu_tanh(acc);
            __nv_bfloat16 hi, lo; split_bf16(f, hi, lo);
            C[base + n_c] = hi; C[base + N + n_c] = lo;
        } else if (epi == 3 || epi == 4) {
            __nv_bfloat16* C = (__nv_bfloat16*)Cout;
            int bb = mrow >> 11, tl = mrow & 2047;
            int head = n_c >> 6, d = n_c & 63;
            __nv_bfloat16 hi, lo; split_bf16(acc, hi, lo);
            size_t base = (((size_t)(bb * 16 + head)) * 2048 + tl) * 128;
            C[base + d] = hi; C[base + 64 + d] = lo;
        } else if (epi == 5) {
            __nv_bfloat16* C = (__nv_bfloat16*)Cout;
            int bb = mrow >> 11, tl = mrow & 2047;
            int head = n_c >> 6, d = n_c & 63;
            __nv_bfloat16 hi, lo; split_bf16(acc, hi, lo);
            size_t base = (size_t)(bb * 16 + head) * 262144;
            C[base + (size_t)d * 2048 + tl] = hi;
            C[base + (size_t)(64 + d) * 2048 + tl] = lo;
        } else {
            float* C = (float*)Cout;
            size_t base = (size_t)mrow * N;
            if (epi == 1) acc += res[base + n_c];
            C[base + n_c] = acc;
        }
    }
#endif
}

template<int EPI>
__global__ __launch_bounds__(256, 1) void tc_gemm(
    const __nv_bfloat16* __restrict__ A2, const __nv_bfloat16* __restrict__ B2,
    const float* __restrict__ res, void* __restrict__ C, int N, int K)
{
    tc_gemm_body(A2, B2, res, C, N, K, blockIdx.y * 128, blockIdx.x * 256, EPI);
}

__global__ __launch_bounds__(256, 1) void tc_gemm_qkv(
    const __nv_bfloat16* __restrict__ A2,
    const __nv_bfloat16* __restrict__ b0, const __nv_bfloat16* __restrict__ b1,
    const __nv_bfloat16* __restrict__ b2,
    __nv_bfloat16* __restrict__ c0, __nv_bfloat16* __restrict__ c1,
    __nv_bfloat16* __restrict__ c2)
{
    const __nv_bfloat16* B2 = (blockIdx.z == 0) ? b0 : ((blockIdx.z == 1) ? b1 : b2);
    __nv_bfloat16* C = (blockIdx.z == 0) ? c0 : ((blockIdx.z == 1) ? c1 : c2);
    tc_gemm_body(A2, B2, nullptr, C, TB_D, TB_D,
                 blockIdx.y * 128, blockIdx.x * 256, 3 + (int)blockIdx.z);
}

// ---------------- tcgen05 causal flash attention ------------------------------
// R13 change: single-read softmax. S is read from TMEM ONCE into registers
// (s[128], literal-indexed/unrolled), max from regs, O fold, exp from regs.
// LDTM per tile: 160KB -> 96KB. Barrier protocol identical to the R11/R12 win.
#define ATT_DSMEM (192 * 1024 + 1024)

__global__ __launch_bounds__(256, 1) void tc_attn(
    const __nv_bfloat16* __restrict__ q3, const __nv_bfloat16* __restrict__ k3,
    const __nv_bfloat16* __restrict__ vt3, __nv_bfloat16* __restrict__ att3)
{
    int qtile = 15 - (int)blockIdx.x;          // heavy tiles first
    int h = blockIdx.y, b = blockIdx.z;
    int ntiles = qtile + 1;
    int q0 = qtile * 128;
    size_t hb = (size_t)b * 16 + h;
    const __nv_bfloat16* qh = q3 + hb * (size_t)2048 * 128;
    const __nv_bfloat16* kh = k3 + hb * (size_t)2048 * 128;
    const __nv_bfloat16* vh = vt3 + hb * (size_t)262144;
#if HAS_TCGEN05
    extern __shared__ char dsm_raw[];
    __shared__ uint32_t s_tmem;
    __shared__ __align__(8) uint64_t bars[7]; // bK0 bK1 bV bP bO bSK0 bSK1
    char* dsmp = (char*)(((uintptr_t)dsm_raw + 1023) & ~(uintptr_t)1023);
    uint32_t dsm = smem_u32(dsmp);
    uint32_t Q0c = dsm, Q1c = dsm + 16384;
    uint32_t Kst = dsm + 32768;
    uint32_t Vt  = dsm + 98304;
    uint32_t Pb  = dsm + 131072;
    uint32_t bK[2]  = { smem_u32(&bars[0]), smem_u32(&bars[1]) };
    uint32_t bV = smem_u32(&bars[2]), bP = smem_u32(&bars[3]);
    uint32_t bO = smem_u32(&bars[4]);
    uint32_t bSK[2] = { smem_u32(&bars[5]), smem_u32(&bars[6]) };
    int tid = threadIdx.x, wid = tid >> 5, lane = tid & 31;

    if (wid == 0) {
        asm volatile("tcgen05.alloc.cta_group::1.sync.aligned.shared::cta.b32 [%0], %1;"
                     :: "r"(smem_u32((void*)&s_tmem)), "r"(256u) : "memory");
    }
    if (tid == 0) {
        mbar_init(bK[0], 64); mbar_init(bK[1], 64);
        mbar_init(bV, 32); mbar_init(bP, 128); mbar_init(bO, 1);
        mbar_init(bSK[0], 1); mbar_init(bSK[1], 1);
    }
    __syncthreads();
    uint32_t tmem = s_tmem;

    // Q preload (warps 4-7)
    if (wid >= 4) {
        int t4 = tid - 128;
        #pragma unroll
        for (int i = 0; i < 8; i++) {
            int u = t4 + 128 * i, r = u >> 3, q = u & 7;
            cp_async16(Q0c + SWZ(r * 128 + q * 16), qh + (size_t)(q0 + r) * 128 + q * 8);
        }
        #pragma unroll
        for (int i = 0; i < 8; i++) {
            int u = t4 + 128 * i, r = u >> 3, q = u & 7;
            cp_async16(Q1c + SWZ(r * 128 + q * 16), qh + (size_t)(q0 + r) * 128 + 64 + q * 8);
        }
        asm volatile("cp.async.wait_all;" ::: "memory");
    }
    __syncthreads();

    if (wid == 4 || wid == 5) {
        int t2 = tid - 128;
        for (int t = 0; t < ntiles; t++) {
            if (t >= 2) mbar_wait(bSK[t & 1], ((t >> 1) - 1) & 1);
            uint32_t Ks = Kst + (t & 1) * 32768;
            int k0 = t * 128;
            #pragma unroll
            for (int i = 0; i < 16; i++) {
                int u = t2 + 64 * i, r = u >> 3, q = u & 7;
                cp_async16(Ks + SWZ(r * 128 + q * 16), kh + (size_t)(k0 + r) * 128 + q * 8);
            }
            #pragma unroll
            for (int i = 0; i < 16; i++) {
                int u = t2 + 64 * i, r = u >> 3, q = u & 7;
                cp_async16(Ks + 16384 + SWZ(r * 128 + q * 16), kh + (size_t)(k0 + r) * 128 + 64 + q * 8);
            }
            cp_async_arrive(bK[t & 1]);
        }
    } else if (wid == 6) {
        int t3 = tid - 192;
        for (int t = 0; t < ntiles; t++) {
            if (t >= 1) mbar_wait(bO, (t - 1) & 1);
            int k0 = t * 128;
            #pragma unroll
            for (int p = 0; p < 2; p++)
                #pragma unroll
                for (int cc = 0; cc < 2; cc++) {
                    uint32_t cb = Vt + (p * 2 + cc) * 8192;
                    #pragma unroll
                    for (int i = 0; i < 16; i++) {
                        int u = t3 + 32 * i, r = u >> 3, q = u & 7;
                        cp_async16(cb + SWZ(r * 128 + q * 16),
                                   vh + (size_t)(p * 64 + r) * 2048 + k0 + cc * 64 + q * 8);
                    }
                }
            cp_async_arrive(bV);
        }
    } else if (wid == 7) {
        for (int t = 0; t < ntiles; t++) {
            mbar_wait(bK[t & 1], (t >> 1) & 1);
            if (elect_one()) {
                uint32_t Ks = Kst + (t & 1) * 32768;
                uint64_t qd[3] = { MK_DESC(Q0c), MK_DESC(Q1c), MK_DESC(Q0c) };
                uint64_t kd[3] = { MK_DESC(Ks), MK_DESC(Ks), MK_DESC(Ks + 16384) };
                #pragma unroll
                for (int seg = 0; seg < 3; seg++)
                    #pragma unroll
                    for (int s = 0; s < 4; s++)
                        mma_f16_ss(tmem, qd[seg] + 2 * s, kd[seg] + 2 * s,
                                   MMA_IDESC, (seg | s) ? 1u : 0u);
                tc_commit(bSK[t & 1]);
            }
            mbar_wait(bV, t & 1);
            mbar_wait(bP, t & 1);
            if (elect_one()) {
                uint64_t pa[3][2] = {
                    { MK_DESC(Pb),         MK_DESC(Pb + 16384) },
                    { MK_DESC(Pb + 32768), MK_DESC(Pb + 49152) },
                    { MK_DESC(Pb),         MK_DESC(Pb + 16384) } };
                const int vpart[3] = { 0, 0, 1 };
                #pragma unroll
                for (int seg = 0; seg < 3; seg++)
                    #pragma unroll
                    for (int s = 0; s < 8; s++) {
                        int cc = s >> 2;
                        mma_f16_ss(tmem + 128,
                                   pa[seg][cc] + 2 * (s & 3),
                                   MK_DESC(Vt + (vpart[seg] * 2 + cc) * 8192) + 2 * (s & 3),
                                   IDESC_PV, (seg | s) ? 1u : 0u);
                    }
                tc_commit(bO);
            }
        }
    } else {
        // ---------------- compute warps 0-3: lane owns row ---------------------
        int rloc = wid * 32 + lane;
        int rg = q0 + rloc;
        float m = -1e30f, l = 0.f, alpha_prev = 0.f;
        float O[64];
        #pragma unroll
        for (int j = 0; j < 64; j++) O[j] = 0.f;

        for (int t = 0; t < ntiles; t++) {
            mbar_wait(bSK[t & 1], (t >> 1) & 1);   // S(t) ready
            TC_FENCE_AFTER();
            int k0 = t * 128;
            int lim = rg - k0;                     // valid cols c <= lim
            // SINGLE TMEM read of S into registers (masked + scaled), max inline
            float s[128];
            float mt = -1e30f;
            #pragma unroll
            for (int cb = 0; cb < 4; cb++) {
                uint32_t dr[32];
                TCGEN05_LD_32X32B_X32(dr, tmem + cb * 32);
                TC_WAIT_LD();
                #pragma unroll
                for (int j = 0; j < 32; j++) {
                    int c = cb * 32 + j;
                    float v = (c <= lim) ? __uint_as_float(dr[j]) * 0.125f : -1e30f;
                    s[c] = v;
                    mt = fmaxf(mt, v);
                }
            }
            float mn = fmaxf(m, mt);
            float al = __expf(m - mn);
            // fold previous PV result BEFORE writing P (PV(t-1) reads Pb)
            if (t > 0) {
                mbar_wait(bO, (t - 1) & 1);
                TC_FENCE_AFTER();
                uint32_t du[32];
                TCGEN05_LD_32X32B_X32(du, tmem + 128);
                TC_WAIT_LD();
                #pragma unroll
                for (int j = 0; j < 32; j++)
                    O[j] = O[j] * alpha_prev + __uint_as_float(du[j]);
                TCGEN05_LD_32X32B_X32(du, tmem + 160);
                TC_WAIT_LD();
                #pragma unroll
                for (int j = 0; j < 32; j++)
                    O[32 + j] = O[32 + j] * alpha_prev + __uint_as_float(du[j]);
            }
            // exp + split-store P into smem (from registers; no TMEM re-read)
            float ps = 0.f;
            #pragma unroll
            for (int c = 0; c < 128; c += 4) {
                float p0 = __expf(s[c]     - mn);
                float p1 = __expf(s[c + 1] - mn);
                float p2 = __expf(s[c + 2] - mn);
                float p3 = __expf(s[c + 3] - mn);
                ps += (p0 + p1) + (p2 + p3);
                __nv_bfloat16 h0,l0,h1,l1,h2,l2,h3,l3;
                split_bf16(p0, h0, l0); split_bf16(p1, h1, l1);
                split_bf16(p2, h2, l2); split_bf16(p3, h3, l3);
                uint2 hv = pack4bf(h0, h1, h2, h3);
                uint2 lv = pack4bf(l0, l1, l2, l3);
                int subo = (c >> 6) * 16384;
                uint32_t so = SWZ(rloc * 128 + (c & 63) * 2);
                *(uint2*)(dsmp + 131072 + subo + so) = hv;   // Phi
                *(uint2*)(dsmp + 163840 + subo + so) = lv;   // Plo
            }
            l = l * al + ps;
            alpha_prev = al;
            m = mn;
            FENCE_ASYNC();
            mbar_arrive(bP);
        }
        mbar_wait(bO, (ntiles - 1) & 1);
        TC_FENCE_AFTER();
        {
            uint32_t du[32];
            TCGEN05_LD_32X32B_X32(du, tmem + 128);
            TC_WAIT_LD();
            #pragma unroll
            for (int j = 0; j < 32; j++)
                O[j] = O[j] * alpha_prev + __uint_as_float(du[j]);
            TCGEN05_LD_32X32B_X32(du, tmem + 160);
            TC_WAIT_LD();
            #pragma unroll
            for (int j = 0; j < 32; j++)
                O[32 + j] = O[32 + j] * alpha_prev + __uint_as_float(du[j]);
        }
        float inv = 1.0f / l;
        __nv_bfloat16 hi[64], lo[64];
        #pragma unroll
        for (int j = 0; j < 64; j++) split_bf16(O[j] * inv, hi[j], lo[j]);
        size_t rb = ((size_t)b * 2048 + rg) * TB_D2 + h * 64;
        uint4* ph = (uint4*)(att3 + rb);
        uint4* pl = (uint4*)(att3 + rb + TB_D);
        #pragma unroll
        for (int i = 0; i < 8; i++) {
            ph[i] = ((uint4*)hi)[i];
            pl[i] = ((uint4*)lo)[i];
        }
    }
    __syncthreads();
    if (wid == 0) {
        asm volatile("tcgen05.relinquish_alloc_permit.cta_group::1.sync.aligned;");
        asm volatile("tcgen05.dealloc.cta_group::1.sync.aligned.b32 %0, %1;"
                     :: "r"(tmem), "r"(256u));
    }
#else
    // ---------------- SIMT fallback (non-sm_103a cubin only) ------------------
    int tid = threadIdx.x;
    if (tid < 128) {
        int rg = q0 + tid;
        float q[64];
        #pragma unroll
        for (int d = 0; d < 64; d++)
            q[d] = __bfloat162float(qh[(size_t)rg * 128 + d]) +
                   __bfloat162float(qh[(size_t)rg * 128 + 64 + d]);
        float m = -1e30f;
        for (int k = 0; k <= rg; k++) {
            float s = 0.f;
            for (int d = 0; d < 64; d++)
                s += q[d] * (__bfloat162float(kh[(size_t)k * 128 + d]) +
                             __bfloat162float(kh[(size_t)k * 128 + 64 + d]));
            m = fmaxf(m, s * 0.125f);
        }
        float l = 0.f, O[64];
        for (int d = 0; d < 64; d++) O[d] = 0.f;
        for (int k = 0; k <= rg; k++) {
            float s = 0.f;
            for (int d = 0; d < 64; d++)
                s += q[d] * (__bfloat162float(kh[(size_t)k * 128 + d]) +
                             __bfloat162float(kh[(size_t)k * 128 + 64 + d]));
            float p = expf(s * 0.125f - m);
            l += p;
            for (int d = 0; d < 64; d++)
                O[d] += p * (__bfloat162float(vh[(size_t)d * 2048 + k]) +
                             __bfloat162float(vh[(size_t)(64 + d) * 2048 + k]));
        }
        float inv = 1.0f / l;
        size_t rb = ((size_t)b * 2048 + rg) * TB_D2 + h * 64;
        for (int d = 0; d < 64; d++) {
            __nv_bfloat16 hi, lo; split_bf16(O[d] * inv, hi, lo);
            att3[rb + d] = hi; att3[rb + TB_D + d] = lo;
        }
    }
#endif
}

// ---------------- launch ------------------------------------------------------
extern "C" void kernel_launch(void* const* d_in, const int* in_sizes, int n_in,
                              void* d_out, int out_size) {
    const float* x     = (const float*)d_in[0];
    const float* wq    = (const float*)d_in[1];
    const float* wk    = (const float*)d_in[2];
    const float* wv    = (const float*)d_in[3];
    const float* wo    = (const float*)d_in[4];
    const float* w_in  = (const float*)d_in[5];
    const float* w_out = (const float*)d_in[6];
    float* out = (float*)d_out;
    (void)in_sizes; (void)n_in; (void)out_size;

    __nv_bfloat16 *xn3, *att3, *ff3, *q3, *k3, *vt3;
    __nv_bfloat16 *wq3, *wk3, *wv3, *wo3, *win3, *wout3;
    float *h;
    cudaGetSymbolAddress((void**)&xn3,  g_xn3);
    cudaGetSymbolAddress((void**)&att3, g_att3);
    cudaGetSymbolAddress((void**)&ff3,  g_ff3);
    cudaGetSymbolAddress((void**)&q3,   g_q3);
    cudaGetSymbolAddress((void**)&k3,   g_k3);
    cudaGetSymbolAddress((void**)&vt3,  g_vt3);
    cudaGetSymbolAddress((void**)&h,    g_h);
    cudaGetSymbolAddress((void**)&wq3,  g_wq3);
    cudaGetSymbolAddress((void**)&wk3,  g_wk3);
    cudaGetSymbolAddress((void**)&wv3,  g_wv3);
    cudaGetSymbolAddress((void**)&wo3,  g_wo3);
    cudaGetSymbolAddress((void**)&win3, g_win3);
    cudaGetSymbolAddress((void**)&wout3, g_wout3);

    cudaFuncSetAttribute(tc_attn,     cudaFuncAttributeMaxDynamicSharedMemorySize, ATT_DSMEM);
    cudaFuncSetAttribute(tc_gemm_qkv, cudaFuncAttributeMaxDynamicSharedMemorySize, GEMM_SMEM);
    cudaFuncSetAttribute(tc_gemm<1>,  cudaFuncAttributeMaxDynamicSharedMemorySize, GEMM_SMEM);
    cudaFuncSetAttribute(tc_gemm<2>,  cudaFuncAttributeMaxDynamicSharedMemorySize, GEMM_SMEM);

    dim3 cwb(32, 8);
    conv_w4_kernel<<<dim3(32, 32, 4), cwb>>>(wq, wk, wv, wo, wq3, wk3, wv3, wo3);   // 1
    conv_win_kernel<<<dim3(128, 32), cwb>>>(w_in, win3);                            // 2
    conv_wout_kernel<<<dim3(32, 128), cwb>>>(w_out, wout3);                         // 3
    srmsnorm3_kernel<<<TB_T, 256>>>(x, xn3);                                        // 4
    tc_gemm_qkv<<<dim3(TB_D / 256, TB_T / 128, 3), 256, GEMM_SMEM>>>(               // 5
        xn3, wq3, wk3, wv3, q3, k3, vt3);
    tc_attn<<<dim3(16, TB_H, TB_B), 256, ATT_DSMEM>>>(q3, k3, vt3, att3);           // 6
    tc_gemm<1><<<dim3(TB_D / 256, TB_T / 128), 256, GEMM_SMEM>>>(                   // 7
        att3, wo3, x, h, TB_D, TB_D);
    srmsnorm3_kernel<<<TB_T, 256>>>(h, xn3);                                        // 8
    tc_gemm<2><<<dim3(TB_F / 256, TB_T / 128), 256, GEMM_SMEM>>>(                   // 9
        xn3, win3, nullptr, ff3, TB_F, TB_D);
    tc_gemm<1><<<dim3(TB_D / 256, TB_T / 128), 256, GEMM_SMEM>>>(                   // 10
        ff3, wout3, h, out, TB_D, TB_F);
}